// round 3
// baseline (speedup 1.0000x reference)
#include <cuda_runtime.h>

#define Bn 32
#define Tn 128
#define Kn 256
#define Hn 512
#define Vn 10000
#define BT (Bn*Tn)
#define G4n (4*Hn)
#define TWOK (2*Kn)

#define HALF_LOG_2PI 0.918938533204672741780329736406f

// ---------------- scratch (static device memory; no allocations) ----------------
__device__ __align__(16) float g_z[BT*Kn];          // 4 MB   z (masked)
__device__ __align__(16) float g_h[BT*Hn];          // 8 MB   LSTM hidden states
__device__ __align__(16) float g_xproj[BT*G4n];     // 32 MB  z_shift @ w_ih^T + biases
__device__ __align__(16) float g_A[Vn*Kn];          // 10 MB  2*inv2var*mu_p
__device__ __align__(16) float g_Bv[Vn*Kn];         // 10 MB  inv2var
__device__ float g_cst[Vn];
__device__ float g_qzlp[BT];
__device__ float g_sumz2[BT];
__device__ float g_contrib[BT];
__device__ __align__(16) float g_hbuf[2][Bn*Hn];    // double-buffered LSTM h state
__device__ float g_cstate[Bn*Hn];

__device__ __forceinline__ float softplus_b(float x){
    // softplus(log2 * x)/log2 == log2(1 + 2^x)
    return (x > 20.f) ? x : log2f(1.f + exp2f(x));
}
__device__ __forceinline__ float sigmf(float x){ return 1.f/(1.f+expf(-x)); }

// ---------------- init: zero LSTM state ----------------
__global__ void k_init(){
    int i = blockIdx.x*blockDim.x + threadIdx.x;
    if (i < Bn*Hn){ g_hbuf[0][i] = 0.f; g_cstate[i] = 0.f; }
}

// ---------------- per-(b,t) prep: z, q_z_lp, sum(z^2) ----------------
__global__ void k_prep_z(const int* __restrict__ x, const int* __restrict__ x_sl,
                         const float* __restrict__ eps, const float* __restrict__ emb)
{
    int row = blockIdx.x;          // b*T + t
    int k   = threadIdx.x;         // 0..255
    int b = row / Tn, t = row % Tn;
    int xv = x[row];
    float mask = (t < x_sl[b]) ? 1.f : 0.f;
    float mu = emb[xv*TWOK + k];
    float sq = softplus_b(emb[xv*TWOK + Kn + k]);
    float e  = eps[row*Kn + k];
    float zv = (mu + sq*e) * mask;
    g_z[row*Kn + k] = zv;
    float q = -HALF_LOG_2PI - logf(sq) - 0.5f*e*e;   // ((z-mu)/sig) == eps where mask==1
    __shared__ float r1[256], r2[256];
    r1[k] = q; r2[k] = zv*zv;
    __syncthreads();
    for (int s = 128; s > 0; s >>= 1){
        if (k < s){ r1[k] += r1[k+s]; r2[k] += r2[k+s]; }
        __syncthreads();
    }
    if (k == 0){ g_qzlp[row] = r1[0]; g_sumz2[row] = r2[0]; }
}

// ---------------- per-v prep: A, Binv, const ----------------
__global__ void k_prep_v(const float* __restrict__ emb)
{
    int v = blockIdx.x;
    int k = threadIdx.x;
    float mu = emb[v*TWOK + k];
    float sp = softplus_b(emb[v*TWOK + Kn + k]);
    float inv2 = 0.5f/(sp*sp);
    g_A[v*Kn + k]  = 2.f*inv2*mu;
    g_Bv[v*Kn + k] = inv2;
    float c = -HALF_LOG_2PI - logf(sp) - mu*mu*inv2;
    __shared__ float red[256];
    red[k] = c;
    __syncthreads();
    for (int s = 128; s > 0; s >>= 1){
        if (k < s) red[k] += red[k+s];
        __syncthreads();
    }
    if (k == 0) g_cst[v] = red[0];
}

// ---------------- x_proj GEMM: z_shift(4096x256) @ w_ih^T(256x2048) + b_ih + b_hh ----------------
__global__ __launch_bounds__(256) void k_xproj(const float* __restrict__ w_ih,
        const float* __restrict__ b_ih, const float* __restrict__ b_hh)
{
    __shared__ __align__(16) float As[32][68];   // [k][m], pad to 68 (272B rows, 16B aligned)
    __shared__ __align__(16) float Bs[32][68];   // [k][n]
    int tid = threadIdx.x;
    int tx = tid & 15, ty = tid >> 4;
    int brow = blockIdx.y * 64;
    int bcol = blockIdx.x * 64;
    float acc[4][4];
    #pragma unroll
    for (int i=0;i<4;i++)
        #pragma unroll
        for (int j=0;j<4;j++) acc[i][j]=0.f;

    for (int k0 = 0; k0 < Kn; k0 += 32){
        #pragma unroll
        for (int l = 0; l < 2; l++){
            int idx = tid + l*256;
            int m = idx >> 3, kq = idx & 7;
            int grow = brow + m;
            float4 aval = make_float4(0.f,0.f,0.f,0.f);
            if ((grow & (Tn-1)) != 0)        // t==0 -> zero row (z_shift)
                aval = *(const float4*)(g_z + (grow-1)*Kn + k0 + kq*4);
            As[kq*4+0][m]=aval.x; As[kq*4+1][m]=aval.y; As[kq*4+2][m]=aval.z; As[kq*4+3][m]=aval.w;
            int g = bcol + m;
            float4 bval = *(const float4*)(w_ih + g*Kn + k0 + kq*4);
            Bs[kq*4+0][m]=bval.x; Bs[kq*4+1][m]=bval.y; Bs[kq*4+2][m]=bval.z; Bs[kq*4+3][m]=bval.w;
        }
        __syncthreads();
        #pragma unroll
        for (int kk = 0; kk < 32; kk++){
            float4 a  = *(const float4*)&As[kk][ty*4];
            float4 bq = *(const float4*)&Bs[kk][tx*4];
            acc[0][0]+=a.x*bq.x; acc[0][1]+=a.x*bq.y; acc[0][2]+=a.x*bq.z; acc[0][3]+=a.x*bq.w;
            acc[1][0]+=a.y*bq.x; acc[1][1]+=a.y*bq.y; acc[1][2]+=a.y*bq.z; acc[1][3]+=a.y*bq.w;
            acc[2][0]+=a.z*bq.x; acc[2][1]+=a.z*bq.y; acc[2][2]+=a.z*bq.z; acc[2][3]+=a.z*bq.w;
            acc[3][0]+=a.w*bq.x; acc[3][1]+=a.w*bq.y; acc[3][2]+=a.w*bq.z; acc[3][3]+=a.w*bq.w;
        }
        __syncthreads();
    }
    #pragma unroll
    for (int i = 0; i < 4; i++){
        int row = brow + ty*4 + i;
        int col = bcol + tx*4;
        float4 o;
        o.x = acc[i][0] + b_ih[col+0] + b_hh[col+0];
        o.y = acc[i][1] + b_ih[col+1] + b_hh[col+1];
        o.z = acc[i][2] + b_ih[col+2] + b_hh[col+2];
        o.w = acc[i][3] + b_ih[col+3] + b_hh[col+3];
        *(float4*)(g_xproj + row*G4n + col) = o;
    }
}

// ---------------- one LSTM time step ----------------
__global__ __launch_bounds__(256) void k_lstm(const float* __restrict__ w_hh, int t)
{
    int b  = blockIdx.y;    // 0..31
    int jb = blockIdx.x;    // 0..7  (64-wide j slice)
    __shared__ __align__(16) float hprev[Hn];
    __shared__ float gbuf[4][64];
    int tid = threadIdx.x;
    int par = t & 1;
    for (int i = tid; i < Hn; i += 256) hprev[i] = g_hbuf[par][b*Hn + i];
    __syncthreads();
    int gate = tid >> 6, jl = tid & 63;
    int grow = gate*Hn + jb*64 + jl;
    float acc = g_xproj[(b*Tn + t)*G4n + grow];
    const float4* wr = (const float4*)(w_hh + grow*Hn);
    const float4* hp = (const float4*)hprev;
    #pragma unroll 8
    for (int q = 0; q < Hn/4; q++){
        float4 w = wr[q]; float4 hh = hp[q];
        acc += w.x*hh.x + w.y*hh.y + w.z*hh.z + w.w*hh.w;
    }
    gbuf[gate][jl] = acc;
    __syncthreads();
    if (tid < 64){
        int j = jb*64 + tid;
        float iv = gbuf[0][tid], fv = gbuf[1][tid], gv = gbuf[2][tid], ov = gbuf[3][tid];
        float c = g_cstate[b*Hn + j];
        c = sigmf(fv)*c + sigmf(iv)*tanhf(gv);
        float hv = sigmf(ov)*tanhf(c);
        g_cstate[b*Hn + j] = c;
        g_hbuf[par^1][b*Hn + j] = hv;
        g_h[(b*Tn + t)*Hn + j] = hv;
    }
}

// ---------------- fused V-loop: 3 GEMV-batches + logsumexp reductions ----------------
// CTA = 16 rows; 256 threads; pairs of lanes share a v (coalesced weight loads),
// row data broadcast from smem. Per row: LSE(prior), LSE(prior+lp), LSE(gen), gen[x].
__global__ __launch_bounds__(256,2) void k_big(
    const float* __restrict__ w_prior, const float* __restrict__ b_prior,
    const float* __restrict__ w_gen,   const float* __restrict__ b_gen,
    const int*   __restrict__ x,       const int*   __restrict__ x_sl)
{
    extern __shared__ float4 shp[];        // 16 rows * 256 float4: [h(128) | z(64) | z2(64)]
    int row0 = blockIdx.x * 16;
    int tid  = threadIdx.x;

    for (int i = tid; i < 16*128; i += 256){
        int r = i >> 7, k4 = i & 127;
        shp[r*256 + k4] = *(const float4*)(g_h + (row0+r)*Hn + k4*4);
    }
    for (int i = tid; i < 16*64; i += 256){
        int r = i >> 6, k4 = i & 63;
        float4 zv = *(const float4*)(g_z + (row0+r)*Kn + k4*4);
        shp[r*256 + 128 + k4] = zv;
        shp[r*256 + 192 + k4] = make_float4(zv.x*zv.x, zv.y*zv.y, zv.z*zv.z, zv.w*zv.w);
    }
    __shared__ float sh_tgt[16];
    __shared__ int   sh_xv[16];
    __shared__ float sh_shift[16];
    __shared__ float sh_acc[16][3];
    if (tid < 16){
        sh_xv[tid]    = x[row0+tid];
        sh_shift[tid] = g_cst[0] - 0.5f*g_sumz2[row0+tid];   // LSE stability shift for m
        sh_tgt[tid]   = 0.f;
        sh_acc[tid][0]=0.f; sh_acc[tid][1]=0.f; sh_acc[tid][2]=0.f;
    }
    __syncthreads();

    int lane = tid & 31;
    int wrp  = tid >> 5;
    int half = lane & 1;       // row-half owned by this lane
    int pr   = lane >> 1;      // pair index: lanes 2p,2p+1 share v
    int rbase = half * 8;
    const float4* myrow = shp + rbase*256;

    float sump[8], summ[8], sumg[8], shf[8];
    int xv[8];
    #pragma unroll
    for (int r=0;r<8;r++){
        sump[r]=0.f; summ[r]=0.f; sumg[r]=0.f;
        shf[r]=sh_shift[rbase+r]; xv[r]=sh_xv[rbase+r];
    }

    for (int v = wrp*16 + pr; v < Vn; v += 128){
        const float4* wp = (const float4*)(w_prior + v*Hn);
        const float4* wa = (const float4*)(g_A  + v*Kn);
        const float4* wb = (const float4*)(g_Bv + v*Kn);
        const float4* wg = (const float4*)(w_gen + v*Kn);
        float ap[8], am[8], ag[8];
        #pragma unroll
        for (int r=0;r<8;r++){ ap[r]=0.f; am[r]=0.f; ag[r]=0.f; }

        #pragma unroll 4
        for (int k4 = 0; k4 < 128; k4++){
            float4 wv = wp[k4];
            #pragma unroll
            for (int r=0;r<8;r++){
                float4 hv = myrow[r*256 + k4];
                ap[r] += wv.x*hv.x + wv.y*hv.y + wv.z*hv.z + wv.w*hv.w;
            }
        }
        #pragma unroll 2
        for (int k4 = 0; k4 < 64; k4++){
            float4 av = wa[k4];
            float4 bv = wb[k4];
            float4 gv = wg[k4];
            #pragma unroll
            for (int r=0;r<8;r++){
                float4 zv = myrow[r*256 + 128 + k4];
                float4 z2 = myrow[r*256 + 192 + k4];
                am[r] += av.x*zv.x + av.y*zv.y + av.z*zv.z + av.w*zv.w
                       - bv.x*z2.x - bv.y*z2.y - bv.z*z2.z - bv.w*z2.w;
                ag[r] += gv.x*zv.x + gv.y*zv.y + gv.z*zv.z + gv.w*zv.w;
            }
        }
        float bp = __ldg(b_prior + v);
        float cv = g_cst[v];
        float bg = __ldg(b_gen + v);
        #pragma unroll
        for (int r=0;r<8;r++){
            float sp_ = ap[r] + bp;                       // prior logit
            float mm  = sp_ + cv + am[r] - shf[r];        // prior logit + lp - shift
            float sg  = ag[r] + bg;                       // gen logit
            sump[r] += expf(sp_);
            summ[r] += expf(mm);
            sumg[r] += expf(sg);
            if (xv[r] == v) sh_tgt[rbase + r] = sg;
        }
    }

    // warp-level reduction: xor over even distances keeps half-parity groups intact
    #pragma unroll
    for (int r=0;r<8;r++){
        float vp=sump[r], vm=summ[r], vg=sumg[r];
        #pragma unroll
        for (int d=2; d<32; d<<=1){
            vp += __shfl_xor_sync(0xffffffffu, vp, d);
            vm += __shfl_xor_sync(0xffffffffu, vm, d);
            vg += __shfl_xor_sync(0xffffffffu, vg, d);
        }
        if (pr == 0){
            atomicAdd(&sh_acc[rbase+r][0], vp);
            atomicAdd(&sh_acc[rbase+r][1], vm);
            atomicAdd(&sh_acc[rbase+r][2], vg);
        }
    }
    __syncthreads();
    if (tid < 16){
        int row = row0 + tid;
        int b = row / Tn, t = row % Tn;
        float lse_p = logf(sh_acc[tid][0]);                 // shift 0 (logits ~ O(1))
        float lse_m = sh_shift[tid] + logf(sh_acc[tid][1]);
        float lse_g = logf(sh_acc[tid][2]);
        float p_z_lp = lse_m - lse_p;                       // LSE(logw + lp)
        float log_px = sh_tgt[tid] - lse_g;
        float mask = (t < x_sl[b]) ? 1.f : 0.f;
        g_contrib[row] = mask * (log_px - g_qzlp[row] + p_z_lp);
    }
}

// ---------------- final scalar ----------------
__global__ void k_final(const int* __restrict__ x_sl, float* __restrict__ out)
{
    __shared__ float red[256];
    int tid = threadIdx.x;
    float s = 0.f;
    for (int i = tid; i < BT; i += 256) s += g_contrib[i];
    red[tid] = s; __syncthreads();
    for (int st = 128; st > 0; st >>= 1){
        if (tid < st) red[tid] += red[tid+st];
        __syncthreads();
    }
    if (tid == 0){
        int tot = 0;
        for (int b = 0; b < Bn; b++) tot += x_sl[b];
        out[0] = -red[0] / (float)tot;
    }
}

// ---------------- launch ----------------
extern "C" void kernel_launch(void* const* d_in, const int* in_sizes, int n_in,
                              void* d_out, int out_size)
{
    const int*   x       = (const int*)  d_in[0];
    const int*   x_sl    = (const int*)  d_in[1];
    const float* eps     = (const float*)d_in[2];
    const float* emb     = (const float*)d_in[3];
    const float* w_ih    = (const float*)d_in[4];
    const float* w_hh    = (const float*)d_in[5];
    const float* b_ih    = (const float*)d_in[6];
    const float* b_hh    = (const float*)d_in[7];
    const float* w_prior = (const float*)d_in[8];
    const float* b_prior = (const float*)d_in[9];
    const float* w_gen   = (const float*)d_in[10];
    const float* b_gen   = (const float*)d_in[11];
    float* out = (float*)d_out;

    cudaFuncSetAttribute(k_big, cudaFuncAttributeMaxDynamicSharedMemorySize,
                         16*1024*(int)sizeof(float));

    k_init<<<(Bn*Hn + 255)/256, 256>>>();
    k_prep_z<<<BT, 256>>>(x, x_sl, eps, emb);
    k_prep_v<<<Vn, 256>>>(emb);
    k_xproj<<<dim3(G4n/64, BT/64), 256>>>(w_ih, b_ih, b_hh);
    for (int t = 0; t < Tn; t++)
        k_lstm<<<dim3(8, Bn), 256>>>(w_hh, t);
    k_big<<<BT/16, 256, 16*1024*sizeof(float)>>>(w_prior, b_prior, w_gen, b_gen, x, x_sl);
    k_final<<<1, 256>>>(x_sl, out);
}

// round 4
// speedup vs baseline: 2.6419x; 2.6419x over previous
#include <cuda_runtime.h>

#define Bn 32
#define Tn 128
#define Kn 256
#define Hn 512
#define Vn 10000
#define BT (Bn*Tn)
#define G4n (4*Hn)
#define TWOK (2*Kn)
#define NVT 157              // ceil(Vn/64)

#define HALF_LOG_2PI 0.918938533204672741780329736406f

// ---------------- static scratch ----------------
__device__ __align__(16) float g_z[BT*Kn];          // 4 MB
__device__ __align__(16) float g_ZZ[BT*2*Kn];       // 8 MB  [z | z^2]
__device__ __align__(16) float g_h[BT*Hn];          // 8 MB
__device__ __align__(16) float g_xproj[BT*G4n];     // 32 MB
__device__ __align__(16) float g_W2[Vn*2*Kn];       // 20 MB [2*inv2var*mu | -inv2var]
__device__ float g_cst[Vn];
__device__ float g_qzlp[BT];
__device__ float g_sumz2[BT];
__device__ float g_tgt[BT];
__device__ float g_part[3*NVT*BT];                  // 7.7 MB per-row exp-sum partials
__device__ float g_contrib[BT];
__device__ __align__(16) float g_hbuf[2][Bn*Hn];
__device__ float g_cstate[Bn*Hn];

__device__ __forceinline__ float softplus_b(float x){
    return (x > 20.f) ? x : log2f(1.f + exp2f(x));
}
__device__ __forceinline__ float sigmf(float x){ return 1.f/(1.f+expf(-x)); }

// ---------------- init ----------------
__global__ void k_init(){
    int i = blockIdx.x*blockDim.x + threadIdx.x;
    if (i < Bn*Hn){ g_hbuf[0][i] = 0.f; g_cstate[i] = 0.f; }
}

// ---------------- per-(b,t): z, z^2, q_z_lp, sum z^2 ----------------
__global__ void k_prep_z(const int* __restrict__ x, const int* __restrict__ x_sl,
                         const float* __restrict__ eps, const float* __restrict__ emb)
{
    int row = blockIdx.x;
    int k   = threadIdx.x;
    int b = row / Tn, t = row % Tn;
    int xv = x[row];
    float mask = (t < x_sl[b]) ? 1.f : 0.f;
    float mu = emb[xv*TWOK + k];
    float sq = softplus_b(emb[xv*TWOK + Kn + k]);
    float e  = eps[row*Kn + k];
    float zv = (mu + sq*e) * mask;
    g_z[row*Kn + k] = zv;
    g_ZZ[row*2*Kn + k]      = zv;
    g_ZZ[row*2*Kn + Kn + k] = zv*zv;
    float q = -HALF_LOG_2PI - logf(sq) - 0.5f*e*e;
    __shared__ float r1[256], r2[256];
    r1[k] = q; r2[k] = zv*zv;
    __syncthreads();
    for (int s = 128; s > 0; s >>= 1){
        if (k < s){ r1[k] += r1[k+s]; r2[k] += r2[k+s]; }
        __syncthreads();
    }
    if (k == 0){ g_qzlp[row] = r1[0]; g_sumz2[row] = r2[0]; }
}

// ---------------- per-v: W2, const ----------------
__global__ void k_prep_v(const float* __restrict__ emb)
{
    int v = blockIdx.x;
    int k = threadIdx.x;
    float mu = emb[v*TWOK + k];
    float sp = softplus_b(emb[v*TWOK + Kn + k]);
    float inv2 = 0.5f/(sp*sp);
    g_W2[v*2*Kn + k]      = 2.f*inv2*mu;
    g_W2[v*2*Kn + Kn + k] = -inv2;
    float c = -HALF_LOG_2PI - logf(sp) - mu*mu*inv2;
    __shared__ float red[256];
    red[k] = c;
    __syncthreads();
    for (int s = 128; s > 0; s >>= 1){
        if (k < s) red[k] += red[k+s];
        __syncthreads();
    }
    if (k == 0) g_cst[v] = red[0];
}

// ---------------- x_proj GEMM ----------------
__global__ __launch_bounds__(256) void k_xproj(const float* __restrict__ w_ih,
        const float* __restrict__ b_ih, const float* __restrict__ b_hh)
{
    __shared__ __align__(16) float As[32][68];
    __shared__ __align__(16) float Bs[32][68];
    int tid = threadIdx.x;
    int tx = tid & 15, ty = tid >> 4;
    int brow = blockIdx.y * 64;
    int bcol = blockIdx.x * 64;
    float acc[4][4];
    #pragma unroll
    for (int i=0;i<4;i++)
        #pragma unroll
        for (int j=0;j<4;j++) acc[i][j]=0.f;

    for (int k0 = 0; k0 < Kn; k0 += 32){
        #pragma unroll
        for (int l = 0; l < 2; l++){
            int idx = tid + l*256;
            int m = idx >> 3, kq = idx & 7;
            int grow = brow + m;
            float4 aval = make_float4(0.f,0.f,0.f,0.f);
            if ((grow & (Tn-1)) != 0)
                aval = *(const float4*)(g_z + (grow-1)*Kn + k0 + kq*4);
            As[kq*4+0][m]=aval.x; As[kq*4+1][m]=aval.y; As[kq*4+2][m]=aval.z; As[kq*4+3][m]=aval.w;
            int g = bcol + m;
            float4 bval = *(const float4*)(w_ih + g*Kn + k0 + kq*4);
            Bs[kq*4+0][m]=bval.x; Bs[kq*4+1][m]=bval.y; Bs[kq*4+2][m]=bval.z; Bs[kq*4+3][m]=bval.w;
        }
        __syncthreads();
        #pragma unroll
        for (int kk = 0; kk < 32; kk++){
            float4 a  = *(const float4*)&As[kk][ty*4];
            float4 bq = *(const float4*)&Bs[kk][tx*4];
            acc[0][0]+=a.x*bq.x; acc[0][1]+=a.x*bq.y; acc[0][2]+=a.x*bq.z; acc[0][3]+=a.x*bq.w;
            acc[1][0]+=a.y*bq.x; acc[1][1]+=a.y*bq.y; acc[1][2]+=a.y*bq.z; acc[1][3]+=a.y*bq.w;
            acc[2][0]+=a.z*bq.x; acc[2][1]+=a.z*bq.y; acc[2][2]+=a.z*bq.z; acc[2][3]+=a.z*bq.w;
            acc[3][0]+=a.w*bq.x; acc[3][1]+=a.w*bq.y; acc[3][2]+=a.w*bq.z; acc[3][3]+=a.w*bq.w;
        }
        __syncthreads();
    }
    #pragma unroll
    for (int i = 0; i < 4; i++){
        int row = brow + ty*4 + i;
        int col = bcol + tx*4;
        float4 o;
        o.x = acc[i][0] + b_ih[col+0] + b_hh[col+0];
        o.y = acc[i][1] + b_ih[col+1] + b_hh[col+1];
        o.z = acc[i][2] + b_ih[col+2] + b_hh[col+2];
        o.w = acc[i][3] + b_ih[col+3] + b_hh[col+3];
        *(float4*)(g_xproj + row*G4n + col) = o;
    }
}

// ---------------- LSTM step: warp-per-gate-row, coalesced w_hh ----------------
__global__ __launch_bounds__(256) void k_lstm(const float* __restrict__ w_hh, int t)
{
    int b  = blockIdx.y;        // batch
    int js = blockIdx.x;        // j-slice of 16 (0..31)
    __shared__ __align__(16) float hprev[Hn];
    __shared__ float gbuf[64];
    int tid = threadIdx.x;
    int lane = tid & 31, w = tid >> 5;
    int par = t & 1;
    for (int i = tid; i < Hn; i += 256) hprev[i] = g_hbuf[par][b*Hn + i];
    __syncthreads();
    const float4* hp = (const float4*)hprev;

    float accs[8];
    #pragma unroll
    for (int r = 0; r < 8; r++){
        int gl = w*8 + r;                   // 0..63 = gate*16 + jl
        int gate = gl >> 4, jl = gl & 15;
        int grow = gate*Hn + js*16 + jl;
        const float4* wr = (const float4*)(w_hh + grow*Hn);
        float a = 0.f;
        #pragma unroll
        for (int c = 0; c < 4; c++){
            float4 wv = wr[c*32 + lane];    // coalesced: 32 lanes x 16B contiguous
            float4 hv = hp[c*32 + lane];
            a += wv.x*hv.x + wv.y*hv.y + wv.z*hv.z + wv.w*hv.w;
        }
        accs[r] = a;
    }
    #pragma unroll
    for (int r = 0; r < 8; r++){
        float a = accs[r];
        #pragma unroll
        for (int d = 16; d > 0; d >>= 1)
            a += __shfl_down_sync(0xffffffffu, a, d);
        if (lane == 0){
            int gl = w*8 + r;
            int gate = gl >> 4, jl = gl & 15;
            int grow = gate*Hn + js*16 + jl;
            gbuf[gl] = a + g_xproj[(b*Tn + t)*G4n + grow];
        }
    }
    __syncthreads();
    if (tid < 16){
        int j = js*16 + tid;
        float iv = gbuf[tid], fv = gbuf[16+tid], gv = gbuf[32+tid], ov = gbuf[48+tid];
        float c = g_cstate[b*Hn + j];
        c = sigmf(fv)*c + sigmf(iv)*tanhf(gv);
        float hv = sigmf(ov)*tanhf(c);
        g_cstate[b*Hn + j] = c;
        g_hbuf[par^1][b*Hn + j] = hv;
        g_h[(b*Tn + t)*Hn + j] = hv;
    }
}

// ---------------- tiled triple-GEMM with fused exp epilogue ----------------
// CTA: 64 rows x 64 v, BK=16, 256 threads, 4x4 microtile, 3 accumulator sets.
__device__ __forceinline__ void gemm_phase(
    const float* __restrict__ Ag, int lda,
    const float* __restrict__ Bg, int ldb,
    int nkt, int row0, int v0, int tid,
    float (&As)[2][16][72], float (&Bs)[2][16][72],
    float (&acc)[4][4])
{
    int tx = tid & 15, ty = tid >> 4;
    int lm = tid >> 2, kq = tid & 3;
    const float* aptr = Ag + (row0+lm)*lda + kq*4;
    bool bvalid = (v0 + lm) < Vn;
    int  bvi = bvalid ? (v0 + lm) : (Vn-1);
    const float* bptr = Bg + bvi*ldb + kq*4;

    __syncthreads();                 // previous smem users done
    float4 a = *(const float4*)aptr;
    float4 bq = bvalid ? *(const float4*)bptr : make_float4(0.f,0.f,0.f,0.f);
    As[0][kq*4+0][lm]=a.x; As[0][kq*4+1][lm]=a.y; As[0][kq*4+2][lm]=a.z; As[0][kq*4+3][lm]=a.w;
    Bs[0][kq*4+0][lm]=bq.x; Bs[0][kq*4+1][lm]=bq.y; Bs[0][kq*4+2][lm]=bq.z; Bs[0][kq*4+3][lm]=bq.w;
    __syncthreads();

    for (int kt = 0; kt < nkt; kt++){
        int cur = kt & 1;
        float4 an = make_float4(0.f,0.f,0.f,0.f);
        float4 bn = make_float4(0.f,0.f,0.f,0.f);
        bool more = (kt+1 < nkt);
        if (more){
            an = *(const float4*)(aptr + (kt+1)*16);
            if (bvalid) bn = *(const float4*)(bptr + (kt+1)*16);
        }
        #pragma unroll
        for (int k = 0; k < 16; k++){
            float4 av = *(const float4*)&As[cur][k][ty*4];
            float4 bv = *(const float4*)&Bs[cur][k][tx*4];
            acc[0][0]+=av.x*bv.x; acc[0][1]+=av.x*bv.y; acc[0][2]+=av.x*bv.z; acc[0][3]+=av.x*bv.w;
            acc[1][0]+=av.y*bv.x; acc[1][1]+=av.y*bv.y; acc[1][2]+=av.y*bv.z; acc[1][3]+=av.y*bv.w;
            acc[2][0]+=av.z*bv.x; acc[2][1]+=av.z*bv.y; acc[2][2]+=av.z*bv.z; acc[2][3]+=av.z*bv.w;
            acc[3][0]+=av.w*bv.x; acc[3][1]+=av.w*bv.y; acc[3][2]+=av.w*bv.z; acc[3][3]+=av.w*bv.w;
        }
        if (more){
            __syncthreads();
            int nb = cur ^ 1;
            As[nb][kq*4+0][lm]=an.x; As[nb][kq*4+1][lm]=an.y; As[nb][kq*4+2][lm]=an.z; As[nb][kq*4+3][lm]=an.w;
            Bs[nb][kq*4+0][lm]=bn.x; Bs[nb][kq*4+1][lm]=bn.y; Bs[nb][kq*4+2][lm]=bn.z; Bs[nb][kq*4+3][lm]=bn.w;
            __syncthreads();
        }
    }
}

__global__ __launch_bounds__(256) void k_big(
    const float* __restrict__ w_prior, const float* __restrict__ b_prior,
    const float* __restrict__ w_gen,   const float* __restrict__ b_gen,
    const int*   __restrict__ x)
{
    __shared__ __align__(16) float As[2][16][72];
    __shared__ __align__(16) float Bs[2][16][72];
    __shared__ float redbuf[16][192];
    __shared__ float sh_shift[64];
    __shared__ int   sh_xv[64];

    int vt = blockIdx.x, rt = blockIdx.y;
    int row0 = rt*64, v0 = vt*64;
    int tid = threadIdx.x;
    int tx = tid & 15, ty = tid >> 4;

    if (tid < 64){
        sh_shift[tid] = g_cst[0] - 0.5f*g_sumz2[row0+tid];
        sh_xv[tid]    = x[row0+tid];
    }

    float accP[4][4] = {};
    float accM[4][4] = {};
    float accG[4][4] = {};

    gemm_phase(g_h,  Hn,    w_prior, Hn,    Hn/16,   row0, v0, tid, As, Bs, accP);
    gemm_phase(g_ZZ, 2*Kn,  g_W2,    2*Kn,  (2*Kn)/16, row0, v0, tid, As, Bs, accM);
    gemm_phase(g_z,  Kn,    w_gen,   Kn,    Kn/16,   row0, v0, tid, As, Bs, accG);

    __syncthreads();

    float p1[4] = {0.f,0.f,0.f,0.f};
    float p2[4] = {0.f,0.f,0.f,0.f};
    float p3[4] = {0.f,0.f,0.f,0.f};
    #pragma unroll
    for (int j = 0; j < 4; j++){
        int v = v0 + tx*4 + j;
        bool ok = v < Vn;
        float bp = ok ? b_prior[v] : 0.f;
        float bg = ok ? b_gen[v]   : 0.f;
        float cv = ok ? g_cst[v]   : 0.f;
        #pragma unroll
        for (int i = 0; i < 4; i++){
            int ml = ty*4 + i;
            float s1 = accP[i][j] + bp;
            float s3 = accG[i][j] + bg;
            float s2 = s1 + cv + accM[i][j] - sh_shift[ml];
            if (ok){
                p1[i] += expf(s1);
                p2[i] += expf(s2);
                p3[i] += expf(s3);
                if (v == sh_xv[ml]) g_tgt[row0+ml] = s3;
            }
        }
    }
    #pragma unroll
    for (int i = 0; i < 4; i++){
        int ml = ty*4 + i;
        redbuf[tx][ml*3+0] = p1[i];
        redbuf[tx][ml*3+1] = p2[i];
        redbuf[tx][ml*3+2] = p3[i];
    }
    __syncthreads();
    if (tid < 192){
        float s = 0.f;
        #pragma unroll
        for (int t = 0; t < 16; t++) s += redbuf[t][tid];
        int ml = tid/3, sx = tid - ml*3;
        g_part[(sx*NVT + vt)*BT + row0 + ml] = s;
    }
}

// ---------------- per-row LSE finish ----------------
__global__ void k_lse(const int* __restrict__ x_sl)
{
    int row = blockIdx.x*256 + threadIdx.x;
    if (row >= BT) return;
    float S1=0.f, S2=0.f, S3=0.f;
    for (int vt = 0; vt < NVT; vt++){
        S1 += g_part[(0*NVT+vt)*BT + row];
        S2 += g_part[(1*NVT+vt)*BT + row];
        S3 += g_part[(2*NVT+vt)*BT + row];
    }
    int b = row / Tn, t = row % Tn;
    float shift = g_cst[0] - 0.5f*g_sumz2[row];
    float lse_p = logf(S1);
    float lse_m = shift + logf(S2);
    float lse_g = logf(S3);
    float mask = (t < x_sl[b]) ? 1.f : 0.f;
    g_contrib[row] = mask * (g_tgt[row] - lse_g - g_qzlp[row] + (lse_m - lse_p));
}

// ---------------- final scalar ----------------
__global__ void k_final(const int* __restrict__ x_sl, float* __restrict__ out)
{
    __shared__ float red[256];
    int tid = threadIdx.x;
    float s = 0.f;
    for (int i = tid; i < BT; i += 256) s += g_contrib[i];
    red[tid] = s; __syncthreads();
    for (int st = 128; st > 0; st >>= 1){
        if (tid < st) red[tid] += red[tid+st];
        __syncthreads();
    }
    if (tid == 0){
        int tot = 0;
        for (int b = 0; b < Bn; b++) tot += x_sl[b];
        out[0] = -red[0] / (float)tot;
    }
}

// ---------------- launch ----------------
extern "C" void kernel_launch(void* const* d_in, const int* in_sizes, int n_in,
                              void* d_out, int out_size)
{
    const int*   x       = (const int*)  d_in[0];
    const int*   x_sl    = (const int*)  d_in[1];
    const float* eps     = (const float*)d_in[2];
    const float* emb     = (const float*)d_in[3];
    const float* w_ih    = (const float*)d_in[4];
    const float* w_hh    = (const float*)d_in[5];
    const float* b_ih    = (const float*)d_in[6];
    const float* b_hh    = (const float*)d_in[7];
    const float* w_prior = (const float*)d_in[8];
    const float* b_prior = (const float*)d_in[9];
    const float* w_gen   = (const float*)d_in[10];
    const float* b_gen   = (const float*)d_in[11];
    float* out = (float*)d_out;

    k_init<<<(Bn*Hn + 255)/256, 256>>>();
    k_prep_z<<<BT, 256>>>(x, x_sl, eps, emb);
    k_prep_v<<<Vn, 256>>>(emb);
    k_xproj<<<dim3(G4n/64, BT/64), 256>>>(w_ih, b_ih, b_hh);
    for (int t = 0; t < Tn; t++)
        k_lstm<<<dim3(32, Bn), 256>>>(w_hh, t);
    k_big<<<dim3(NVT, BT/64), 256>>>(w_prior, b_prior, w_gen, b_gen, x);
    k_lse<<<BT/256, 256>>>(x_sl);
    k_final<<<1, 256>>>(x_sl, out);
}

// round 5
// speedup vs baseline: 2.9904x; 1.1319x over previous
#include <cuda_runtime.h>
#include <cstdint>

#define Bn 32
#define Tn 128
#define Kn 256
#define Hn 512
#define Vn 10000
#define BT (Bn*Tn)
#define G4n (4*Hn)
#define TWOK (2*Kn)
#define NVT 157              // ceil(Vn/64)

#define HALF_LOG_2PI 0.918938533204672741780329736406f

// ---------------- static scratch ----------------
__device__ __align__(16) float g_z[BT*Kn];          // 4 MB
__device__ __align__(16) float g_ZZ[BT*2*Kn];       // 8 MB  [z | z^2]
__device__ __align__(16) float g_h[BT*Hn];          // 8 MB
__device__ __align__(16) float g_xproj[BT*G4n];     // 32 MB
__device__ __align__(16) float g_W2[Vn*2*Kn];       // 20 MB [2*inv2var*mu | -inv2var]
__device__ float g_cst[Vn];
__device__ float g_qzlp[BT];
__device__ float g_sumz2[BT];
__device__ float g_tgt[BT];
__device__ float g_part[3*NVT*BT];
__device__ float g_contrib[BT];
__device__ __align__(16) float g_hbuf[2][Bn*Hn];
__device__ float g_cstate[Bn*Hn];

__device__ __forceinline__ float softplus_b(float x){
    return (x > 20.f) ? x : log2f(1.f + exp2f(x));
}
__device__ __forceinline__ float sigmf(float x){ return 1.f/(1.f+expf(-x)); }

// ---------------- init ----------------
__global__ void k_init(){
    int i = blockIdx.x*blockDim.x + threadIdx.x;
    if (i < Bn*Hn){ g_hbuf[0][i] = 0.f; g_cstate[i] = 0.f; }
}

// ---------------- per-(b,t): z, z^2, q_z_lp, sum z^2 ----------------
__global__ void k_prep_z(const int* __restrict__ x, const int* __restrict__ x_sl,
                         const float* __restrict__ eps, const float* __restrict__ emb)
{
    int row = blockIdx.x;
    int k   = threadIdx.x;
    int b = row / Tn, t = row % Tn;
    int xv = x[row];
    float mask = (t < x_sl[b]) ? 1.f : 0.f;
    float mu = emb[xv*TWOK + k];
    float sq = softplus_b(emb[xv*TWOK + Kn + k]);
    float e  = eps[row*Kn + k];
    float zv = (mu + sq*e) * mask;
    g_z[row*Kn + k] = zv;
    g_ZZ[row*2*Kn + k]      = zv;
    g_ZZ[row*2*Kn + Kn + k] = zv*zv;
    float q = -HALF_LOG_2PI - logf(sq) - 0.5f*e*e;
    __shared__ float r1[256], r2[256];
    r1[k] = q; r2[k] = zv*zv;
    __syncthreads();
    for (int s = 128; s > 0; s >>= 1){
        if (k < s){ r1[k] += r1[k+s]; r2[k] += r2[k+s]; }
        __syncthreads();
    }
    if (k == 0){ g_qzlp[row] = r1[0]; g_sumz2[row] = r2[0]; }
}

// ---------------- per-v: W2, const ----------------
__global__ void k_prep_v(const float* __restrict__ emb)
{
    int v = blockIdx.x;
    int k = threadIdx.x;
    float mu = emb[v*TWOK + k];
    float sp = softplus_b(emb[v*TWOK + Kn + k]);
    float inv2 = 0.5f/(sp*sp);
    g_W2[v*2*Kn + k]      = 2.f*inv2*mu;
    g_W2[v*2*Kn + Kn + k] = -inv2;
    float c = -HALF_LOG_2PI - logf(sp) - mu*mu*inv2;
    __shared__ float red[256];
    red[k] = c;
    __syncthreads();
    for (int s = 128; s > 0; s >>= 1){
        if (k < s) red[k] += red[k+s];
        __syncthreads();
    }
    if (k == 0) g_cst[v] = red[0];
}

// ---------------- x_proj GEMM ----------------
__global__ __launch_bounds__(256) void k_xproj(const float* __restrict__ w_ih,
        const float* __restrict__ b_ih, const float* __restrict__ b_hh)
{
    __shared__ __align__(16) float As[32][68];
    __shared__ __align__(16) float Bs[32][68];
    int tid = threadIdx.x;
    int tx = tid & 15, ty = tid >> 4;
    int brow = blockIdx.y * 64;
    int bcol = blockIdx.x * 64;
    float acc[4][4];
    #pragma unroll
    for (int i=0;i<4;i++)
        #pragma unroll
        for (int j=0;j<4;j++) acc[i][j]=0.f;

    for (int k0 = 0; k0 < Kn; k0 += 32){
        #pragma unroll
        for (int l = 0; l < 2; l++){
            int idx = tid + l*256;
            int m = idx >> 3, kq = idx & 7;
            int grow = brow + m;
            float4 aval = make_float4(0.f,0.f,0.f,0.f);
            if ((grow & (Tn-1)) != 0)
                aval = *(const float4*)(g_z + (grow-1)*Kn + k0 + kq*4);
            As[kq*4+0][m]=aval.x; As[kq*4+1][m]=aval.y; As[kq*4+2][m]=aval.z; As[kq*4+3][m]=aval.w;
            int g = bcol + m;
            float4 bval = *(const float4*)(w_ih + g*Kn + k0 + kq*4);
            Bs[kq*4+0][m]=bval.x; Bs[kq*4+1][m]=bval.y; Bs[kq*4+2][m]=bval.z; Bs[kq*4+3][m]=bval.w;
        }
        __syncthreads();
        #pragma unroll
        for (int kk = 0; kk < 32; kk++){
            float4 a  = *(const float4*)&As[kk][ty*4];
            float4 bq = *(const float4*)&Bs[kk][tx*4];
            acc[0][0]+=a.x*bq.x; acc[0][1]+=a.x*bq.y; acc[0][2]+=a.x*bq.z; acc[0][3]+=a.x*bq.w;
            acc[1][0]+=a.y*bq.x; acc[1][1]+=a.y*bq.y; acc[1][2]+=a.y*bq.z; acc[1][3]+=a.y*bq.w;
            acc[2][0]+=a.z*bq.x; acc[2][1]+=a.z*bq.y; acc[2][2]+=a.z*bq.z; acc[2][3]+=a.z*bq.w;
            acc[3][0]+=a.w*bq.x; acc[3][1]+=a.w*bq.y; acc[3][2]+=a.w*bq.z; acc[3][3]+=a.w*bq.w;
        }
        __syncthreads();
    }
    #pragma unroll
    for (int i = 0; i < 4; i++){
        int row = brow + ty*4 + i;
        int col = bcol + tx*4;
        float4 o;
        o.x = acc[i][0] + b_ih[col+0] + b_hh[col+0];
        o.y = acc[i][1] + b_ih[col+1] + b_hh[col+1];
        o.z = acc[i][2] + b_ih[col+2] + b_hh[col+2];
        o.w = acc[i][3] + b_ih[col+3] + b_hh[col+3];
        *(float4*)(g_xproj + row*G4n + col) = o;
    }
}

// ---------------- LSTM step v3: w_hh read ONCE per step ----------------
// 128 CTAs; CTA = 4 j-slots x 4 gates (16 gate-rows) for ALL 32 batches.
// lane = batch; each warp owns 2 gate-rows, accumulates full K=512 dot.
__global__ __launch_bounds__(256) void k_lstm(const float* __restrict__ w_hh, int t)
{
    extern __shared__ float h_s[];        // 32 * 516 floats (66 KB)
    __shared__ float gbuf[16][33];
    int tid = threadIdx.x, lane = tid & 31, w = tid >> 5;
    int js = blockIdx.x;                  // j-slice of 4 (0..127)
    int par = t & 1;

    for (int i = tid; i < 32*128; i += 256){
        int b = i >> 7, q = i & 127;
        *(float4*)&h_s[b*516 + q*4] = *(const float4*)&g_hbuf[par][b*512 + q*4];
    }
    __syncthreads();

    int r0 = w*2, r1 = w*2 + 1;           // local rows 0..15: gate = r>>2, jj = r&3
    int grow0 = (r0>>2)*Hn + js*4 + (r0&3);
    int grow1 = (r1>>2)*Hn + js*4 + (r1&3);
    const float4* wp0 = (const float4*)(w_hh + (size_t)grow0*Hn);
    const float4* wp1 = (const float4*)(w_hh + (size_t)grow1*Hn);
    const float4* hb  = (const float4*)(h_s + lane*516);

    float a0 = 0.f, a1 = 0.f;
    #pragma unroll 8
    for (int q = 0; q < 128; q++){
        float4 hv = hb[q];
        float4 w0 = __ldg(wp0 + q);       // uniform across warp -> broadcast
        float4 w1 = __ldg(wp1 + q);
        a0 += w0.x*hv.x + w0.y*hv.y + w0.z*hv.z + w0.w*hv.w;
        a1 += w1.x*hv.x + w1.y*hv.y + w1.z*hv.z + w1.w*hv.w;
    }
    a0 += g_xproj[(lane*Tn + t)*G4n + grow0];
    a1 += g_xproj[(lane*Tn + t)*G4n + grow1];
    gbuf[r0][lane] = a0;
    gbuf[r1][lane] = a1;
    __syncthreads();

    if (tid < 128){
        int b = tid & 31, jj = tid >> 5;
        int j = js*4 + jj;
        float iv = gbuf[jj][b], fv = gbuf[4+jj][b], gv = gbuf[8+jj][b], ov = gbuf[12+jj][b];
        float c = g_cstate[b*Hn + j];
        c = sigmf(fv)*c + sigmf(iv)*tanhf(gv);
        float hv2 = sigmf(ov)*tanhf(c);
        g_cstate[b*Hn + j] = c;
        g_hbuf[par^1][b*Hn + j] = hv2;
        g_h[(b*Tn + t)*Hn + j] = hv2;
    }
}

// ================= k_big: TF32 tensor-core triple GEMM + fused LSE =================
#define BM 128
#define BN 64
#define LDSA 36

struct SmemBig {
    float As[2][BM][LDSA];
    float Bs[2][BN][LDSA];
};

__device__ __forceinline__ uint32_t f2tf(float f){
    uint32_t r; asm("cvt.rna.tf32.f32 %0, %1;" : "=r"(r) : "f"(f)); return r;
}
__device__ __forceinline__ float4 tf4(float4 v){
    float4 o;
    o.x = __uint_as_float(f2tf(v.x)); o.y = __uint_as_float(f2tf(v.y));
    o.z = __uint_as_float(f2tf(v.z)); o.w = __uint_as_float(f2tf(v.w));
    return o;
}
__device__ __forceinline__ void mma8(float* d, const uint32_t* a, const uint32_t* b){
    asm volatile("mma.sync.aligned.m16n8k8.row.col.f32.tf32.tf32.f32 "
        "{%0,%1,%2,%3}, {%4,%5,%6,%7}, {%8,%9}, {%0,%1,%2,%3};"
        : "+f"(d[0]), "+f"(d[1]), "+f"(d[2]), "+f"(d[3])
        : "r"(a[0]), "r"(a[1]), "r"(a[2]), "r"(a[3]), "r"(b[0]), "r"(b[1]));
}

__device__ __forceinline__ void ldA(const float* __restrict__ Ag, int lda, int row0,
                                    int kt, int tid, float4 (&rA)[4]){
    #pragma unroll
    for (int i=0;i<4;i++){
        int idx = tid + i*256;
        int row = idx>>3, q = idx&7;
        rA[i] = *(const float4*)(Ag + (size_t)(row0+row)*lda + kt*32 + q*4);
    }
}
__device__ __forceinline__ void ldB(const float* __restrict__ Bg, int ldb, int v0,
                                    int kt, int tid, float4 (&rB)[2]){
    #pragma unroll
    for (int i=0;i<2;i++){
        int idx = tid + i*256;
        int row = idx>>3, q = idx&7;
        rB[i] = (v0+row < Vn) ? *(const float4*)(Bg + (size_t)(v0+row)*ldb + kt*32 + q*4)
                              : make_float4(0.f,0.f,0.f,0.f);
    }
}
__device__ __forceinline__ void stAB(SmemBig* sm, int buf, int tid,
                                     const float4 (&rA)[4], const float4 (&rB)[2]){
    #pragma unroll
    for (int i=0;i<4;i++){
        int idx = tid + i*256; int row = idx>>3, q = idx&7;
        *(float4*)&sm->As[buf][row][q*4] = tf4(rA[i]);
    }
    #pragma unroll
    for (int i=0;i<2;i++){
        int idx = tid + i*256; int row = idx>>3, q = idx&7;
        *(float4*)&sm->Bs[buf][row][q*4] = tf4(rB[i]);
    }
}

__device__ __forceinline__ void comp(SmemBig* sm, int buf, int lane, int moff, int noff,
                                     float (&acc)[8][4]){
    #pragma unroll
    for (int k8=0;k8<4;k8++){
        int kb = k8*8 + (lane&3);
        uint32_t afr[2][4], bfr[4][2];
        int mg = moff + (lane>>2);
        #pragma unroll
        for (int mt=0;mt<2;mt++){
            const float* a0p = &sm->As[buf][mg+mt*16][kb];
            const float* a1p = &sm->As[buf][mg+mt*16+8][kb];
            afr[mt][0] = __float_as_uint(a0p[0]);
            afr[mt][1] = __float_as_uint(a1p[0]);
            afr[mt][2] = __float_as_uint(a0p[4]);
            afr[mt][3] = __float_as_uint(a1p[4]);
        }
        int ng = noff + (lane>>2);
        #pragma unroll
        for (int nt=0;nt<4;nt++){
            const float* bp = &sm->Bs[buf][ng+nt*8][kb];
            bfr[nt][0] = __float_as_uint(bp[0]);
            bfr[nt][1] = __float_as_uint(bp[4]);
        }
        #pragma unroll
        for (int mt=0;mt<2;mt++)
            #pragma unroll
            for (int nt=0;nt<4;nt++)
                mma8(acc[mt*4+nt], afr[mt], bfr[nt]);
    }
}

__device__ __forceinline__ void gemm_tc(SmemBig* sm,
    const float* __restrict__ Ag, int lda,
    const float* __restrict__ Bg, int ldb,
    int nchunks, int row0, int v0, int tid, float (&acc)[8][4])
{
    int lane = tid&31, wid = tid>>5;
    int moff = (wid>>1)*32, noff = (wid&1)*32;
    float4 rA[4]; float4 rB[2];
    ldA(Ag,lda,row0,0,tid,rA); ldB(Bg,ldb,v0,0,tid,rB);
    stAB(sm,0,tid,rA,rB);
    __syncthreads();
    for (int kt=0; kt<nchunks; kt++){
        int cur = kt&1;
        bool more = (kt+1 < nchunks);
        if (more){ ldA(Ag,lda,row0,kt+1,tid,rA); ldB(Bg,ldb,v0,kt+1,tid,rB); }
        comp(sm,cur,lane,moff,noff,acc);
        if (more) stAB(sm,cur^1,tid,rA,rB);
        __syncthreads();
    }
}

extern __shared__ char dynsm[];
__global__ __launch_bounds__(256,1) void k_big(
    const float* __restrict__ w_prior, const float* __restrict__ b_prior,
    const float* __restrict__ w_gen,   const float* __restrict__ b_gen,
    const int*   __restrict__ x)
{
    SmemBig* sm = (SmemBig*)dynsm;
    __shared__ float sh_sum[128][3];
    __shared__ float sh_shift[128];
    __shared__ int   sh_xv[128];

    int vt = blockIdx.x, rt = blockIdx.y;
    int row0 = rt*BM, v0 = vt*BN;
    int tid = threadIdx.x;

    if (tid < 128){
        sh_shift[tid] = g_cst[0] - 0.5f*g_sumz2[row0+tid];
        sh_xv[tid]    = x[row0+tid];
        sh_sum[tid][0]=0.f; sh_sum[tid][1]=0.f; sh_sum[tid][2]=0.f;
    }

    float accP[8][4] = {};
    float accM[8][4] = {};
    float accG[8][4] = {};

    gemm_tc(sm, g_h,  Hn,   w_prior, Hn,   Hn/32,   row0, v0, tid, accP);
    gemm_tc(sm, g_ZZ, TWOK, g_W2,    TWOK, TWOK/32, row0, v0, tid, accM);
    gemm_tc(sm, g_z,  Kn,   w_gen,   Kn,   Kn/32,   row0, v0, tid, accG);

    __syncthreads();

    int lane = tid&31, wid = tid>>5;
    int moff = (wid>>1)*32, noff = (wid&1)*32;
    float rs[4][3] = {};
    #pragma unroll
    for (int nt=0; nt<4; nt++){
        #pragma unroll
        for (int c=0;c<2;c++){
            int n = noff + nt*8 + (lane&3)*2 + c;
            int v = v0 + n;
            bool ok = v < Vn;
            int vc = ok ? v : (Vn-1);
            float bp = __ldg(&b_prior[vc]);
            float bg = __ldg(&b_gen[vc]);
            float cv = g_cst[vc];
            #pragma unroll
            for (int mt=0;mt<2;mt++){
                #pragma unroll
                for (int hf=0; hf<2; hf++){
                    int rloc = moff + mt*16 + (lane>>2) + hf*8;
                    int ai = hf*2 + c;
                    float s1 = accP[mt*4+nt][ai] + bp;
                    float s3 = accG[mt*4+nt][ai] + bg;
                    float s2 = s1 + cv + accM[mt*4+nt][ai] - sh_shift[rloc];
                    if (ok){
                        rs[mt*2+hf][0] += expf(s1);
                        rs[mt*2+hf][1] += expf(s2);
                        rs[mt*2+hf][2] += expf(s3);
                        if (v == sh_xv[rloc]) g_tgt[row0 + rloc] = s3;
                    }
                }
            }
        }
    }
    #pragma unroll
    for (int lr=0; lr<4; lr++){
        float v0s = rs[lr][0], v1s = rs[lr][1], v2s = rs[lr][2];
        v0s += __shfl_xor_sync(0xffffffffu, v0s, 1);
        v0s += __shfl_xor_sync(0xffffffffu, v0s, 2);
        v1s += __shfl_xor_sync(0xffffffffu, v1s, 1);
        v1s += __shfl_xor_sync(0xffffffffu, v1s, 2);
        v2s += __shfl_xor_sync(0xffffffffu, v2s, 1);
        v2s += __shfl_xor_sync(0xffffffffu, v2s, 2);
        if ((lane&3)==0){
            int mt = lr>>1, hf = lr&1;
            int rloc = moff + mt*16 + (lane>>2) + hf*8;
            atomicAdd(&sh_sum[rloc][0], v0s);
            atomicAdd(&sh_sum[rloc][1], v1s);
            atomicAdd(&sh_sum[rloc][2], v2s);
        }
    }
    __syncthreads();
    if (tid < 128){
        g_part[(0*NVT + vt)*BT + row0 + tid] = sh_sum[tid][0];
        g_part[(1*NVT + vt)*BT + row0 + tid] = sh_sum[tid][1];
        g_part[(2*NVT + vt)*BT + row0 + tid] = sh_sum[tid][2];
    }
}

// ---------------- per-row LSE finish ----------------
__global__ void k_lse(const int* __restrict__ x_sl)
{
    int row = blockIdx.x*256 + threadIdx.x;
    if (row >= BT) return;
    float S1=0.f, S2=0.f, S3=0.f;
    for (int vt = 0; vt < NVT; vt++){
        S1 += g_part[(0*NVT+vt)*BT + row];
        S2 += g_part[(1*NVT+vt)*BT + row];
        S3 += g_part[(2*NVT+vt)*BT + row];
    }
    int b = row / Tn, t = row % Tn;
    float shift = g_cst[0] - 0.5f*g_sumz2[row];
    float lse_p = logf(S1);
    float lse_m = shift + logf(S2);
    float lse_g = logf(S3);
    float mask = (t < x_sl[b]) ? 1.f : 0.f;
    g_contrib[row] = mask * (g_tgt[row] - lse_g - g_qzlp[row] + (lse_m - lse_p));
}

// ---------------- final scalar ----------------
__global__ void k_final(const int* __restrict__ x_sl, float* __restrict__ out)
{
    __shared__ float red[256];
    int tid = threadIdx.x;
    float s = 0.f;
    for (int i = tid; i < BT; i += 256) s += g_contrib[i];
    red[tid] = s; __syncthreads();
    for (int st = 128; st > 0; st >>= 1){
        if (tid < st) red[tid] += red[tid+st];
        __syncthreads();
    }
    if (tid == 0){
        int tot = 0;
        for (int b = 0; b < Bn; b++) tot += x_sl[b];
        out[0] = -red[0] / (float)tot;
    }
}

// ---------------- launch ----------------
extern "C" void kernel_launch(void* const* d_in, const int* in_sizes, int n_in,
                              void* d_out, int out_size)
{
    const int*   x       = (const int*)  d_in[0];
    const int*   x_sl    = (const int*)  d_in[1];
    const float* eps     = (const float*)d_in[2];
    const float* emb     = (const float*)d_in[3];
    const float* w_ih    = (const float*)d_in[4];
    const float* w_hh    = (const float*)d_in[5];
    const float* b_ih    = (const float*)d_in[6];
    const float* b_hh    = (const float*)d_in[7];
    const float* w_prior = (const float*)d_in[8];
    const float* b_prior = (const float*)d_in[9];
    const float* w_gen   = (const float*)d_in[10];
    const float* b_gen   = (const float*)d_in[11];
    float* out = (float*)d_out;

    int smem_big  = (int)sizeof(SmemBig);            // ~55 KB
    int smem_lstm = 32*516*(int)sizeof(float);       // ~66 KB
    cudaFuncSetAttribute(k_big,  cudaFuncAttributeMaxDynamicSharedMemorySize, smem_big);
    cudaFuncSetAttribute(k_lstm, cudaFuncAttributeMaxDynamicSharedMemorySize, smem_lstm);

    k_init<<<(Bn*Hn + 255)/256, 256>>>();
    k_prep_z<<<BT, 256>>>(x, x_sl, eps, emb);
    k_prep_v<<<Vn, 256>>>(emb);
    k_xproj<<<dim3(G4n/64, BT/64), 256>>>(w_ih, b_ih, b_hh);
    for (int t = 0; t < Tn; t++)
        k_lstm<<<128, 256, smem_lstm>>>(w_hh, t);
    k_big<<<dim3(NVT, BT/BM), 256, smem_big>>>(w_prior, b_prior, w_gen, b_gen, x);
    k_lse<<<BT/256, 256>>>(x_sl);
    k_final<<<1, 256>>>(x_sl, out);
}

// round 7
// speedup vs baseline: 5.2068x; 1.7412x over previous
#include <cuda_runtime.h>
#include <cstdint>

#define Bn 32
#define Tn 128
#define Kn 256
#define Hn 512
#define Vn 10000
#define BT (Bn*Tn)
#define G4n (4*Hn)
#define TWOK (2*Kn)
#define NVT 157              // ceil(Vn/64)

#define HALF_LOG_2PI 0.918938533204672741780329736406f

// ---------------- static scratch ----------------
__device__ __align__(16) float g_z[BT*Kn];          // 4 MB
__device__ __align__(16) float g_ZZ[BT*2*Kn];       // 8 MB  [z | z^2]
__device__ __align__(16) float g_h[BT*Hn];          // 8 MB
__device__ __align__(16) float g_xproj[BT*G4n];     // 32 MB
__device__ __align__(16) float g_W2[Vn*2*Kn];       // 20 MB [2*inv2var*mu | -inv2var]
__device__ float g_cst[Vn];
__device__ float g_qzlp[BT];
__device__ float g_sumz2[BT];
__device__ float g_tgt[BT];
__device__ float g_part[3*NVT*BT];
__device__ float g_contrib[BT];
__device__ __align__(16) float g_hbuf[2][Bn*Hn];
__device__ unsigned g_ctr;                          // persistent-LSTM step barrier

__device__ __forceinline__ float softplus_b(float x){
    return (x > 20.f) ? x : log2f(1.f + exp2f(x));
}
__device__ __forceinline__ float sigmf(float x){ return 1.f/(1.f+expf(-x)); }

// ---------------- init ----------------
__global__ void k_init(){
    int i = blockIdx.x*blockDim.x + threadIdx.x;
    if (i < Bn*Hn){ g_hbuf[0][i] = 0.f; }
    if (i == 0) g_ctr = 0u;
}

// ---------------- per-(b,t): z, z^2, q_z_lp, sum z^2 ----------------
__global__ void k_prep_z(const int* __restrict__ x, const int* __restrict__ x_sl,
                         const float* __restrict__ eps, const float* __restrict__ emb)
{
    int row = blockIdx.x;
    int k   = threadIdx.x;
    int b = row / Tn, t = row % Tn;
    int xv = x[row];
    float mask = (t < x_sl[b]) ? 1.f : 0.f;
    float mu = emb[xv*TWOK + k];
    float sq = softplus_b(emb[xv*TWOK + Kn + k]);
    float e  = eps[row*Kn + k];
    float zv = (mu + sq*e) * mask;
    g_z[row*Kn + k] = zv;
    g_ZZ[row*2*Kn + k]      = zv;
    g_ZZ[row*2*Kn + Kn + k] = zv*zv;
    float q = -HALF_LOG_2PI - logf(sq) - 0.5f*e*e;
    __shared__ float r1[256], r2[256];
    r1[k] = q; r2[k] = zv*zv;
    __syncthreads();
    for (int s = 128; s > 0; s >>= 1){
        if (k < s){ r1[k] += r1[k+s]; r2[k] += r2[k+s]; }
        __syncthreads();
    }
    if (k == 0){ g_qzlp[row] = r1[0]; g_sumz2[row] = r2[0]; }
}

// ---------------- per-v: W2, const ----------------
__global__ void k_prep_v(const float* __restrict__ emb)
{
    int v = blockIdx.x;
    int k = threadIdx.x;
    float mu = emb[v*TWOK + k];
    float sp = softplus_b(emb[v*TWOK + Kn + k]);
    float inv2 = 0.5f/(sp*sp);
    g_W2[v*2*Kn + k]      = 2.f*inv2*mu;
    g_W2[v*2*Kn + Kn + k] = -inv2;
    float c = -HALF_LOG_2PI - logf(sp) - mu*mu*inv2;
    __shared__ float red[256];
    red[k] = c;
    __syncthreads();
    for (int s = 128; s > 0; s >>= 1){
        if (k < s) red[k] += red[k+s];
        __syncthreads();
    }
    if (k == 0) g_cst[v] = red[0];
}

// ---------------- x_proj GEMM ----------------
__global__ __launch_bounds__(256) void k_xproj(const float* __restrict__ w_ih,
        const float* __restrict__ b_ih, const float* __restrict__ b_hh)
{
    __shared__ __align__(16) float As[32][68];
    __shared__ __align__(16) float Bs[32][68];
    int tid = threadIdx.x;
    int tx = tid & 15, ty = tid >> 4;
    int brow = blockIdx.y * 64;
    int bcol = blockIdx.x * 64;
    float acc[4][4];
    #pragma unroll
    for (int i=0;i<4;i++)
        #pragma unroll
        for (int j=0;j<4;j++) acc[i][j]=0.f;

    for (int k0 = 0; k0 < Kn; k0 += 32){
        #pragma unroll
        for (int l = 0; l < 2; l++){
            int idx = tid + l*256;
            int m = idx >> 3, kq = idx & 7;
            int grow = brow + m;
            float4 aval = make_float4(0.f,0.f,0.f,0.f);
            if ((grow & (Tn-1)) != 0)
                aval = *(const float4*)(g_z + (grow-1)*Kn + k0 + kq*4);
            As[kq*4+0][m]=aval.x; As[kq*4+1][m]=aval.y; As[kq*4+2][m]=aval.z; As[kq*4+3][m]=aval.w;
            int g = bcol + m;
            float4 bval = *(const float4*)(w_ih + g*Kn + k0 + kq*4);
            Bs[kq*4+0][m]=bval.x; Bs[kq*4+1][m]=bval.y; Bs[kq*4+2][m]=bval.z; Bs[kq*4+3][m]=bval.w;
        }
        __syncthreads();
        #pragma unroll
        for (int kk = 0; kk < 32; kk++){
            float4 a  = *(const float4*)&As[kk][ty*4];
            float4 bq = *(const float4*)&Bs[kk][tx*4];
            acc[0][0]+=a.x*bq.x; acc[0][1]+=a.x*bq.y; acc[0][2]+=a.x*bq.z; acc[0][3]+=a.x*bq.w;
            acc[1][0]+=a.y*bq.x; acc[1][1]+=a.y*bq.y; acc[1][2]+=a.y*bq.z; acc[1][3]+=a.y*bq.w;
            acc[2][0]+=a.z*bq.x; acc[2][1]+=a.z*bq.y; acc[2][2]+=a.z*bq.z; acc[2][3]+=a.z*bq.w;
            acc[3][0]+=a.w*bq.x; acc[3][1]+=a.w*bq.y; acc[3][2]+=a.w*bq.z; acc[3][3]+=a.w*bq.w;
        }
        __syncthreads();
    }
    #pragma unroll
    for (int i = 0; i < 4; i++){
        int row = brow + ty*4 + i;
        int col = bcol + tx*4;
        float4 o;
        o.x = acc[i][0] + b_ih[col+0] + b_hh[col+0];
        o.y = acc[i][1] + b_ih[col+1] + b_hh[col+1];
        o.z = acc[i][2] + b_ih[col+2] + b_hh[col+2];
        o.w = acc[i][3] + b_ih[col+3] + b_hh[col+3];
        *(float4*)(g_xproj + row*G4n + col) = o;
    }
}

// ================= persistent LSTM: single launch, device-side step barrier =================
// 128 CTAs (all resident). CTA js owns 16 gate-rows (4 j-slots x 4 gates) for all 32 batches.
// w_hh slice cached in smem once; c-state in registers; h through double-buffered global.
// warp w: jh = w>>2 (j-half of 256), rq = w&3 (4 local rows rq*4..rq*4+3).
__global__ __launch_bounds__(256) void k_lstm_all(const float* __restrict__ w_hh)
{
    extern __shared__ float sm[];
    float* w_s  = sm;                    // 16*512 = 8192 floats (32 KB)
    float* h_s  = sm + 16*512;           // 32*516 floats (66 KB)
    float* pbuf = h_s + 32*516;          // 2*16*33 floats
    int tid = threadIdx.x, lane = tid & 31, w = tid >> 5;
    int js = blockIdx.x;                 // 0..127

    // load w_hh slice (once): local row r -> global row (r>>2)*Hn + js*4 + (r&3)
    for (int i = tid; i < 16*128; i += 256){
        int r = i >> 7, q = i & 127;
        int grow = (r>>2)*Hn + js*4 + (r&3);
        *(float4*)&w_s[r*512 + q*4] = *(const float4*)&w_hh[(size_t)grow*Hn + q*4];
    }

    int jh = w >> 2;
    int rq = w & 3;
    const float4* wr0 = (const float4*)(w_s + (rq*4+0)*512) + jh*64;
    const float4* wr1 = (const float4*)(w_s + (rq*4+1)*512) + jh*64;
    const float4* wr2 = (const float4*)(w_s + (rq*4+2)*512) + jh*64;
    const float4* wr3 = (const float4*)(w_s + (rq*4+3)*512) + jh*64;

    float c_reg = 0.f;                   // (b = tid&31, jj = tid>>5) for tid<128
    volatile unsigned* vc = &g_ctr;

    for (int t = 0; t < Tn; t++){
        int par = t & 1;
        if (tid == 0 && t > 0){
            unsigned target = (unsigned)t * 128u;
            while (*vc < target) {}
        }
        __syncthreads();                 // barrier orders h loads after observation

        // stage h(t-1) into smem (L2-coherent loads; bypass possibly-stale L1)
        for (int i = tid; i < 32*128; i += 256){
            int b = i >> 7, q = i & 127;
            float4 hv = __ldcg((const float4*)&g_hbuf[par][b*512 + q*4]);
            *(float4*)&h_s[b*516 + q*4] = hv;
        }
        __syncthreads();

        // partial dots: lane = batch, 4 rows, half of j
        {
            const float4* hb = (const float4*)(h_s + lane*516) + jh*64;
            float a0=0.f, a1=0.f, a2=0.f, a3=0.f;
            #pragma unroll 8
            for (int q = 0; q < 64; q++){
                float4 hv = hb[q];
                float4 w0 = wr0[q], w1 = wr1[q], w2 = wr2[q], w3 = wr3[q];
                a0 += w0.x*hv.x + w0.y*hv.y + w0.z*hv.z + w0.w*hv.w;
                a1 += w1.x*hv.x + w1.y*hv.y + w1.z*hv.z + w1.w*hv.w;
                a2 += w2.x*hv.x + w2.y*hv.y + w2.z*hv.z + w2.w*hv.w;
                a3 += w3.x*hv.x + w3.y*hv.y + w3.z*hv.z + w3.w*hv.w;
            }
            pbuf[(jh*16 + rq*4+0)*33 + lane] = a0;
            pbuf[(jh*16 + rq*4+1)*33 + lane] = a1;
            pbuf[(jh*16 + rq*4+2)*33 + lane] = a2;
            pbuf[(jh*16 + rq*4+3)*33 + lane] = a3;
        }
        __syncthreads();

        // activations: thread (b = tid&31, jj = tid>>5) for tid<128
        if (tid < 128){
            int b = tid & 31, jj = tid >> 5;
            int j = js*4 + jj;
            float g4[4];
            #pragma unroll
            for (int gate = 0; gate < 4; gate++){
                int r = gate*4 + jj;
                g4[gate] = pbuf[r*33 + b] + pbuf[(16 + r)*33 + b]
                         + g_xproj[(b*Tn + t)*G4n + gate*Hn + j];
            }
            float c = c_reg;
            c = sigmf(g4[1])*c + sigmf(g4[0])*tanhf(g4[2]);
            float hv = sigmf(g4[3])*tanhf(c);
            c_reg = c;
            g_hbuf[par^1][b*512 + j] = hv;
            g_h[(b*Tn + t)*Hn + j] = hv;
        }
        __threadfence();                 // release h writes to GPU scope
        __syncthreads();
        if (tid == 0) atomicAdd(&g_ctr, 1u);
    }
}

// ================= k_big: TF32 tensor-core triple GEMM + fused LSE =================
#define BM 128
#define BN 64
#define LDSA 36

struct SmemBig {
    float As[2][BM][LDSA];
    float Bs[2][BN][LDSA];
};

__device__ __forceinline__ uint32_t f2tf(float f){
    uint32_t r; asm("cvt.rna.tf32.f32 %0, %1;" : "=r"(r) : "f"(f)); return r;
}
__device__ __forceinline__ float4 tf4(float4 v){
    float4 o;
    o.x = __uint_as_float(f2tf(v.x)); o.y = __uint_as_float(f2tf(v.y));
    o.z = __uint_as_float(f2tf(v.z)); o.w = __uint_as_float(f2tf(v.w));
    return o;
}
__device__ __forceinline__ void mma8(float* d, const uint32_t* a, const uint32_t* b){
    asm volatile("mma.sync.aligned.m16n8k8.row.col.f32.tf32.tf32.f32 "
        "{%0,%1,%2,%3}, {%4,%5,%6,%7}, {%8,%9}, {%0,%1,%2,%3};"
        : "+f"(d[0]), "+f"(d[1]), "+f"(d[2]), "+f"(d[3])
        : "r"(a[0]), "r"(a[1]), "r"(a[2]), "r"(a[3]), "r"(b[0]), "r"(b[1]));
}

__device__ __forceinline__ void ldA(const float* __restrict__ Ag, int lda, int row0,
                                    int kt, int tid, float4 (&rA)[4]){
    #pragma unroll
    for (int i=0;i<4;i++){
        int idx = tid + i*256;
        int row = idx>>3, q = idx&7;
        rA[i] = *(const float4*)(Ag + (size_t)(row0+row)*lda + kt*32 + q*4);
    }
}
__device__ __forceinline__ void ldB(const float* __restrict__ Bg, int ldb, int v0,
                                    int kt, int tid, float4 (&rB)[2]){
    #pragma unroll
    for (int i=0;i<2;i++){
        int idx = tid + i*256;
        int row = idx>>3, q = idx&7;
        rB[i] = (v0+row < Vn) ? *(const float4*)(Bg + (size_t)(v0+row)*ldb + kt*32 + q*4)
                              : make_float4(0.f,0.f,0.f,0.f);
    }
}
__device__ __forceinline__ void stAB(SmemBig* sm, int buf, int tid,
                                     const float4 (&rA)[4], const float4 (&rB)[2]){
    #pragma unroll
    for (int i=0;i<4;i++){
        int idx = tid + i*256; int row = idx>>3, q = idx&7;
        *(float4*)&sm->As[buf][row][q*4] = tf4(rA[i]);
    }
    #pragma unroll
    for (int i=0;i<2;i++){
        int idx = tid + i*256; int row = idx>>3, q = idx&7;
        *(float4*)&sm->Bs[buf][row][q*4] = tf4(rB[i]);
    }
}

__device__ __forceinline__ void comp(SmemBig* sm, int buf, int lane, int moff, int noff,
                                     float (&acc)[8][4]){
    #pragma unroll
    for (int k8=0;k8<4;k8++){
        int kb = k8*8 + (lane&3);
        uint32_t afr[2][4], bfr[4][2];
        int mg = moff + (lane>>2);
        #pragma unroll
        for (int mt=0;mt<2;mt++){
            const float* a0p = &sm->As[buf][mg+mt*16][kb];
            const float* a1p = &sm->As[buf][mg+mt*16+8][kb];
            afr[mt][0] = __float_as_uint(a0p[0]);
            afr[mt][1] = __float_as_uint(a1p[0]);
            afr[mt][2] = __float_as_uint(a0p[4]);
            afr[mt][3] = __float_as_uint(a1p[4]);
        }
        int ng = noff + (lane>>2);
        #pragma unroll
        for (int nt=0;nt<4;nt++){
            const float* bp = &sm->Bs[buf][ng+nt*8][kb];
            bfr[nt][0] = __float_as_uint(bp[0]);
            bfr[nt][1] = __float_as_uint(bp[4]);
        }
        #pragma unroll
        for (int mt=0;mt<2;mt++)
            #pragma unroll
            for (int nt=0;nt<4;nt++)
                mma8(acc[mt*4+nt], afr[mt], bfr[nt]);
    }
}

__device__ __forceinline__ void gemm_tc(SmemBig* sm,
    const float* __restrict__ Ag, int lda,
    const float* __restrict__ Bg, int ldb,
    int nchunks, int row0, int v0, int tid, float (&acc)[8][4])
{
    int lane = tid&31, wid = tid>>5;
    int moff = (wid>>1)*32, noff = (wid&1)*32;
    float4 rA[4]; float4 rB[2];
    ldA(Ag,lda,row0,0,tid,rA); ldB(Bg,ldb,v0,0,tid,rB);
    stAB(sm,0,tid,rA,rB);
    __syncthreads();
    for (int kt=0; kt<nchunks; kt++){
        int cur = kt&1;
        bool more = (kt+1 < nchunks);
        if (more){ ldA(Ag,lda,row0,kt+1,tid,rA); ldB(Bg,ldb,v0,kt+1,tid,rB); }
        comp(sm,cur,lane,moff,noff,acc);
        if (more) stAB(sm,cur^1,tid,rA,rB);
        __syncthreads();
    }
}

extern __shared__ char dynsm[];
__global__ __launch_bounds__(256,1) void k_big(
    const float* __restrict__ w_prior, const float* __restrict__ b_prior,
    const float* __restrict__ w_gen,   const float* __restrict__ b_gen,
    const int*   __restrict__ x)
{
    SmemBig* sm = (SmemBig*)dynsm;
    __shared__ float sh_sum[128][3];
    __shared__ float sh_shift[128];
    __shared__ int   sh_xv[128];

    int vt = blockIdx.x, rt = blockIdx.y;
    int row0 = rt*BM, v0 = vt*BN;
    int tid = threadIdx.x;

    if (tid < 128){
        sh_shift[tid] = g_cst[0] - 0.5f*g_sumz2[row0+tid];
        sh_xv[tid]    = x[row0+tid];
        sh_sum[tid][0]=0.f; sh_sum[tid][1]=0.f; sh_sum[tid][2]=0.f;
    }

    float accP[8][4] = {};
    float accM[8][4] = {};
    float accG[8][4] = {};

    gemm_tc(sm, g_h,  Hn,   w_prior, Hn,   Hn/32,   row0, v0, tid, accP);
    gemm_tc(sm, g_ZZ, TWOK, g_W2,    TWOK, TWOK/32, row0, v0, tid, accM);
    gemm_tc(sm, g_z,  Kn,   w_gen,   Kn,   Kn/32,   row0, v0, tid, accG);

    __syncthreads();

    int lane = tid&31, wid = tid>>5;
    int moff = (wid>>1)*32, noff = (wid&1)*32;
    float rs[4][3] = {};
    #pragma unroll
    for (int nt=0; nt<4; nt++){
        #pragma unroll
        for (int c=0;c<2;c++){
            int n = noff + nt*8 + (lane&3)*2 + c;
            int v = v0 + n;
            bool ok = v < Vn;
            int vc = ok ? v : (Vn-1);
            float bp = __ldg(&b_prior[vc]);
            float bg = __ldg(&b_gen[vc]);
            float cv = g_cst[vc];
            #pragma unroll
            for (int mt=0;mt<2;mt++){
                #pragma unroll
                for (int hf=0; hf<2; hf++){
                    int rloc = moff + mt*16 + (lane>>2) + hf*8;
                    int ai = hf*2 + c;
                    float s1 = accP[mt*4+nt][ai] + bp;
                    float s3 = accG[mt*4+nt][ai] + bg;
                    float s2 = s1 + cv + accM[mt*4+nt][ai] - sh_shift[rloc];
                    if (ok){
                        rs[mt*2+hf][0] += expf(s1);
                        rs[mt*2+hf][1] += expf(s2);
                        rs[mt*2+hf][2] += expf(s3);
                        if (v == sh_xv[rloc]) g_tgt[row0 + rloc] = s3;
                    }
                }
            }
        }
    }
    #pragma unroll
    for (int lr=0; lr<4; lr++){
        float v0s = rs[lr][0], v1s = rs[lr][1], v2s = rs[lr][2];
        v0s += __shfl_xor_sync(0xffffffffu, v0s, 1);
        v0s += __shfl_xor_sync(0xffffffffu, v0s, 2);
        v1s += __shfl_xor_sync(0xffffffffu, v1s, 1);
        v1s += __shfl_xor_sync(0xffffffffu, v1s, 2);
        v2s += __shfl_xor_sync(0xffffffffu, v2s, 1);
        v2s += __shfl_xor_sync(0xffffffffu, v2s, 2);
        if ((lane&3)==0){
            int mt = lr>>1, hf = lr&1;
            int rloc = moff + mt*16 + (lane>>2) + hf*8;
            atomicAdd(&sh_sum[rloc][0], v0s);
            atomicAdd(&sh_sum[rloc][1], v1s);
            atomicAdd(&sh_sum[rloc][2], v2s);
        }
    }
    __syncthreads();
    if (tid < 128){
        g_part[(0*NVT + vt)*BT + row0 + tid] = sh_sum[tid][0];
        g_part[(1*NVT + vt)*BT + row0 + tid] = sh_sum[tid][1];
        g_part[(2*NVT + vt)*BT + row0 + tid] = sh_sum[tid][2];
    }
}

// ---------------- per-row LSE finish ----------------
__global__ void k_lse(const int* __restrict__ x_sl)
{
    int row = blockIdx.x*256 + threadIdx.x;
    if (row >= BT) return;
    float S1=0.f, S2=0.f, S3=0.f;
    for (int vt = 0; vt < NVT; vt++){
        S1 += g_part[(0*NVT+vt)*BT + row];
        S2 += g_part[(1*NVT+vt)*BT + row];
        S3 += g_part[(2*NVT+vt)*BT + row];
    }
    int b = row / Tn, t = row % Tn;
    float shift = g_cst[0] - 0.5f*g_sumz2[row];
    float lse_p = logf(S1);
    float lse_m = shift + logf(S2);
    float lse_g = logf(S3);
    float mask = (t < x_sl[b]) ? 1.f : 0.f;
    g_contrib[row] = mask * (g_tgt[row] - lse_g - g_qzlp[row] + (lse_m - lse_p));
}

// ---------------- final scalar ----------------
__global__ void k_final(const int* __restrict__ x_sl, float* __restrict__ out)
{
    __shared__ float red[256];
    int tid = threadIdx.x;
    float s = 0.f;
    for (int i = tid; i < BT; i += 256) s += g_contrib[i];
    red[tid] = s; __syncthreads();
    for (int st = 128; st > 0; st >>= 1){
        if (tid < st) red[tid] += red[tid+st];
        __syncthreads();
    }
    if (tid == 0){
        int tot = 0;
        for (int b = 0; b < Bn; b++) tot += x_sl[b];
        out[0] = -red[0] / (float)tot;
    }
}

// ---------------- launch ----------------
extern "C" void kernel_launch(void* const* d_in, const int* in_sizes, int n_in,
                              void* d_out, int out_size)
{
    const int*   x       = (const int*)  d_in[0];
    const int*   x_sl    = (const int*)  d_in[1];
    const float* eps     = (const float*)d_in[2];
    const float* emb     = (const float*)d_in[3];
    const float* w_ih    = (const float*)d_in[4];
    const float* w_hh    = (const float*)d_in[5];
    const float* b_ih    = (const float*)d_in[6];
    const float* b_hh    = (const float*)d_in[7];
    const float* w_prior = (const float*)d_in[8];
    const float* b_prior = (const float*)d_in[9];
    const float* w_gen   = (const float*)d_in[10];
    const float* b_gen   = (const float*)d_in[11];
    float* out = (float*)d_out;

    int smem_big  = (int)sizeof(SmemBig);                         // ~55 KB
    int smem_lstm = (16*512 + 32*516 + 2*16*33)*(int)sizeof(float); // ~103 KB
    cudaFuncSetAttribute(k_big,      cudaFuncAttributeMaxDynamicSharedMemorySize, smem_big);
    cudaFuncSetAttribute(k_lstm_all, cudaFuncAttributeMaxDynamicSharedMemorySize, smem_lstm);

    k_init<<<(Bn*Hn + 255)/256, 256>>>();                          // launch 1
    k_prep_z<<<BT, 256>>>(x, x_sl, eps, emb);                      // launch 2
    k_prep_v<<<Vn, 256>>>(emb);                                    // launch 3
    k_xproj<<<dim3(G4n/64, BT/64), 256>>>(w_ih, b_ih, b_hh);       // launch 4
    k_lstm_all<<<128, 256, smem_lstm>>>(w_hh);                     // launch 5
    k_big<<<dim3(NVT, BT/BM), 256, smem_big>>>(w_prior, b_prior, w_gen, b_gen, x); // launch 6 (ncu -s 5)
    k_lse<<<BT/256, 256>>>(x_sl);
    k_final<<<1, 256>>>(x_sl, out);
}

// round 8
// speedup vs baseline: 6.5005x; 1.2485x over previous
#include <cuda_runtime.h>
#include <cuda_bf16.h>
#include <cstdint>

#define Bn 32
#define Tn 128
#define Kn 256
#define Hn 512
#define Vn 10000
#define BT (Bn*Tn)
#define G4n (4*Hn)
#define TWOK (2*Kn)
#define NVT 157              // ceil(Vn/64)

#define HALF_LOG_2PI 0.918938533204672741780329736406f

typedef unsigned long long ull;

// ---------------- static scratch ----------------
__device__ __align__(16) __nv_bfloat16 g_zb[BT*Kn];      // 2 MB
__device__ __align__(16) __nv_bfloat16 g_ZZb[BT*TWOK];   // 4 MB [z | z^2]
__device__ __align__(16) __nv_bfloat16 g_hb[BT*Hn];      // 4 MB
__device__ __align__(16) __nv_bfloat16 g_W2b[Vn*TWOK];   // 10 MB [2*inv2var*mu | -inv2var]
__device__ __align__(16) __nv_bfloat16 g_wpb[Vn*Hn];     // 10 MB
__device__ __align__(16) __nv_bfloat16 g_wgb[Vn*Kn];     // 5 MB
__device__ __align__(16) __nv_bfloat16 g_wihb[G4n*Kn];   // 1 MB
__device__ __align__(16) float g_xproj[BT*G4n];          // 32 MB
__device__ float g_cst[Vn];
__device__ float g_qzlp[BT];
__device__ float g_sumz2[BT];
__device__ float g_tgt[BT];
__device__ float g_part[3*NVT*BT];
__device__ float g_contrib[BT];
__device__ __align__(16) float g_hbuf[2][Bn*Hn];
__device__ unsigned g_ctr;

__device__ __forceinline__ float softplus_b(float x){
    return (x > 20.f) ? x : log2f(1.f + exp2f(x));
}
__device__ __forceinline__ float sigmf(float x){ return 1.f/(1.f+expf(-x)); }

// packed f32x2 FMA (PTX-only path; ptxas won't auto-fuse)
__device__ __forceinline__ ull ffma2(ull a, ull b, ull c){
    ull d;
    asm("fma.rn.f32x2 %0, %1, %2, %3;" : "=l"(d) : "l"(a), "l"(b), "l"(c));
    return d;
}
__device__ __forceinline__ float2 unpk(ull v){
    float lo, hi;
    asm("mov.b64 {%0, %1}, %2;" : "=f"(lo), "=f"(hi) : "l"(v));
    return make_float2(lo, hi);
}

// ---------------- init ----------------
__global__ void k_init(){
    int i = blockIdx.x*blockDim.x + threadIdx.x;
    if (i < Bn*Hn){ g_hbuf[0][i] = 0.f; }
    if (i == 0) g_ctr = 0u;
}

// ---------------- fp32 -> bf16 convert ----------------
__global__ void k_cvt(const float* __restrict__ src, __nv_bfloat16* __restrict__ dst, int n){
    int i = blockIdx.x*blockDim.x + threadIdx.x;
    int stride = gridDim.x*blockDim.x;
    for (; i < n; i += stride) dst[i] = __float2bfloat16(src[i]);
}

// ---------------- per-(b,t): z(bf16), z^2(bf16), q_z_lp, sum z^2 ----------------
__global__ void k_prep_z(const int* __restrict__ x, const int* __restrict__ x_sl,
                         const float* __restrict__ eps, const float* __restrict__ emb)
{
    int row = blockIdx.x;
    int k   = threadIdx.x;
    int b = row / Tn, t = row % Tn;
    int xv = x[row];
    float mask = (t < x_sl[b]) ? 1.f : 0.f;
    float mu = emb[xv*TWOK + k];
    float sq = softplus_b(emb[xv*TWOK + Kn + k]);
    float e  = eps[row*Kn + k];
    float zv = (mu + sq*e) * mask;
    g_zb[row*Kn + k]         = __float2bfloat16(zv);
    g_ZZb[row*TWOK + k]      = __float2bfloat16(zv);
    g_ZZb[row*TWOK + Kn + k] = __float2bfloat16(zv*zv);
    float q = -HALF_LOG_2PI - logf(sq) - 0.5f*e*e;
    __shared__ float r1[256], r2[256];
    r1[k] = q; r2[k] = zv*zv;
    __syncthreads();
    for (int s = 128; s > 0; s >>= 1){
        if (k < s){ r1[k] += r1[k+s]; r2[k] += r2[k+s]; }
        __syncthreads();
    }
    if (k == 0){ g_qzlp[row] = r1[0]; g_sumz2[row] = r2[0]; }
}

// ---------------- per-v: W2(bf16), const ----------------
__global__ void k_prep_v(const float* __restrict__ emb)
{
    int v = blockIdx.x;
    int k = threadIdx.x;
    float mu = emb[v*TWOK + k];
    float sp = softplus_b(emb[v*TWOK + Kn + k]);
    float inv2 = 0.5f/(sp*sp);
    g_W2b[v*TWOK + k]      = __float2bfloat16(2.f*inv2*mu);
    g_W2b[v*TWOK + Kn + k] = __float2bfloat16(-inv2);
    float c = -HALF_LOG_2PI - logf(sp) - mu*mu*inv2;
    __shared__ float red[256];
    red[k] = c;
    __syncthreads();
    for (int s = 128; s > 0; s >>= 1){
        if (k < s) red[k] += red[k+s];
        __syncthreads();
    }
    if (k == 0) g_cst[v] = red[0];
}

// ================= bf16 GEMM building blocks (m16n8k16) =================
// Tiles: BM=128, BN=64, BK=32. Smem rows padded to 40 bf16 (conflict-free frags).
struct SmemTC {
    __nv_bfloat16 As[2][128][40];
    __nv_bfloat16 Bs[2][64][40];
};

__device__ __forceinline__ void mma16(float* d, const uint32_t* a, const uint32_t* b){
    asm volatile("mma.sync.aligned.m16n8k16.row.col.f32.bf16.bf16.f32 "
        "{%0,%1,%2,%3}, {%4,%5,%6,%7}, {%8,%9}, {%0,%1,%2,%3};"
        : "+f"(d[0]),"+f"(d[1]),"+f"(d[2]),"+f"(d[3])
        : "r"(a[0]),"r"(a[1]),"r"(a[2]),"r"(a[3]), "r"(b[0]),"r"(b[1]));
}

__device__ __forceinline__ void ldA16(const __nv_bfloat16* __restrict__ Ag, int lda,
                                      int row0, int kt, int tid, uint4 (&rA)[2]){
    #pragma unroll
    for (int i=0;i<2;i++){
        int idx = tid + i*256;
        int row = idx>>2, q = idx&3;
        rA[i] = *(const uint4*)(Ag + (size_t)(row0+row)*lda + kt*32 + q*8);
    }
}
// A loader with z_shift semantics (row t==0 reads zeros, else row-1 of zb)
__device__ __forceinline__ void ldA16s(const __nv_bfloat16* __restrict__ zb,
                                       int row0, int kt, int tid, uint4 (&rA)[2]){
    #pragma unroll
    for (int i=0;i<2;i++){
        int idx = tid + i*256;
        int row = idx>>2, q = idx&3;
        int grow = row0 + row;
        rA[i] = make_uint4(0u,0u,0u,0u);
        if ((grow & (Tn-1)) != 0)
            rA[i] = *(const uint4*)(zb + (size_t)(grow-1)*Kn + kt*32 + q*8);
    }
}
__device__ __forceinline__ void ldB16(const __nv_bfloat16* __restrict__ Bg, int ldb,
                                      int v0, int nmax, int kt, int tid, uint4& rB){
    int row = tid>>2, q = tid&3;
    rB = (v0+row < nmax) ? *(const uint4*)(Bg + (size_t)(v0+row)*ldb + kt*32 + q*8)
                         : make_uint4(0u,0u,0u,0u);
}
__device__ __forceinline__ void stAB16(SmemTC* sm, int buf, int tid,
                                       const uint4 (&rA)[2], const uint4& rB){
    #pragma unroll
    for (int i=0;i<2;i++){
        int idx = tid + i*256; int row = idx>>2, q = idx&3;
        *(uint4*)&sm->As[buf][row][q*8] = rA[i];
    }
    { int row = tid>>2, q = tid&3;
      *(uint4*)&sm->Bs[buf][row][q*8] = rB; }
}

__device__ __forceinline__ void comp16(SmemTC* sm, int buf, int lane, int moff, int noff,
                                       float (&acc)[8][4]){
    int gr = lane>>2, tg = lane&3;
    #pragma unroll
    for (int kk=0; kk<2; kk++){
        int c0 = kk*16 + tg*2;
        uint32_t afr[2][4], bfr[4][2];
        #pragma unroll
        for (int mt=0; mt<2; mt++){
            int rbase = moff + mt*16 + gr;
            afr[mt][0] = *(const uint32_t*)&sm->As[buf][rbase  ][c0];
            afr[mt][1] = *(const uint32_t*)&sm->As[buf][rbase+8][c0];
            afr[mt][2] = *(const uint32_t*)&sm->As[buf][rbase  ][c0+8];
            afr[mt][3] = *(const uint32_t*)&sm->As[buf][rbase+8][c0+8];
        }
        #pragma unroll
        for (int nt=0; nt<4; nt++){
            int nrow = noff + nt*8 + gr;
            bfr[nt][0] = *(const uint32_t*)&sm->Bs[buf][nrow][c0];
            bfr[nt][1] = *(const uint32_t*)&sm->Bs[buf][nrow][c0+8];
        }
        #pragma unroll
        for (int mt=0;mt<2;mt++)
            #pragma unroll
            for (int nt=0;nt<4;nt++)
                mma16(acc[mt*4+nt], afr[mt], bfr[nt]);
    }
}

__device__ __forceinline__ void gemm16(SmemTC* sm,
    const __nv_bfloat16* __restrict__ Ag, int lda,
    const __nv_bfloat16* __restrict__ Bg, int ldb, int nmax,
    int nchunks, int row0, int v0, int tid, float (&acc)[8][4])
{
    int lane = tid&31, wid = tid>>5;
    int moff = (wid>>1)*32, noff = (wid&1)*32;
    uint4 rA[2]; uint4 rB;
    ldA16(Ag,lda,row0,0,tid,rA); ldB16(Bg,ldb,v0,nmax,0,tid,rB);
    stAB16(sm,0,tid,rA,rB);
    __syncthreads();
    for (int kt=0; kt<nchunks; kt++){
        int cur = kt&1;
        bool more = (kt+1 < nchunks);
        if (more){ ldA16(Ag,lda,row0,kt+1,tid,rA); ldB16(Bg,ldb,v0,nmax,kt+1,tid,rB); }
        comp16(sm,cur,lane,moff,noff,acc);
        if (more) stAB16(sm,cur^1,tid,rA,rB);
        __syncthreads();
    }
}

// ---------------- x_proj GEMM (bf16 tensor): z_shift @ w_ih^T + b_ih + b_hh ----------------
__global__ __launch_bounds__(256) void k_xproj16(const float* __restrict__ b_ih,
                                                 const float* __restrict__ b_hh)
{
    __shared__ SmemTC sm;
    int bcol = blockIdx.x * 64;       // N-tile of G4n
    int row0 = blockIdx.y * 128;      // row-tile of BT
    int tid = threadIdx.x;
    int lane = tid&31, wid = tid>>5;
    int moff = (wid>>1)*32, noff = (wid&1)*32;
    int gr = lane>>2, tg = lane&3;

    float acc[8][4] = {};
    // manual pipeline with shifted A loader
    {
        uint4 rA[2]; uint4 rB;
        ldA16s(g_zb,row0,0,tid,rA); ldB16(g_wihb,Kn,bcol,G4n,0,tid,rB);
        stAB16(&sm,0,tid,rA,rB);
        __syncthreads();
        const int nchunks = Kn/32;
        for (int kt=0; kt<nchunks; kt++){
            int cur = kt&1;
            bool more = (kt+1 < nchunks);
            if (more){ ldA16s(g_zb,row0,kt+1,tid,rA); ldB16(g_wihb,Kn,bcol,G4n,kt+1,tid,rB); }
            comp16(&sm,cur,lane,moff,noff,acc);
            if (more) stAB16(&sm,cur^1,tid,rA,rB);
            __syncthreads();
        }
    }
    #pragma unroll
    for (int nt=0; nt<4; nt++){
        #pragma unroll
        for (int c=0;c<2;c++){
            int col = bcol + noff + nt*8 + tg*2 + c;
            float bias = b_ih[col] + b_hh[col];
            #pragma unroll
            for (int mt=0;mt<2;mt++)
                #pragma unroll
                for (int hf=0; hf<2; hf++){
                    int row = row0 + moff + mt*16 + gr + hf*8;
                    g_xproj[(size_t)row*G4n + col] = acc[mt*4+nt][hf*2+c] + bias;
                }
        }
    }
}

// ================= persistent LSTM (single launch, f32x2 dot) =================
__global__ __launch_bounds__(256) void k_lstm_all(const float* __restrict__ w_hh)
{
    extern __shared__ float sm[];
    float* w_s  = sm;                    // 16*512 floats (32 KB)
    float* h_s  = sm + 16*512;           // 32*516 floats (66 KB)
    float* pbuf = h_s + 32*516;          // 2*16*33 floats
    int tid = threadIdx.x, lane = tid & 31, w = tid >> 5;
    int js = blockIdx.x;                 // 0..127

    for (int i = tid; i < 16*128; i += 256){
        int r = i >> 7, q = i & 127;
        int grow = (r>>2)*Hn + js*4 + (r&3);
        *(float4*)&w_s[r*512 + q*4] = *(const float4*)&w_hh[(size_t)grow*Hn + q*4];
    }

    int jh = w >> 2;
    int rq = w & 3;
    const ulonglong2* w0p = (const ulonglong2*)(w_s + (rq*4+0)*512 + jh*256);
    const ulonglong2* w1p = (const ulonglong2*)(w_s + (rq*4+1)*512 + jh*256);
    const ulonglong2* w2p = (const ulonglong2*)(w_s + (rq*4+2)*512 + jh*256);
    const ulonglong2* w3p = (const ulonglong2*)(w_s + (rq*4+3)*512 + jh*256);

    float c_reg = 0.f;
    volatile unsigned* vc = &g_ctr;

    for (int t = 0; t < Tn; t++){
        int par = t & 1;
        if (tid == 0 && t > 0){
            unsigned target = (unsigned)t * 128u;
            while (*vc < target) {}
        }
        __syncthreads();

        for (int i = tid; i < 32*128; i += 256){
            int b = i >> 7, q = i & 127;
            float4 hv = __ldcg((const float4*)&g_hbuf[par][b*512 + q*4]);
            *(float4*)&h_s[b*516 + q*4] = hv;
        }
        __syncthreads();

        {
            const ulonglong2* hbp = (const ulonglong2*)(h_s + lane*516 + jh*256);
            ull a00=0,a01=0, a10=0,a11=0, a20=0,a21=0, a30=0,a31=0;
            #pragma unroll 8
            for (int q = 0; q < 64; q++){
                ulonglong2 hv = hbp[q];
                ulonglong2 w0 = w0p[q]; a00=ffma2(w0.x,hv.x,a00); a01=ffma2(w0.y,hv.y,a01);
                ulonglong2 w1 = w1p[q]; a10=ffma2(w1.x,hv.x,a10); a11=ffma2(w1.y,hv.y,a11);
                ulonglong2 w2 = w2p[q]; a20=ffma2(w2.x,hv.x,a20); a21=ffma2(w2.y,hv.y,a21);
                ulonglong2 w3 = w3p[q]; a30=ffma2(w3.x,hv.x,a30); a31=ffma2(w3.y,hv.y,a31);
            }
            float2 u, v2;
            u=unpk(a00); v2=unpk(a01); pbuf[(jh*16 + rq*4+0)*33 + lane] = u.x+u.y+v2.x+v2.y;
            u=unpk(a10); v2=unpk(a11); pbuf[(jh*16 + rq*4+1)*33 + lane] = u.x+u.y+v2.x+v2.y;
            u=unpk(a20); v2=unpk(a21); pbuf[(jh*16 + rq*4+2)*33 + lane] = u.x+u.y+v2.x+v2.y;
            u=unpk(a30); v2=unpk(a31); pbuf[(jh*16 + rq*4+3)*33 + lane] = u.x+u.y+v2.x+v2.y;
        }
        __syncthreads();

        if (tid < 128){
            int b = tid & 31, jj = tid >> 5;
            int j = js*4 + jj;
            float g4[4];
            #pragma unroll
            for (int gate = 0; gate < 4; gate++){
                int r = gate*4 + jj;
                g4[gate] = pbuf[r*33 + b] + pbuf[(16 + r)*33 + b]
                         + g_xproj[(size_t)(b*Tn + t)*G4n + gate*Hn + j];
            }
            float c = c_reg;
            c = sigmf(g4[1])*c + sigmf(g4[0])*tanhf(g4[2]);
            float hv = sigmf(g4[3])*tanhf(c);
            c_reg = c;
            g_hbuf[par^1][b*512 + j] = hv;
            g_hb[(size_t)(b*Tn + t)*Hn + j] = __float2bfloat16(hv);
        }
        __threadfence();
        __syncthreads();
        if (tid == 0) atomicAdd(&g_ctr, 1u);
    }
}

// ================= k_big: bf16 tensor triple GEMM + fused LSE =================
__global__ __launch_bounds__(256) void k_big(
    const float* __restrict__ b_prior, const float* __restrict__ b_gen,
    const int*   __restrict__ x)
{
    __shared__ SmemTC sm;
    __shared__ float sh_sum[128][3];
    __shared__ float sh_shift[128];
    __shared__ int   sh_xv[128];

    int vt = blockIdx.x, rt = blockIdx.y;
    int row0 = rt*128, v0 = vt*64;
    int tid = threadIdx.x;

    if (tid < 128){
        sh_shift[tid] = g_cst[0] - 0.5f*g_sumz2[row0+tid];
        sh_xv[tid]    = x[row0+tid];
        sh_sum[tid][0]=0.f; sh_sum[tid][1]=0.f; sh_sum[tid][2]=0.f;
    }

    float accP[8][4] = {};
    float accM[8][4] = {};
    float accG[8][4] = {};

    gemm16(&sm, g_hb,  Hn,   g_wpb,  Hn,   Vn, Hn/32,   row0, v0, tid, accP);
    gemm16(&sm, g_ZZb, TWOK, g_W2b,  TWOK, Vn, TWOK/32, row0, v0, tid, accM);
    gemm16(&sm, g_zb,  Kn,   g_wgb,  Kn,   Vn, Kn/32,   row0, v0, tid, accG);

    __syncthreads();

    int lane = tid&31, wid = tid>>5;
    int moff = (wid>>1)*32, noff = (wid&1)*32;
    float rs[4][3] = {};
    #pragma unroll
    for (int nt=0; nt<4; nt++){
        #pragma unroll
        for (int c=0;c<2;c++){
            int n = noff + nt*8 + (lane&3)*2 + c;
            int v = v0 + n;
            bool ok = v < Vn;
            int vc = ok ? v : (Vn-1);
            float bp = __ldg(&b_prior[vc]);
            float bg = __ldg(&b_gen[vc]);
            float cv = g_cst[vc];
            #pragma unroll
            for (int mt=0;mt<2;mt++){
                #pragma unroll
                for (int hf=0; hf<2; hf++){
                    int rloc = moff + mt*16 + (lane>>2) + hf*8;
                    int ai = hf*2 + c;
                    float s1 = accP[mt*4+nt][ai] + bp;
                    float s3 = accG[mt*4+nt][ai] + bg;
                    float s2 = s1 + cv + accM[mt*4+nt][ai] - sh_shift[rloc];
                    if (ok){
                        rs[mt*2+hf][0] += expf(s1);
                        rs[mt*2+hf][1] += expf(s2);
                        rs[mt*2+hf][2] += expf(s3);
                        if (v == sh_xv[rloc]) g_tgt[row0 + rloc] = s3;
                    }
                }
            }
        }
    }
    #pragma unroll
    for (int lr=0; lr<4; lr++){
        float v0s = rs[lr][0], v1s = rs[lr][1], v2s = rs[lr][2];
        v0s += __shfl_xor_sync(0xffffffffu, v0s, 1);
        v0s += __shfl_xor_sync(0xffffffffu, v0s, 2);
        v1s += __shfl_xor_sync(0xffffffffu, v1s, 1);
        v1s += __shfl_xor_sync(0xffffffffu, v1s, 2);
        v2s += __shfl_xor_sync(0xffffffffu, v2s, 1);
        v2s += __shfl_xor_sync(0xffffffffu, v2s, 2);
        if ((lane&3)==0){
            int mt = lr>>1, hf = lr&1;
            int rloc = moff + mt*16 + (lane>>2) + hf*8;
            atomicAdd(&sh_sum[rloc][0], v0s);
            atomicAdd(&sh_sum[rloc][1], v1s);
            atomicAdd(&sh_sum[rloc][2], v2s);
        }
    }
    __syncthreads();
    if (tid < 128){
        g_part[(0*NVT + vt)*BT + row0 + tid] = sh_sum[tid][0];
        g_part[(1*NVT + vt)*BT + row0 + tid] = sh_sum[tid][1];
        g_part[(2*NVT + vt)*BT + row0 + tid] = sh_sum[tid][2];
    }
}

// ---------------- per-row LSE finish ----------------
__global__ void k_lse(const int* __restrict__ x_sl)
{
    int row = blockIdx.x*256 + threadIdx.x;
    if (row >= BT) return;
    float S1=0.f, S2=0.f, S3=0.f;
    for (int vt = 0; vt < NVT; vt++){
        S1 += g_part[(0*NVT+vt)*BT + row];
        S2 += g_part[(1*NVT+vt)*BT + row];
        S3 += g_part[(2*NVT+vt)*BT + row];
    }
    int b = row / Tn, t = row % Tn;
    float shift = g_cst[0] - 0.5f*g_sumz2[row];
    float lse_p = logf(S1);
    float lse_m = shift + logf(S2);
    float lse_g = logf(S3);
    float mask = (t < x_sl[b]) ? 1.f : 0.f;
    g_contrib[row] = mask * (g_tgt[row] - lse_g - g_qzlp[row] + (lse_m - lse_p));
}

// ---------------- final scalar ----------------
__global__ void k_final(const int* __restrict__ x_sl, float* __restrict__ out)
{
    __shared__ float red[256];
    int tid = threadIdx.x;
    float s = 0.f;
    for (int i = tid; i < BT; i += 256) s += g_contrib[i];
    red[tid] = s; __syncthreads();
    for (int st = 128; st > 0; st >>= 1){
        if (tid < st) red[tid] += red[tid+st];
        __syncthreads();
    }
    if (tid == 0){
        int tot = 0;
        for (int b = 0; b < Bn; b++) tot += x_sl[b];
        out[0] = -red[0] / (float)tot;
    }
}

// ---------------- launch ----------------
extern "C" void kernel_launch(void* const* d_in, const int* in_sizes, int n_in,
                              void* d_out, int out_size)
{
    const int*   x       = (const int*)  d_in[0];
    const int*   x_sl    = (const int*)  d_in[1];
    const float* eps     = (const float*)d_in[2];
    const float* emb     = (const float*)d_in[3];
    const float* w_ih    = (const float*)d_in[4];
    const float* w_hh    = (const float*)d_in[5];
    const float* b_ih    = (const float*)d_in[6];
    const float* b_hh    = (const float*)d_in[7];
    const float* w_prior = (const float*)d_in[8];
    const float* b_prior = (const float*)d_in[9];
    const float* w_gen   = (const float*)d_in[10];
    const float* b_gen   = (const float*)d_in[11];
    float* out = (float*)d_out;

    int smem_lstm = (16*512 + 32*516 + 2*16*33)*(int)sizeof(float); // ~103 KB
    cudaFuncSetAttribute(k_lstm_all, cudaFuncAttributeMaxDynamicSharedMemorySize, smem_lstm);

    __nv_bfloat16 *d_wihb, *d_wpb, *d_wgb;
    cudaGetSymbolAddress((void**)&d_wihb, g_wihb);
    cudaGetSymbolAddress((void**)&d_wpb,  g_wpb);
    cudaGetSymbolAddress((void**)&d_wgb,  g_wgb);

    k_init<<<(Bn*Hn + 255)/256, 256>>>();                          // 1
    k_prep_z<<<BT, 256>>>(x, x_sl, eps, emb);                      // 2
    k_prep_v<<<Vn, 256>>>(emb);                                    // 3
    k_cvt<<<512, 256>>>(w_ih, d_wihb, G4n*Kn);                     // 4
    k_xproj16<<<dim3(G4n/64, BT/128), 256>>>(b_ih, b_hh);          // 5
    k_lstm_all<<<128, 256, smem_lstm>>>(w_hh);                     // 6 (ncu -s 5)
    k_cvt<<<2048, 256>>>(w_prior, d_wpb, Vn*Hn);                   // 7
    k_cvt<<<1024, 256>>>(w_gen,   d_wgb, Vn*Kn);                   // 8
    k_big<<<dim3(NVT, BT/128), 256>>>(b_prior, b_gen, x);          // 9
    k_lse<<<BT/256, 256>>>(x_sl);
    k_final<<<1, 256>>>(x_sl, out);
}

// round 10
// speedup vs baseline: 8.5348x; 1.3130x over previous
#include <cuda_runtime.h>
#include <cuda_bf16.h>
#include <cstdint>

#define Bn 32
#define Tn 128
#define Kn 256
#define Hn 512
#define Vn 10000
#define BT (Bn*Tn)
#define G4n (4*Hn)
#define TWOK (2*Kn)
#define NVT 157              // ceil(Vn/64)

#define HALF_LOG_2PI 0.918938533204672741780329736406f

typedef unsigned long long ull;

// ---------------- static scratch ----------------
__device__ __align__(16) __nv_bfloat16 g_zb[BT*Kn];      // 2 MB
__device__ __align__(16) __nv_bfloat16 g_ZZb[BT*TWOK];   // 4 MB [z | z^2]
__device__ __align__(16) __nv_bfloat16 g_hb[BT*Hn];      // 4 MB
__device__ __align__(16) __nv_bfloat16 g_W2b[Vn*TWOK];   // 10 MB
__device__ __align__(16) __nv_bfloat16 g_wpb[Vn*Hn];     // 10 MB
__device__ __align__(16) __nv_bfloat16 g_wgb[Vn*Kn];     // 5 MB
__device__ __align__(16) __nv_bfloat16 g_wihb[G4n*Kn];   // 1 MB
__device__ __align__(16) float g_xproj[BT*G4n];          // 32 MB
__device__ float g_cst[Vn];
__device__ float g_qzlp[BT];
__device__ float g_sumz2[BT];
__device__ float g_tgt[BT];
__device__ float g_part[3*NVT*BT];
__device__ float g_contrib[BT];
__device__ __align__(16) float g_hbuf[2][Bn*Hn];
__device__ unsigned g_ctr;

__device__ __forceinline__ float softplus_b(float x){
    return (x > 20.f) ? x : log2f(1.f + exp2f(x));
}
__device__ __forceinline__ float sigmf(float x){ return 1.f/(1.f+expf(-x)); }

__device__ __forceinline__ ull ffma2(ull a, ull b, ull c){
    ull d;
    asm("fma.rn.f32x2 %0, %1, %2, %3;" : "=l"(d) : "l"(a), "l"(b), "l"(c));
    return d;
}
__device__ __forceinline__ float2 unpk(ull v){
    float lo, hi;
    asm("mov.b64 {%0, %1}, %2;" : "=f"(lo), "=f"(hi) : "l"(v));
    return make_float2(lo, hi);
}

// ---------------- cp.async helpers ----------------
__device__ __forceinline__ uint32_t smem_u32(const void* p){
    uint32_t a;
    asm("{ .reg .u64 t; cvta.to.shared.u64 t, %1; cvt.u32.u64 %0, t; }" : "=r"(a) : "l"(p));
    return a;
}
__device__ __forceinline__ void cp16(uint32_t dst, const void* src){
    asm volatile("cp.async.cg.shared.global [%0], [%1], 16;" :: "r"(dst), "l"(src) : "memory");
}
#define CP_COMMIT() asm volatile("cp.async.commit_group;" ::: "memory")
template<int N> __device__ __forceinline__ void cp_wait(){
    asm volatile("cp.async.wait_group %0;" :: "n"(N) : "memory");
}
#define SWZ128(o) ((o) ^ (((o) >> 3) & 0x70))

// ---------------- fp32 -> bf16 convert ----------------
__global__ void k_cvt(const float* __restrict__ src, __nv_bfloat16* __restrict__ dst, int n){
    int i = blockIdx.x*blockDim.x + threadIdx.x;
    int stride = gridDim.x*blockDim.x;
    for (; i < n; i += stride) dst[i] = __float2bfloat16(src[i]);
}

// ---------------- per-(b,t): z, z^2, q_z_lp, sum z^2 (+init fold) ----------------
__global__ void k_prep_z(const int* __restrict__ x, const int* __restrict__ x_sl,
                         const float* __restrict__ eps, const float* __restrict__ emb)
{
    int row = blockIdx.x;
    int k   = threadIdx.x;
    int lin = row*256 + k;
    if (lin < Bn*Hn) g_hbuf[0][lin] = 0.f;
    if (lin == 0) g_ctr = 0u;
    int b = row / Tn, t = row % Tn;
    int xv = x[row];
    float mask = (t < x_sl[b]) ? 1.f : 0.f;
    float mu = emb[xv*TWOK + k];
    float sq = softplus_b(emb[xv*TWOK + Kn + k]);
    float e  = eps[row*Kn + k];
    float zv = (mu + sq*e) * mask;
    g_zb[row*Kn + k]         = __float2bfloat16(zv);
    g_ZZb[row*TWOK + k]      = __float2bfloat16(zv);
    g_ZZb[row*TWOK + Kn + k] = __float2bfloat16(zv*zv);
    float q = -HALF_LOG_2PI - logf(sq) - 0.5f*e*e;
    __shared__ float r1[256], r2[256];
    r1[k] = q; r2[k] = zv*zv;
    __syncthreads();
    for (int s = 128; s > 0; s >>= 1){
        if (k < s){ r1[k] += r1[k+s]; r2[k] += r2[k+s]; }
        __syncthreads();
    }
    if (k == 0){ g_qzlp[row] = r1[0]; g_sumz2[row] = r2[0]; }
}

// ---------------- per-v: W2(bf16), const ----------------
__global__ void k_prep_v(const float* __restrict__ emb)
{
    int v = blockIdx.x;
    int k = threadIdx.x;
    float mu = emb[v*TWOK + k];
    float sp = softplus_b(emb[v*TWOK + Kn + k]);
    float inv2 = 0.5f/(sp*sp);
    g_W2b[v*TWOK + k]      = __float2bfloat16(2.f*inv2*mu);
    g_W2b[v*TWOK + Kn + k] = __float2bfloat16(-inv2);
    float c = -HALF_LOG_2PI - logf(sp) - mu*mu*inv2;
    __shared__ float red[256];
    red[k] = c;
    __syncthreads();
    for (int s = 128; s > 0; s >>= 1){
        if (k < s) red[k] += red[k+s];
        __syncthreads();
    }
    if (k == 0) g_cst[v] = red[0];
}

// ================= legacy bf16 mma (m16n8k16) =================
__device__ __forceinline__ void mma16(float* d, const uint32_t* a, const uint32_t* b){
    asm volatile("mma.sync.aligned.m16n8k16.row.col.f32.bf16.bf16.f32 "
        "{%0,%1,%2,%3}, {%4,%5,%6,%7}, {%8,%9}, {%0,%1,%2,%3};"
        : "+f"(d[0]),"+f"(d[1]),"+f"(d[2]),"+f"(d[3])
        : "r"(a[0]),"r"(a[1]),"r"(a[2]),"r"(a[3]), "r"(b[0]),"r"(b[1]));
}

// ---------------- x_proj GEMM (legacy bf16 mma, padded-smem variant) ----------------
struct SmemTC {
    __nv_bfloat16 As[2][128][40];
    __nv_bfloat16 Bs[2][64][40];
};
__device__ __forceinline__ void ldA16s(const __nv_bfloat16* __restrict__ zb,
                                       int row0, int kt, int tid, uint4 (&rA)[2]){
    #pragma unroll
    for (int i=0;i<2;i++){
        int idx = tid + i*256;
        int row = idx>>2, q = idx&3;
        int grow = row0 + row;
        rA[i] = make_uint4(0u,0u,0u,0u);
        if ((grow & (Tn-1)) != 0)
            rA[i] = *(const uint4*)(zb + (size_t)(grow-1)*Kn + kt*32 + q*8);
    }
}
__device__ __forceinline__ void ldB16(const __nv_bfloat16* __restrict__ Bg, int ldb,
                                      int v0, int nmax, int kt, int tid, uint4& rB){
    int row = tid>>2, q = tid&3;
    int v = v0 + row; if (v >= nmax) v = nmax-1;
    rB = *(const uint4*)(Bg + (size_t)v*ldb + kt*32 + q*8);
}
__device__ __forceinline__ void stAB16(SmemTC* sm, int buf, int tid,
                                       const uint4 (&rA)[2], const uint4& rB){
    #pragma unroll
    for (int i=0;i<2;i++){
        int idx = tid + i*256; int row = idx>>2, q = idx&3;
        *(uint4*)&sm->As[buf][row][q*8] = rA[i];
    }
    { int row = tid>>2, q = tid&3;
      *(uint4*)&sm->Bs[buf][row][q*8] = rB; }
}
__device__ __forceinline__ void comp16(SmemTC* sm, int buf, int lane, int moff, int noff,
                                       float (&acc)[8][4]){
    int gr = lane>>2, tg = lane&3;
    #pragma unroll
    for (int kk=0; kk<2; kk++){
        int c0 = kk*16 + tg*2;
        uint32_t afr[2][4], bfr[4][2];
        #pragma unroll
        for (int mt=0; mt<2; mt++){
            int rbase = moff + mt*16 + gr;
            afr[mt][0] = *(const uint32_t*)&sm->As[buf][rbase  ][c0];
            afr[mt][1] = *(const uint32_t*)&sm->As[buf][rbase+8][c0];
            afr[mt][2] = *(const uint32_t*)&sm->As[buf][rbase  ][c0+8];
            afr[mt][3] = *(const uint32_t*)&sm->As[buf][rbase+8][c0+8];
        }
        #pragma unroll
        for (int nt=0; nt<4; nt++){
            int nrow = noff + nt*8 + gr;
            bfr[nt][0] = *(const uint32_t*)&sm->Bs[buf][nrow][c0];
            bfr[nt][1] = *(const uint32_t*)&sm->Bs[buf][nrow][c0+8];
        }
        #pragma unroll
        for (int mt=0;mt<2;mt++)
            #pragma unroll
            for (int nt=0;nt<4;nt++)
                mma16(acc[mt*4+nt], afr[mt], bfr[nt]);
    }
}

__global__ __launch_bounds__(256) void k_xproj16(const float* __restrict__ b_ih,
                                                 const float* __restrict__ b_hh)
{
    __shared__ SmemTC sm;
    int bcol = blockIdx.x * 64;
    int row0 = blockIdx.y * 128;
    int tid = threadIdx.x;
    int lane = tid&31, wid = tid>>5;
    int moff = (wid>>1)*32, noff = (wid&1)*32;
    int gr = lane>>2, tg = lane&3;

    float acc[8][4] = {};
    {
        uint4 rA[2]; uint4 rB;
        ldA16s(g_zb,row0,0,tid,rA); ldB16(g_wihb,Kn,bcol,G4n,0,tid,rB);
        stAB16(&sm,0,tid,rA,rB);
        __syncthreads();
        const int nchunks = Kn/32;
        for (int kt=0; kt<nchunks; kt++){
            int cur = kt&1;
            bool more = (kt+1 < nchunks);
            if (more){ ldA16s(g_zb,row0,kt+1,tid,rA); ldB16(g_wihb,Kn,bcol,G4n,kt+1,tid,rB); }
            comp16(&sm,cur,lane,moff,noff,acc);
            if (more) stAB16(&sm,cur^1,tid,rA,rB);
            __syncthreads();
        }
    }
    #pragma unroll
    for (int nt=0; nt<4; nt++){
        #pragma unroll
        for (int c=0;c<2;c++){
            int col = bcol + noff + nt*8 + tg*2 + c;
            float bias = b_ih[col] + b_hh[col];
            #pragma unroll
            for (int mt=0;mt<2;mt++)
                #pragma unroll
                for (int hf=0; hf<2; hf++){
                    int row = row0 + moff + mt*16 + gr + hf*8;
                    g_xproj[(size_t)row*G4n + col] = acc[mt*4+nt][hf*2+c] + bias;
                }
        }
    }
}

// ================= persistent LSTM (single launch, f32x2 dot) =================
__global__ __launch_bounds__(256) void k_lstm_all(const float* __restrict__ w_hh)
{
    extern __shared__ float sm[];
    float* w_s  = sm;
    float* h_s  = sm + 16*512;
    float* pbuf = h_s + 32*516;
    int tid = threadIdx.x, lane = tid & 31, w = tid >> 5;
    int js = blockIdx.x;

    for (int i = tid; i < 16*128; i += 256){
        int r = i >> 7, q = i & 127;
        int grow = (r>>2)*Hn + js*4 + (r&3);
        *(float4*)&w_s[r*512 + q*4] = *(const float4*)&w_hh[(size_t)grow*Hn + q*4];
    }

    int jh = w >> 2;
    int rq = w & 3;
    const ulonglong2* w0p = (const ulonglong2*)(w_s + (rq*4+0)*512 + jh*256);
    const ulonglong2* w1p = (const ulonglong2*)(w_s + (rq*4+1)*512 + jh*256);
    const ulonglong2* w2p = (const ulonglong2*)(w_s + (rq*4+2)*512 + jh*256);
    const ulonglong2* w3p = (const ulonglong2*)(w_s + (rq*4+3)*512 + jh*256);

    float c_reg = 0.f;
    volatile unsigned* vc = &g_ctr;

    for (int t = 0; t < Tn; t++){
        int par = t & 1;
        if (tid == 0 && t > 0){
            unsigned target = (unsigned)t * 128u;
            while (*vc < target) {}
        }
        __syncthreads();

        for (int i = tid; i < 32*128; i += 256){
            int b = i >> 7, q = i & 127;
            float4 hv = __ldcg((const float4*)&g_hbuf[par][b*512 + q*4]);
            *(float4*)&h_s[b*516 + q*4] = hv;
        }
        __syncthreads();

        {
            const ulonglong2* hbp = (const ulonglong2*)(h_s + lane*516 + jh*256);
            ull a00=0,a01=0, a10=0,a11=0, a20=0,a21=0, a30=0,a31=0;
            #pragma unroll 8
            for (int q = 0; q < 64; q++){
                ulonglong2 hv = hbp[q];
                ulonglong2 w0 = w0p[q]; a00=ffma2(w0.x,hv.x,a00); a01=ffma2(w0.y,hv.y,a01);
                ulonglong2 w1 = w1p[q]; a10=ffma2(w1.x,hv.x,a10); a11=ffma2(w1.y,hv.y,a11);
                ulonglong2 w2 = w2p[q]; a20=ffma2(w2.x,hv.x,a20); a21=ffma2(w2.y,hv.y,a21);
                ulonglong2 w3 = w3p[q]; a30=ffma2(w3.x,hv.x,a30); a31=ffma2(w3.y,hv.y,a31);
            }
            float2 u, v2;
            u=unpk(a00); v2=unpk(a01); pbuf[(jh*16 + rq*4+0)*33 + lane] = u.x+u.y+v2.x+v2.y;
            u=unpk(a10); v2=unpk(a11); pbuf[(jh*16 + rq*4+1)*33 + lane] = u.x+u.y+v2.x+v2.y;
            u=unpk(a20); v2=unpk(a21); pbuf[(jh*16 + rq*4+2)*33 + lane] = u.x+u.y+v2.x+v2.y;
            u=unpk(a30); v2=unpk(a31); pbuf[(jh*16 + rq*4+3)*33 + lane] = u.x+u.y+v2.x+v2.y;
        }
        __syncthreads();

        if (tid < 128){
            int b = tid & 31, jj = tid >> 5;
            int j = js*4 + jj;
            float g4[4];
            #pragma unroll
            for (int gate = 0; gate < 4; gate++){
                int r = gate*4 + jj;
                g4[gate] = pbuf[r*33 + b] + pbuf[(16 + r)*33 + b]
                         + g_xproj[(size_t)(b*Tn + t)*G4n + gate*Hn + j];
            }
            float c = c_reg;
            c = sigmf(g4[1])*c + sigmf(g4[0])*tanhf(g4[2]);
            float hv = sigmf(g4[3])*tanhf(c);
            c_reg = c;
            g_hbuf[par^1][b*512 + j] = hv;
            g_hb[(size_t)(b*Tn + t)*Hn + j] = __float2bfloat16(hv);
        }
        __threadfence();
        __syncthreads();
        if (tid == 0) atomicAdd(&g_ctr, 1u);
    }
}

// ================= k_big: cp.async BK=64 triple GEMM + fused LSE =================
// CTA 128 rows x 64 v; 20 chunks of K=64 across 3 phases; unpadded 128B rows + XOR swizzle.
#define A_BYTES 16384
#define B_BYTES 8192
#define BUFSZ   (A_BYTES + B_BYTES)
#define DYN_BIG (2*BUFSZ)

__device__ __forceinline__ void issue_chunk(uint32_t abase, int buf, int tid,
    const __nv_bfloat16* __restrict__ Ag, const __nv_bfloat16* __restrict__ Bg,
    int lda, int local, int row0, int v0)
{
    uint32_t As = abase + buf*BUFSZ;
    uint32_t Bs = As + A_BYTES;
    #pragma unroll
    for (int i=0;i<4;i++){
        int idx = tid + i*256; int r = idx>>3, u = idx&7;
        cp16(As + SWZ128(r*128 + u*16), Ag + (size_t)(row0+r)*lda + local*64 + u*8);
    }
    #pragma unroll
    for (int i=0;i<2;i++){
        int idx = tid + i*256; int r = idx>>3, u = idx&7;
        int v = v0 + r; if (v >= Vn) v = Vn-1;   // clamp; epilogue discards
        cp16(Bs + SWZ128(r*128 + u*16), Bg + (size_t)v*lda + local*64 + u*8);
    }
    CP_COMMIT();
}

__device__ __forceinline__ void comp64(const char* dyn, uint32_t /*unused*/, int buf,
                                       int lane, int moff, int noff, float (&acc)[8][4])
{
    const char* As = dyn + buf*BUFSZ;
    const char* Bs = As + A_BYTES;
    int gr = lane>>2, tg = lane&3;
    #pragma unroll
    for (int kk=0; kk<4; kk++){
        int cb = (kk*16 + tg*2)*2;             // byte col of k-pair
        uint32_t afr[2][4], bfr[4][2];
        #pragma unroll
        for (int mt=0; mt<2; mt++){
            int r0 = moff + mt*16 + gr;
            int r1 = r0 + 8;
            afr[mt][0] = *(const uint32_t*)(As + SWZ128(r0*128 + cb));
            afr[mt][1] = *(const uint32_t*)(As + SWZ128(r1*128 + cb));
            afr[mt][2] = *(const uint32_t*)(As + SWZ128(r0*128 + cb + 16));
            afr[mt][3] = *(const uint32_t*)(As + SWZ128(r1*128 + cb + 16));
        }
        #pragma unroll
        for (int nt=0; nt<4; nt++){
            int nr = noff + nt*8 + gr;
            bfr[nt][0] = *(const uint32_t*)(Bs + SWZ128(nr*128 + cb));
            bfr[nt][1] = *(const uint32_t*)(Bs + SWZ128(nr*128 + cb + 16));
        }
        #pragma unroll
        for (int mt=0;mt<2;mt++)
            #pragma unroll
            for (int nt=0;nt<4;nt++)
                mma16(acc[mt*4+nt], afr[mt], bfr[nt]);
    }
}

__device__ __forceinline__ void chunk_src(int c, const __nv_bfloat16*& A,
                                          const __nv_bfloat16*& B, int& ld, int& loc, int& p)
{
    if (c < 8)      { p=0; A=g_hb;  B=g_wpb; ld=Hn;   loc=c;    }
    else if (c < 16){ p=1; A=g_ZZb; B=g_W2b; ld=TWOK; loc=c-8;  }
    else            { p=2; A=g_zb;  B=g_wgb; ld=Kn;   loc=c-16; }
}

__global__ __launch_bounds__(256) void k_big(
    const float* __restrict__ b_prior, const float* __restrict__ b_gen,
    const int* __restrict__ x)
{
    extern __shared__ __align__(128) char dynb[];
    __shared__ float sh_sum[128][3];
    __shared__ float sh_shift[128];
    __shared__ int   sh_xv[128];

    int vt = blockIdx.x, rt = blockIdx.y;
    int row0 = rt*128, v0 = vt*64;
    int tid = threadIdx.x;
    uint32_t abase = smem_u32(dynb);

    if (tid < 128){
        sh_shift[tid] = g_cst[0] - 0.5f*g_sumz2[row0+tid];
        sh_xv[tid]    = x[row0+tid];
        sh_sum[tid][0]=0.f; sh_sum[tid][1]=0.f; sh_sum[tid][2]=0.f;
    }

    float accP[8][4] = {};
    float accM[8][4] = {};
    float accG[8][4] = {};

    int lane = tid&31, wid = tid>>5;
    int moff = (wid>>1)*32, noff = (wid&1)*32;

    {
        const __nv_bfloat16 *Ag, *Bg; int lda, loc, p;
        chunk_src(0, Ag, Bg, lda, loc, p);
        issue_chunk(abase, 0, tid, Ag, Bg, lda, loc, row0, v0);
    }
    #pragma unroll 1
    for (int c = 0; c < 20; c++){
        bool more = (c+1 < 20);
        if (more){
            const __nv_bfloat16 *Ag, *Bg; int lda, loc, p;
            chunk_src(c+1, Ag, Bg, lda, loc, p);
            issue_chunk(abase, (c+1)&1, tid, Ag, Bg, lda, loc, row0, v0);
            cp_wait<1>();
        } else {
            cp_wait<0>();
        }
        __syncthreads();
        int p = (c < 8) ? 0 : (c < 16) ? 1 : 2;
        if (p == 0)      comp64(dynb, abase, c&1, lane, moff, noff, accP);
        else if (p == 1) comp64(dynb, abase, c&1, lane, moff, noff, accM);
        else             comp64(dynb, abase, c&1, lane, moff, noff, accG);
    }

    __syncthreads();

    float rs[4][3] = {};
    #pragma unroll
    for (int nt=0; nt<4; nt++){
        #pragma unroll
        for (int cc=0;cc<2;cc++){
            int n = noff + nt*8 + (lane&3)*2 + cc;
            int v = v0 + n;
            bool ok = v < Vn;
            int vc = ok ? v : (Vn-1);
            float bp = __ldg(&b_prior[vc]);
            float bg = __ldg(&b_gen[vc]);
            float cv = g_cst[vc];
            #pragma unroll
            for (int mt=0;mt<2;mt++){
                #pragma unroll
                for (int hf=0; hf<2; hf++){
                    int rloc = moff + mt*16 + (lane>>2) + hf*8;
                    int ai = hf*2 + cc;
                    float s1 = accP[mt*4+nt][ai] + bp;
                    float s3 = accG[mt*4+nt][ai] + bg;
                    float s2 = s1 + cv + accM[mt*4+nt][ai] - sh_shift[rloc];
                    if (ok){
                        rs[mt*2+hf][0] += __expf(s1);
                        rs[mt*2+hf][1] += __expf(s2);
                        rs[mt*2+hf][2] += __expf(s3);
                        if (v == sh_xv[rloc]) g_tgt[row0 + rloc] = s3;
                    }
                }
            }
        }
    }
    #pragma unroll
    for (int lr=0; lr<4; lr++){
        float v0s = rs[lr][0], v1s = rs[lr][1], v2s = rs[lr][2];
        v0s += __shfl_xor_sync(0xffffffffu, v0s, 1);
        v0s += __shfl_xor_sync(0xffffffffu, v0s, 2);
        v1s += __shfl_xor_sync(0xffffffffu, v1s, 1);
        v1s += __shfl_xor_sync(0xffffffffu, v1s, 2);
        v2s += __shfl_xor_sync(0xffffffffu, v2s, 1);
        v2s += __shfl_xor_sync(0xffffffffu, v2s, 2);
        if ((lane&3)==0){
            int mt = lr>>1, hf = lr&1;
            int rloc = moff + mt*16 + (lane>>2) + hf*8;
            atomicAdd(&sh_sum[rloc][0], v0s);
            atomicAdd(&sh_sum[rloc][1], v1s);
            atomicAdd(&sh_sum[rloc][2], v2s);
        }
    }
    __syncthreads();
    if (tid < 128){
        g_part[(0*NVT + vt)*BT + row0 + tid] = sh_sum[tid][0];
        g_part[(1*NVT + vt)*BT + row0 + tid] = sh_sum[tid][1];
        g_part[(2*NVT + vt)*BT + row0 + tid] = sh_sum[tid][2];
    }
}

// ---------------- per-row LSE finish ----------------
__global__ void k_lse(const int* __restrict__ x_sl)
{
    int row = blockIdx.x*256 + threadIdx.x;
    if (row >= BT) return;
    float S1=0.f, S2=0.f, S3=0.f;
    for (int vt = 0; vt < NVT; vt++){
        S1 += g_part[(0*NVT+vt)*BT + row];
        S2 += g_part[(1*NVT+vt)*BT + row];
        S3 += g_part[(2*NVT+vt)*BT + row];
    }
    int b = row / Tn, t = row % Tn;
    float shift = g_cst[0] - 0.5f*g_sumz2[row];
    float lse_p = logf(S1);
    float lse_m = shift + logf(S2);
    float lse_g = logf(S3);
    float mask = (t < x_sl[b]) ? 1.f : 0.f;
    g_contrib[row] = mask * (g_tgt[row] - lse_g - g_qzlp[row] + (lse_m - lse_p));
}

// ---------------- final scalar ----------------
__global__ void k_final(const int* __restrict__ x_sl, float* __restrict__ out)
{
    __shared__ float red[256];
    int tid = threadIdx.x;
    float s = 0.f;
    for (int i = tid; i < BT; i += 256) s += g_contrib[i];
    red[tid] = s; __syncthreads();
    for (int st = 128; st > 0; st >>= 1){
        if (tid < st) red[tid] += red[tid+st];
        __syncthreads();
    }
    if (tid == 0){
        int tot = 0;
        for (int b = 0; b < Bn; b++) tot += x_sl[b];
        out[0] = -red[0] / (float)tot;
    }
}

// ---------------- launch ----------------
extern "C" void kernel_launch(void* const* d_in, const int* in_sizes, int n_in,
                              void* d_out, int out_size)
{
    const int*   x       = (const int*)  d_in[0];
    const int*   x_sl    = (const int*)  d_in[1];
    const float* eps     = (const float*)d_in[2];
    const float* emb     = (const float*)d_in[3];
    const float* w_ih    = (const float*)d_in[4];
    const float* w_hh    = (const float*)d_in[5];
    const float* b_ih    = (const float*)d_in[6];
    const float* b_hh    = (const float*)d_in[7];
    const float* w_prior = (const float*)d_in[8];
    const float* b_prior = (const float*)d_in[9];
    const float* w_gen   = (const float*)d_in[10];
    const float* b_gen   = (const float*)d_in[11];
    float* out = (float*)d_out;

    int smem_lstm = (16*512 + 32*516 + 2*16*33)*(int)sizeof(float); // ~103 KB
    cudaFuncSetAttribute(k_lstm_all, cudaFuncAttributeMaxDynamicSharedMemorySize, smem_lstm);
    cudaFuncSetAttribute(k_big,      cudaFuncAttributeMaxDynamicSharedMemorySize, DYN_BIG);

    __nv_bfloat16 *d_wihb, *d_wpb, *d_wgb;
    cudaGetSymbolAddress((void**)&d_wihb, g_wihb);
    cudaGetSymbolAddress((void**)&d_wpb,  g_wpb);
    cudaGetSymbolAddress((void**)&d_wgb,  g_wgb);

    k_prep_z<<<BT, 256>>>(x, x_sl, eps, emb);                      // 1 (init folded)
    k_cvt<<<512, 256>>>(w_ih, d_wihb, G4n*Kn);                     // 2
    k_xproj16<<<dim3(G4n/64, BT/128), 256>>>(b_ih, b_hh);          // 3
    k_lstm_all<<<128, 256, smem_lstm>>>(w_hh);                     // 4  <- ncu target
    k_prep_v<<<Vn, 256>>>(emb);                                    // 5
    k_cvt<<<2048, 256>>>(w_prior, d_wpb, Vn*Hn);                   // 6
    k_cvt<<<1024, 256>>>(w_gen,   d_wgb, Vn*Kn);                   // 7
    k_big<<<dim3(NVT, BT/128), 256, DYN_BIG>>>(b_prior, b_gen, x); // 8
    k_lse<<<BT/256, 256>>>(x_sl);                                  // 9
    k_final<<<1, 256>>>(x_sl, out);                                // 10
}

// round 11
// speedup vs baseline: 8.8169x; 1.0331x over previous
#include <cuda_runtime.h>
#include <cuda_bf16.h>
#include <cstdint>

#define Bn 32
#define Tn 128
#define Kn 256
#define Hn 512
#define Vn 10000
#define BT (Bn*Tn)
#define G4n (4*Hn)
#define TWOK (2*Kn)
#define NVT 157              // ceil(Vn/64)

#define HALF_LOG_2PI 0.918938533204672741780329736406f

typedef unsigned long long ull;

// ---------------- static scratch ----------------
__device__ __align__(16) __nv_bfloat16 g_zb[BT*Kn];      // 2 MB
__device__ __align__(16) __nv_bfloat16 g_ZZb[BT*TWOK];   // 4 MB [z | z^2]
__device__ __align__(16) __nv_bfloat16 g_hb[BT*Hn];      // 4 MB
__device__ __align__(16) __nv_bfloat16 g_W2b[Vn*TWOK];   // 10 MB
__device__ __align__(16) __nv_bfloat16 g_wpb[Vn*Hn];     // 10 MB
__device__ __align__(16) __nv_bfloat16 g_wgb[Vn*Kn];     // 5 MB
__device__ __align__(16) __nv_bfloat16 g_wihb[G4n*Kn];   // 1 MB
__device__ __align__(16) float g_xproj[BT*G4n];          // 32 MB
__device__ float g_cst[Vn];
__device__ float g_qzlp[BT];
__device__ float g_sumz2[BT];
__device__ float g_tgt[BT];
__device__ float g_part[3*NVT*BT];
__device__ float g_contrib[BT];
__device__ __align__(16) float g_hbuf[2][Bn*Hn];
__device__ unsigned g_ctr;

__device__ __forceinline__ float softplus_b(float x){
    return (x > 20.f) ? x : log2f(1.f + exp2f(x));
}
__device__ __forceinline__ float sigmf(float x){ return 1.f/(1.f+expf(-x)); }

__device__ __forceinline__ ull ffma2(ull a, ull b, ull c){
    ull d;
    asm("fma.rn.f32x2 %0, %1, %2, %3;" : "=l"(d) : "l"(a), "l"(b), "l"(c));
    return d;
}
__device__ __forceinline__ float2 unpk(ull v){
    float lo, hi;
    asm("mov.b64 {%0, %1}, %2;" : "=f"(lo), "=f"(hi) : "l"(v));
    return make_float2(lo, hi);
}

// ---------------- cp.async helpers ----------------
__device__ __forceinline__ uint32_t smem_u32(const void* p){
    uint32_t a;
    asm("{ .reg .u64 t; cvta.to.shared.u64 t, %1; cvt.u32.u64 %0, t; }" : "=r"(a) : "l"(p));
    return a;
}
__device__ __forceinline__ void cp16(uint32_t dst, const void* src){
    asm volatile("cp.async.cg.shared.global [%0], [%1], 16;" :: "r"(dst), "l"(src) : "memory");
}
#define CP_COMMIT() asm volatile("cp.async.commit_group;" ::: "memory")
template<int N> __device__ __forceinline__ void cp_wait(){
    asm volatile("cp.async.wait_group %0;" :: "n"(N) : "memory");
}
#define SWZ128(o) ((o) ^ (((o) >> 3) & 0x70))

// ================= merged prep: z-path, v-path, all weight converts =================
// grid = Vn blocks of 256. Every block: v-path (W2b, cst, wp/wg/wih converts).
// Blocks < BT additionally: z-path (zb, ZZb, qzlp, sumz2) + hbuf/ctr init.
__global__ void k_prep(const int* __restrict__ x, const int* __restrict__ x_sl,
                       const float* __restrict__ eps, const float* __restrict__ emb,
                       const float* __restrict__ w_ih, const float* __restrict__ w_prior,
                       const float* __restrict__ w_gen)
{
    int v = blockIdx.x;          // 0..Vn-1
    int k = threadIdx.x;         // 0..255
    __shared__ float red[256];

    // ---- v-path ----
    float mu = emb[v*TWOK + k];
    float sp = softplus_b(emb[v*TWOK + Kn + k]);
    float inv2 = 0.5f/(sp*sp);
    g_W2b[v*TWOK + k]      = __float2bfloat16(2.f*inv2*mu);
    g_W2b[v*TWOK + Kn + k] = __float2bfloat16(-inv2);
    // weight converts
    g_wpb[v*Hn + k]       = __float2bfloat16(w_prior[(size_t)v*Hn + k]);
    g_wpb[v*Hn + 256 + k] = __float2bfloat16(w_prior[(size_t)v*Hn + 256 + k]);
    g_wgb[v*Kn + k]       = __float2bfloat16(w_gen[(size_t)v*Kn + k]);
    {
        int idx = v*256 + k;
        if (idx < G4n*Kn) g_wihb[idx] = __float2bfloat16(w_ih[idx]);
        if (idx < Bn*Hn)  g_hbuf[0][idx] = 0.f;
        if (idx == 0)     g_ctr = 0u;
    }
    float c = -HALF_LOG_2PI - logf(sp) - mu*mu*inv2;
    red[k] = c;
    __syncthreads();
    for (int s = 128; s > 0; s >>= 1){
        if (k < s) red[k] += red[k+s];
        __syncthreads();
    }
    if (k == 0) g_cst[v] = red[0];

    // ---- z-path (blocks 0..BT-1) ----
    if (v < BT){
        __shared__ float r1[256], r2[256];
        int row = v;
        int b = row / Tn, t = row % Tn;
        int xv = x[row];
        float mask = (t < x_sl[b]) ? 1.f : 0.f;
        float muq = emb[xv*TWOK + k];
        float sq  = softplus_b(emb[xv*TWOK + Kn + k]);
        float e   = eps[row*Kn + k];
        float zv  = (muq + sq*e) * mask;
        g_zb[row*Kn + k]         = __float2bfloat16(zv);
        g_ZZb[row*TWOK + k]      = __float2bfloat16(zv);
        g_ZZb[row*TWOK + Kn + k] = __float2bfloat16(zv*zv);
        float q = -HALF_LOG_2PI - logf(sq) - 0.5f*e*e;
        r1[k] = q; r2[k] = zv*zv;
        __syncthreads();
        for (int s = 128; s > 0; s >>= 1){
            if (k < s){ r1[k] += r1[k+s]; r2[k] += r2[k+s]; }
            __syncthreads();
        }
        if (k == 0){ g_qzlp[row] = r1[0]; g_sumz2[row] = r2[0]; }
    }
}

// ================= legacy bf16 mma (m16n8k16) =================
__device__ __forceinline__ void mma16(float* d, const uint32_t* a, const uint32_t* b){
    asm volatile("mma.sync.aligned.m16n8k16.row.col.f32.bf16.bf16.f32 "
        "{%0,%1,%2,%3}, {%4,%5,%6,%7}, {%8,%9}, {%0,%1,%2,%3};"
        : "+f"(d[0]),"+f"(d[1]),"+f"(d[2]),"+f"(d[3])
        : "r"(a[0]),"r"(a[1]),"r"(a[2]),"r"(a[3]), "r"(b[0]),"r"(b[1]));
}

// ---------------- x_proj GEMM (legacy bf16 mma, padded-smem variant) ----------------
struct SmemTC {
    __nv_bfloat16 As[2][128][40];
    __nv_bfloat16 Bs[2][64][40];
};
__device__ __forceinline__ void ldA16s(const __nv_bfloat16* __restrict__ zb,
                                       int row0, int kt, int tid, uint4 (&rA)[2]){
    #pragma unroll
    for (int i=0;i<2;i++){
        int idx = tid + i*256;
        int row = idx>>2, q = idx&3;
        int grow = row0 + row;
        rA[i] = make_uint4(0u,0u,0u,0u);
        if ((grow & (Tn-1)) != 0)
            rA[i] = *(const uint4*)(zb + (size_t)(grow-1)*Kn + kt*32 + q*8);
    }
}
__device__ __forceinline__ void ldB16(const __nv_bfloat16* __restrict__ Bg, int ldb,
                                      int v0, int nmax, int kt, int tid, uint4& rB){
    int row = tid>>2, q = tid&3;
    int v = v0 + row; if (v >= nmax) v = nmax-1;
    rB = *(const uint4*)(Bg + (size_t)v*ldb + kt*32 + q*8);
}
__device__ __forceinline__ void stAB16(SmemTC* sm, int buf, int tid,
                                       const uint4 (&rA)[2], const uint4& rB){
    #pragma unroll
    for (int i=0;i<2;i++){
        int idx = tid + i*256; int row = idx>>2, q = idx&3;
        *(uint4*)&sm->As[buf][row][q*8] = rA[i];
    }
    { int row = tid>>2, q = tid&3;
      *(uint4*)&sm->Bs[buf][row][q*8] = rB; }
}
__device__ __forceinline__ void comp16(SmemTC* sm, int buf, int lane, int moff, int noff,
                                       float (&acc)[8][4]){
    int gr = lane>>2, tg = lane&3;
    #pragma unroll
    for (int kk=0; kk<2; kk++){
        int c0 = kk*16 + tg*2;
        uint32_t afr[2][4], bfr[4][2];
        #pragma unroll
        for (int mt=0; mt<2; mt++){
            int rbase = moff + mt*16 + gr;
            afr[mt][0] = *(const uint32_t*)&sm->As[buf][rbase  ][c0];
            afr[mt][1] = *(const uint32_t*)&sm->As[buf][rbase+8][c0];
            afr[mt][2] = *(const uint32_t*)&sm->As[buf][rbase  ][c0+8];
            afr[mt][3] = *(const uint32_t*)&sm->As[buf][rbase+8][c0+8];
        }
        #pragma unroll
        for (int nt=0; nt<4; nt++){
            int nrow = noff + nt*8 + gr;
            bfr[nt][0] = *(const uint32_t*)&sm->Bs[buf][nrow][c0];
            bfr[nt][1] = *(const uint32_t*)&sm->Bs[buf][nrow][c0+8];
        }
        #pragma unroll
        for (int mt=0;mt<2;mt++)
            #pragma unroll
            for (int nt=0;nt<4;nt++)
                mma16(acc[mt*4+nt], afr[mt], bfr[nt]);
    }
}

__global__ __launch_bounds__(256) void k_xproj16(const float* __restrict__ b_ih,
                                                 const float* __restrict__ b_hh)
{
    __shared__ SmemTC sm;
    int bcol = blockIdx.x * 64;
    int row0 = blockIdx.y * 128;
    int tid = threadIdx.x;
    int lane = tid&31, wid = tid>>5;
    int moff = (wid>>1)*32, noff = (wid&1)*32;
    int gr = lane>>2, tg = lane&3;

    float acc[8][4] = {};
    {
        uint4 rA[2]; uint4 rB;
        ldA16s(g_zb,row0,0,tid,rA); ldB16(g_wihb,Kn,bcol,G4n,0,tid,rB);
        stAB16(&sm,0,tid,rA,rB);
        __syncthreads();
        const int nchunks = Kn/32;
        for (int kt=0; kt<nchunks; kt++){
            int cur = kt&1;
            bool more = (kt+1 < nchunks);
            if (more){ ldA16s(g_zb,row0,kt+1,tid,rA); ldB16(g_wihb,Kn,bcol,G4n,kt+1,tid,rB); }
            comp16(&sm,cur,lane,moff,noff,acc);
            if (more) stAB16(&sm,cur^1,tid,rA,rB);
            __syncthreads();
        }
    }
    #pragma unroll
    for (int nt=0; nt<4; nt++){
        #pragma unroll
        for (int c=0;c<2;c++){
            int col = bcol + noff + nt*8 + tg*2 + c;
            float bias = b_ih[col] + b_hh[col];
            #pragma unroll
            for (int mt=0;mt<2;mt++)
                #pragma unroll
                for (int hf=0; hf<2; hf++){
                    int row = row0 + moff + mt*16 + gr + hf*8;
                    g_xproj[(size_t)row*G4n + col] = acc[mt*4+nt][hf*2+c] + bias;
                }
        }
    }
}

// ================= persistent LSTM (single launch, f32x2 dot) =================
__global__ __launch_bounds__(256) void k_lstm_all(const float* __restrict__ w_hh)
{
    extern __shared__ float sm[];
    float* w_s  = sm;
    float* h_s  = sm + 16*512;
    float* pbuf = h_s + 32*516;
    int tid = threadIdx.x, lane = tid & 31, w = tid >> 5;
    int js = blockIdx.x;

    for (int i = tid; i < 16*128; i += 256){
        int r = i >> 7, q = i & 127;
        int grow = (r>>2)*Hn + js*4 + (r&3);
        *(float4*)&w_s[r*512 + q*4] = *(const float4*)&w_hh[(size_t)grow*Hn + q*4];
    }

    int jh = w >> 2;
    int rq = w & 3;
    const ulonglong2* w0p = (const ulonglong2*)(w_s + (rq*4+0)*512 + jh*256);
    const ulonglong2* w1p = (const ulonglong2*)(w_s + (rq*4+1)*512 + jh*256);
    const ulonglong2* w2p = (const ulonglong2*)(w_s + (rq*4+2)*512 + jh*256);
    const ulonglong2* w3p = (const ulonglong2*)(w_s + (rq*4+3)*512 + jh*256);

    float c_reg = 0.f;
    volatile unsigned* vc = &g_ctr;

    for (int t = 0; t < Tn; t++){
        int par = t & 1;
        if (tid == 0 && t > 0){
            unsigned target = (unsigned)t * 128u;
            while (*vc < target) {}
        }
        __syncthreads();

        for (int i = tid; i < 32*128; i += 256){
            int b = i >> 7, q = i & 127;
            float4 hv = __ldcg((const float4*)&g_hbuf[par][b*512 + q*4]);
            *(float4*)&h_s[b*516 + q*4] = hv;
        }
        __syncthreads();

        {
            const ulonglong2* hbp = (const ulonglong2*)(h_s + lane*516 + jh*256);
            ull a00=0,a01=0, a10=0,a11=0, a20=0,a21=0, a30=0,a31=0;
            #pragma unroll 8
            for (int q = 0; q < 64; q++){
                ulonglong2 hv = hbp[q];
                ulonglong2 w0 = w0p[q]; a00=ffma2(w0.x,hv.x,a00); a01=ffma2(w0.y,hv.y,a01);
                ulonglong2 w1 = w1p[q]; a10=ffma2(w1.x,hv.x,a10); a11=ffma2(w1.y,hv.y,a11);
                ulonglong2 w2 = w2p[q]; a20=ffma2(w2.x,hv.x,a20); a21=ffma2(w2.y,hv.y,a21);
                ulonglong2 w3 = w3p[q]; a30=ffma2(w3.x,hv.x,a30); a31=ffma2(w3.y,hv.y,a31);
            }
            float2 u, v2;
            u=unpk(a00); v2=unpk(a01); pbuf[(jh*16 + rq*4+0)*33 + lane] = u.x+u.y+v2.x+v2.y;
            u=unpk(a10); v2=unpk(a11); pbuf[(jh*16 + rq*4+1)*33 + lane] = u.x+u.y+v2.x+v2.y;
            u=unpk(a20); v2=unpk(a21); pbuf[(jh*16 + rq*4+2)*33 + lane] = u.x+u.y+v2.x+v2.y;
            u=unpk(a30); v2=unpk(a31); pbuf[(jh*16 + rq*4+3)*33 + lane] = u.x+u.y+v2.x+v2.y;
        }
        __syncthreads();

        if (tid < 128){
            int b = tid & 31, jj = tid >> 5;
            int j = js*4 + jj;
            float g4[4];
            #pragma unroll
            for (int gate = 0; gate < 4; gate++){
                int r = gate*4 + jj;
                g4[gate] = pbuf[r*33 + b] + pbuf[(16 + r)*33 + b]
                         + g_xproj[(size_t)(b*Tn + t)*G4n + gate*Hn + j];
            }
            float c = c_reg;
            c = sigmf(g4[1])*c + sigmf(g4[0])*tanhf(g4[2]);
            float hv = sigmf(g4[3])*tanhf(c);
            c_reg = c;
            g_hbuf[par^1][b*512 + j] = hv;
            g_hb[(size_t)(b*Tn + t)*Hn + j] = __float2bfloat16(hv);
        }
        __threadfence();
        __syncthreads();
        if (tid == 0) atomicAdd(&g_ctr, 1u);
    }
}

// ================= k_big: cp.async triple GEMM, 2 CTAs/SM, fused LSE =================
#define A_BYTES 16384
#define B_BYTES 8192
#define BUFSZ   (A_BYTES + B_BYTES)
#define DYN_BIG (2*BUFSZ)

__device__ __forceinline__ void issue_chunk(uint32_t abase, int buf, int tid,
    const __nv_bfloat16* __restrict__ Ag, const __nv_bfloat16* __restrict__ Bg,
    int lda, int local, int row0, int v0)
{
    uint32_t As = abase + buf*BUFSZ;
    uint32_t Bs = As + A_BYTES;
    #pragma unroll
    for (int i=0;i<4;i++){
        int idx = tid + i*256; int r = idx>>3, u = idx&7;
        cp16(As + SWZ128(r*128 + u*16), Ag + (size_t)(row0+r)*lda + local*64 + u*8);
    }
    #pragma unroll
    for (int i=0;i<2;i++){
        int idx = tid + i*256; int r = idx>>3, u = idx&7;
        int v = v0 + r; if (v >= Vn) v = Vn-1;   // clamp; epilogue discards
        cp16(Bs + SWZ128(r*128 + u*16), Bg + (size_t)v*lda + local*64 + u*8);
    }
    CP_COMMIT();
}

__device__ __forceinline__ void comp64(const char* dyn, int buf,
                                       int lane, int moff, int noff, float (&acc)[8][4])
{
    const char* As = dyn + buf*BUFSZ;
    const char* Bs = As + A_BYTES;
    int gr = lane>>2, tg = lane&3;
    #pragma unroll
    for (int kk=0; kk<4; kk++){
        int cb = (kk*16 + tg*2)*2;             // byte col of k-pair
        uint32_t afr[2][4], bfr[4][2];
        #pragma unroll
        for (int mt=0; mt<2; mt++){
            int r0 = moff + mt*16 + gr;
            int r1 = r0 + 8;
            afr[mt][0] = *(const uint32_t*)(As + SWZ128(r0*128 + cb));
            afr[mt][1] = *(const uint32_t*)(As + SWZ128(r1*128 + cb));
            afr[mt][2] = *(const uint32_t*)(As + SWZ128(r0*128 + cb + 16));
            afr[mt][3] = *(const uint32_t*)(As + SWZ128(r1*128 + cb + 16));
        }
        #pragma unroll
        for (int nt=0; nt<4; nt++){
            int nr = noff + nt*8 + gr;
            bfr[nt][0] = *(const uint32_t*)(Bs + SWZ128(nr*128 + cb));
            bfr[nt][1] = *(const uint32_t*)(Bs + SWZ128(nr*128 + cb + 16));
        }
        #pragma unroll
        for (int mt=0;mt<2;mt++)
            #pragma unroll
            for (int nt=0;nt<4;nt++)
                mma16(acc[mt*4+nt], afr[mt], bfr[nt]);
    }
}

__device__ __forceinline__ void chunk_src(int c, const __nv_bfloat16*& A,
                                          const __nv_bfloat16*& B, int& ld, int& loc)
{
    if (c < 8)      { A=g_hb;  B=g_wpb; ld=Hn;   loc=c;    }
    else if (c < 16){ A=g_ZZb; B=g_W2b; ld=TWOK; loc=c-8;  }
    else            { A=g_zb;  B=g_wgb; ld=Kn;   loc=c-16; }
}

__global__ __launch_bounds__(256,2) void k_big(
    const float* __restrict__ b_prior, const float* __restrict__ b_gen,
    const int* __restrict__ x)
{
    extern __shared__ __align__(128) char dynb[];
    __shared__ float sh_sum[128][3];
    __shared__ float sh_shift[128];
    __shared__ int   sh_xv[128];

    int vt = blockIdx.x, rt = blockIdx.y;
    int row0 = rt*128, v0 = vt*64;
    int tid = threadIdx.x;
    uint32_t abase = smem_u32(dynb);

    if (tid < 128){
        sh_shift[tid] = g_cst[0] - 0.5f*g_sumz2[row0+tid];
        sh_xv[tid]    = x[row0+tid];
        sh_sum[tid][0]=0.f; sh_sum[tid][1]=0.f; sh_sum[tid][2]=0.f;
    }

    int lane = tid&31, wid = tid>>5;
    int moff = (wid>>1)*32, noff = (wid&1)*32;

    float accA[8][4] = {};      // phase P, then reused for phase G
    float accB[8][4] = {};      // phase M
    float rs1[4] = {}, rs2[4] = {}, rs3[4] = {};

    // prologue: issue chunk 0 (race-free pattern: wait -> sync -> issue -> comp)
    {
        const __nv_bfloat16 *Ag, *Bg; int lda, loc;
        chunk_src(0, Ag, Bg, lda, loc);
        issue_chunk(abase, 0, tid, Ag, Bg, lda, loc, row0, v0);
    }

    // phases P (0..7) and M (8..15)
    #pragma unroll 1
    for (int c = 0; c < 16; c++){
        cp_wait<0>();
        __syncthreads();
        {
            const __nv_bfloat16 *Ag, *Bg; int lda, loc;
            chunk_src(c+1, Ag, Bg, lda, loc);
            issue_chunk(abase, (c+1)&1, tid, Ag, Bg, lda, loc, row0, v0);
        }
        if (c < 8) comp64(dynb, c&1, lane, moff, noff, accA);
        else       comp64(dynb, c&1, lane, moff, noff, accB);
    }

    // epilogue PM: exp(s1), exp(s2) — frees accA for phase G
    #pragma unroll
    for (int nt=0; nt<4; nt++){
        #pragma unroll
        for (int cc=0;cc<2;cc++){
            int n = noff + nt*8 + (lane&3)*2 + cc;
            int v = v0 + n;
            bool ok = v < Vn;
            int vc = ok ? v : (Vn-1);
            float bp = __ldg(&b_prior[vc]);
            float cv = g_cst[vc];
            #pragma unroll
            for (int mt=0;mt<2;mt++){
                #pragma unroll
                for (int hf=0; hf<2; hf++){
                    int rloc = moff + mt*16 + (lane>>2) + hf*8;
                    int ai = hf*2 + cc;
                    float s1 = accA[mt*4+nt][ai] + bp;
                    float s2 = s1 + cv + accB[mt*4+nt][ai] - sh_shift[rloc];
                    if (ok){
                        rs1[mt*2+hf] += __expf(s1);
                        rs2[mt*2+hf] += __expf(s2);
                    }
                }
            }
        }
    }
    #pragma unroll
    for (int i=0;i<8;i++)
        #pragma unroll
        for (int j=0;j<4;j++) accA[i][j] = 0.f;

    // phase G (16..19); chunk 16 already in flight
    #pragma unroll 1
    for (int c = 16; c < 20; c++){
        cp_wait<0>();
        __syncthreads();
        if (c+1 < 20){
            const __nv_bfloat16 *Ag, *Bg; int lda, loc;
            chunk_src(c+1, Ag, Bg, lda, loc);
            issue_chunk(abase, (c+1)&1, tid, Ag, Bg, lda, loc, row0, v0);
        }
        comp64(dynb, c&1, lane, moff, noff, accA);
    }

    // epilogue G: exp(s3) + target logit
    #pragma unroll
    for (int nt=0; nt<4; nt++){
        #pragma unroll
        for (int cc=0;cc<2;cc++){
            int n = noff + nt*8 + (lane&3)*2 + cc;
            int v = v0 + n;
            bool ok = v < Vn;
            int vc = ok ? v : (Vn-1);
            float bg = __ldg(&b_gen[vc]);
            #pragma unroll
            for (int mt=0;mt<2;mt++){
                #pragma unroll
                for (int hf=0; hf<2; hf++){
                    int rloc = moff + mt*16 + (lane>>2) + hf*8;
                    int ai = hf*2 + cc;
                    float s3 = accA[mt*4+nt][ai] + bg;
                    if (ok){
                        rs3[mt*2+hf] += __expf(s3);
                        if (v == sh_xv[rloc]) g_tgt[row0 + rloc] = s3;
                    }
                }
            }
        }
    }

    // reduce across the 4 k-threads sharing each row
    #pragma unroll
    for (int lr=0; lr<4; lr++){
        float v0s = rs1[lr], v1s = rs2[lr], v2s = rs3[lr];
        v0s += __shfl_xor_sync(0xffffffffu, v0s, 1);
        v0s += __shfl_xor_sync(0xffffffffu, v0s, 2);
        v1s += __shfl_xor_sync(0xffffffffu, v1s, 1);
        v1s += __shfl_xor_sync(0xffffffffu, v1s, 2);
        v2s += __shfl_xor_sync(0xffffffffu, v2s, 1);
        v2s += __shfl_xor_sync(0xffffffffu, v2s, 2);
        if ((lane&3)==0){
            int mt = lr>>1, hf = lr&1;
            int rloc = moff + mt*16 + (lane>>2) + hf*8;
            atomicAdd(&sh_sum[rloc][0], v0s);
            atomicAdd(&sh_sum[rloc][1], v1s);
            atomicAdd(&sh_sum[rloc][2], v2s);
        }
    }
    __syncthreads();
    if (tid < 128){
        g_part[(0*NVT + vt)*BT + row0 + tid] = sh_sum[tid][0];
        g_part[(1*NVT + vt)*BT + row0 + tid] = sh_sum[tid][1];
        g_part[(2*NVT + vt)*BT + row0 + tid] = sh_sum[tid][2];
    }
}

// ---------------- per-row LSE finish ----------------
__global__ void k_lse(const int* __restrict__ x_sl)
{
    int row = blockIdx.x*256 + threadIdx.x;
    if (row >= BT) return;
    float S1=0.f, S2=0.f, S3=0.f;
    for (int vt = 0; vt < NVT; vt++){
        S1 += g_part[(0*NVT+vt)*BT + row];
        S2 += g_part[(1*NVT+vt)*BT + row];
        S3 += g_part[(2*NVT+vt)*BT + row];
    }
    int b = row / Tn, t = row % Tn;
    float shift = g_cst[0] - 0.5f*g_sumz2[row];
    float lse_p = logf(S1);
    float lse_m = shift + logf(S2);
    float lse_g = logf(S3);
    float mask = (t < x_sl[b]) ? 1.f : 0.f;
    g_contrib[row] = mask * (g_tgt[row] - lse_g - g_qzlp[row] + (lse_m - lse_p));
}

// ---------------- final scalar ----------------
__global__ void k_final(const int* __restrict__ x_sl, float* __restrict__ out)
{
    __shared__ float red[256];
    int tid = threadIdx.x;
    float s = 0.f;
    for (int i = tid; i < BT; i += 256) s += g_contrib[i];
    red[tid] = s; __syncthreads();
    for (int st = 128; st > 0; st >>= 1){
        if (tid < st) red[tid] += red[tid+st];
        __syncthreads();
    }
    if (tid == 0){
        int tot = 0;
        for (int b = 0; b < Bn; b++) tot += x_sl[b];
        out[0] = -red[0] / (float)tot;
    }
}

// ---------------- launch ----------------
extern "C" void kernel_launch(void* const* d_in, const int* in_sizes, int n_in,
                              void* d_out, int out_size)
{
    const int*   x       = (const int*)  d_in[0];
    const int*   x_sl    = (const int*)  d_in[1];
    const float* eps     = (const float*)d_in[2];
    const float* emb     = (const float*)d_in[3];
    const float* w_ih    = (const float*)d_in[4];
    const float* w_hh    = (const float*)d_in[5];
    const float* b_ih    = (const float*)d_in[6];
    const float* b_hh    = (const float*)d_in[7];
    const float* w_prior = (const float*)d_in[8];
    const float* b_prior = (const float*)d_in[9];
    const float* w_gen   = (const float*)d_in[10];
    const float* b_gen   = (const float*)d_in[11];
    float* out = (float*)d_out;

    int smem_lstm = (16*512 + 32*516 + 2*16*33)*(int)sizeof(float); // ~103 KB
    cudaFuncSetAttribute(k_lstm_all, cudaFuncAttributeMaxDynamicSharedMemorySize, smem_lstm);
    cudaFuncSetAttribute(k_big,      cudaFuncAttributeMaxDynamicSharedMemorySize, DYN_BIG);

    k_prep<<<Vn, 256>>>(x, x_sl, eps, emb, w_ih, w_prior, w_gen);  // 1
    k_xproj16<<<dim3(G4n/64, BT/128), 256>>>(b_ih, b_hh);          // 2
    k_lstm_all<<<128, 256, smem_lstm>>>(w_hh);                     // 3
    k_big<<<dim3(NVT, BT/128), 256, DYN_BIG>>>(b_prior, b_gen, x); // 4  <- ncu target
    k_lse<<<BT/256, 256>>>(x_sl);                                  // 5
    k_final<<<1, 256>>>(x_sl, out);                                // 6
}

// round 12
// speedup vs baseline: 9.5462x; 1.0827x over previous
#include <cuda_runtime.h>
#include <cuda_bf16.h>
#include <cstdint>

#define Bn 32
#define Tn 128
#define Kn 256
#define Hn 512
#define Vn 10000
#define BT (Bn*Tn)
#define G4n (4*Hn)
#define TWOK (2*Kn)
#define NVT 157              // ceil(Vn/64)

#define HALF_LOG_2PI 0.918938533204672741780329736406f

typedef unsigned long long ull;

// ---------------- static scratch ----------------
__device__ __align__(16) __nv_bfloat16 g_zb[BT*Kn];      // 2 MB
__device__ __align__(16) __nv_bfloat16 g_ZZb[BT*TWOK];   // 4 MB [z | z^2]
__device__ __align__(16) __nv_bfloat16 g_hb[BT*Hn];      // 4 MB
__device__ __align__(16) __nv_bfloat16 g_W2b[Vn*TWOK];   // 10 MB
__device__ __align__(16) __nv_bfloat16 g_wpb[Vn*Hn];     // 10 MB
__device__ __align__(16) __nv_bfloat16 g_wgb[Vn*Kn];     // 5 MB
__device__ __align__(16) __nv_bfloat16 g_wihb[G4n*Kn];   // 1 MB
__device__ __align__(16) float g_xproj[BT*G4n];          // 32 MB
__device__ float g_cst[Vn];
__device__ float g_qzlp[BT];
__device__ float g_sumz2[BT];
__device__ float g_tgt[BT];
__device__ float g_part[3*NVT*BT];
__device__ float g_contrib[BT];
__device__ __align__(16) float g_hbuf[2][Bn*Hn];
__device__ unsigned g_ctr;

__device__ __forceinline__ float softplus_b(float x){
    return (x > 20.f) ? x : log2f(1.f + exp2f(x));
}
__device__ __forceinline__ float sigmf(float x){ return 1.f/(1.f+expf(-x)); }

__device__ __forceinline__ ull ffma2(ull a, ull b, ull c){
    ull d;
    asm("fma.rn.f32x2 %0, %1, %2, %3;" : "=l"(d) : "l"(a), "l"(b), "l"(c));
    return d;
}
__device__ __forceinline__ float2 unpk(ull v){
    float lo, hi;
    asm("mov.b64 {%0, %1}, %2;" : "=f"(lo), "=f"(hi) : "l"(v));
    return make_float2(lo, hi);
}

// ---------------- cp.async / ldmatrix helpers ----------------
__device__ __forceinline__ uint32_t smem_u32(const void* p){
    uint32_t a;
    asm("{ .reg .u64 t; cvta.to.shared.u64 t, %1; cvt.u32.u64 %0, t; }" : "=r"(a) : "l"(p));
    return a;
}
__device__ __forceinline__ void cp16(uint32_t dst, const void* src){
    asm volatile("cp.async.cg.shared.global [%0], [%1], 16;" :: "r"(dst), "l"(src) : "memory");
}
#define CP_COMMIT() asm volatile("cp.async.commit_group;" ::: "memory")
template<int N> __device__ __forceinline__ void cp_wait(){
    asm volatile("cp.async.wait_group %0;" :: "n"(N) : "memory");
}
#define SWZ128(o) ((o) ^ (((o) >> 3) & 0x70))

__device__ __forceinline__ void ldsm4(uint32_t* r, uint32_t addr){
    asm volatile("ldmatrix.sync.aligned.m8n8.x4.shared.b16 {%0,%1,%2,%3}, [%4];"
        : "=r"(r[0]),"=r"(r[1]),"=r"(r[2]),"=r"(r[3]) : "r"(addr));
}

// ================= merged prep: z-path, v-path, all weight converts =================
__global__ void k_prep(const int* __restrict__ x, const int* __restrict__ x_sl,
                       const float* __restrict__ eps, const float* __restrict__ emb,
                       const float* __restrict__ w_ih, const float* __restrict__ w_prior,
                       const float* __restrict__ w_gen)
{
    int v = blockIdx.x;          // 0..Vn-1
    int k = threadIdx.x;         // 0..255
    __shared__ float red[256];

    // ---- v-path ----
    float mu = emb[v*TWOK + k];
    float sp = softplus_b(emb[v*TWOK + Kn + k]);
    float inv2 = 0.5f/(sp*sp);
    g_W2b[v*TWOK + k]      = __float2bfloat16(2.f*inv2*mu);
    g_W2b[v*TWOK + Kn + k] = __float2bfloat16(-inv2);
    g_wpb[v*Hn + k]       = __float2bfloat16(w_prior[(size_t)v*Hn + k]);
    g_wpb[v*Hn + 256 + k] = __float2bfloat16(w_prior[(size_t)v*Hn + 256 + k]);
    g_wgb[v*Kn + k]       = __float2bfloat16(w_gen[(size_t)v*Kn + k]);
    {
        int idx = v*256 + k;
        if (idx < G4n*Kn) g_wihb[idx] = __float2bfloat16(w_ih[idx]);
        if (idx < Bn*Hn)  g_hbuf[0][idx] = 0.f;
        if (idx == 0)     g_ctr = 0u;
    }
    float c = -HALF_LOG_2PI - logf(sp) - mu*mu*inv2;
    red[k] = c;
    __syncthreads();
    for (int s = 128; s > 0; s >>= 1){
        if (k < s) red[k] += red[k+s];
        __syncthreads();
    }
    if (k == 0) g_cst[v] = red[0];

    // ---- z-path (blocks 0..BT-1) ----
    if (v < BT){
        __shared__ float r1[256], r2[256];
        int row = v;
        int b = row / Tn, t = row % Tn;
        int xv = x[row];
        float mask = (t < x_sl[b]) ? 1.f : 0.f;
        float muq = emb[xv*TWOK + k];
        float sq  = softplus_b(emb[xv*TWOK + Kn + k]);
        float e   = eps[row*Kn + k];
        float zv  = (muq + sq*e) * mask;
        g_zb[row*Kn + k]         = __float2bfloat16(zv);
        g_ZZb[row*TWOK + k]      = __float2bfloat16(zv);
        g_ZZb[row*TWOK + Kn + k] = __float2bfloat16(zv*zv);
        float q = -HALF_LOG_2PI - logf(sq) - 0.5f*e*e;
        r1[k] = q; r2[k] = zv*zv;
        __syncthreads();
        for (int s = 128; s > 0; s >>= 1){
            if (k < s){ r1[k] += r1[k+s]; r2[k] += r2[k+s]; }
            __syncthreads();
        }
        if (k == 0){ g_qzlp[row] = r1[0]; g_sumz2[row] = r2[0]; }
    }
}

// ================= legacy bf16 mma (m16n8k16) =================
__device__ __forceinline__ void mma16(float* d, const uint32_t* a, const uint32_t* b){
    asm volatile("mma.sync.aligned.m16n8k16.row.col.f32.bf16.bf16.f32 "
        "{%0,%1,%2,%3}, {%4,%5,%6,%7}, {%8,%9}, {%0,%1,%2,%3};"
        : "+f"(d[0]),"+f"(d[1]),"+f"(d[2]),"+f"(d[3])
        : "r"(a[0]),"r"(a[1]),"r"(a[2]),"r"(a[3]), "r"(b[0]),"r"(b[1]));
}

// ---------------- x_proj GEMM (ldmatrix + padded smem, K=32 chunks) ----------------
struct __align__(16) SmemTC {
    __nv_bfloat16 As[2][128][40];
    __nv_bfloat16 Bs[2][64][40];
};
__device__ __forceinline__ void ldA16s(const __nv_bfloat16* __restrict__ zb,
                                       int row0, int kt, int tid, uint4 (&rA)[2]){
    #pragma unroll
    for (int i=0;i<2;i++){
        int idx = tid + i*256;
        int row = idx>>2, q = idx&3;
        int grow = row0 + row;
        rA[i] = make_uint4(0u,0u,0u,0u);
        if ((grow & (Tn-1)) != 0)
            rA[i] = *(const uint4*)(zb + (size_t)(grow-1)*Kn + kt*32 + q*8);
    }
}
__device__ __forceinline__ void ldB16(const __nv_bfloat16* __restrict__ Bg, int ldb,
                                      int v0, int nmax, int kt, int tid, uint4& rB){
    int row = tid>>2, q = tid&3;
    int v = v0 + row; if (v >= nmax) v = nmax-1;
    rB = *(const uint4*)(Bg + (size_t)v*ldb + kt*32 + q*8);
}
__device__ __forceinline__ void stAB16(SmemTC* sm, int buf, int tid,
                                       const uint4 (&rA)[2], const uint4& rB){
    #pragma unroll
    for (int i=0;i<2;i++){
        int idx = tid + i*256; int row = idx>>2, q = idx&3;
        *(uint4*)&sm->As[buf][row][q*8] = rA[i];
    }
    { int row = tid>>2, q = tid&3;
      *(uint4*)&sm->Bs[buf][row][q*8] = rB; }
}
// ldmatrix compute for padded-40 (80B row stride), K=32 chunk
__device__ __forceinline__ void comp16L(uint32_t As_b, uint32_t Bs_b,
    uint32_t aoffP, uint32_t acolb, uint32_t boffP, uint32_t bcolb,
    float (&acc)[8][4])
{
    #pragma unroll
    for (int kk=0; kk<2; kk++){
        uint32_t af0[4], af1[4], b0[4], b1[4];
        uint32_t ac = kk*32 + acolb;
        uint32_t bc = kk*32 + bcolb;
        ldsm4(af0, As_b + aoffP + ac);
        ldsm4(af1, As_b + aoffP + 16*80 + ac);
        ldsm4(b0,  Bs_b + boffP + bc);
        ldsm4(b1,  Bs_b + boffP + 16*80 + bc);
        mma16(acc[0], af0, b0);
        mma16(acc[1], af0, b0+2);
        mma16(acc[2], af0, b1);
        mma16(acc[3], af0, b1+2);
        mma16(acc[4], af1, b0);
        mma16(acc[5], af1, b0+2);
        mma16(acc[6], af1, b1);
        mma16(acc[7], af1, b1+2);
    }
}

__global__ __launch_bounds__(256) void k_xproj16(const float* __restrict__ b_ih,
                                                 const float* __restrict__ b_hh)
{
    __shared__ SmemTC sm;
    int bcol = blockIdx.x * 64;
    int row0 = blockIdx.y * 128;
    int tid = threadIdx.x;
    int lane = tid&31, wid = tid>>5;
    int moff = (wid>>1)*32, noff = (wid&1)*32;
    int gr = lane>>2, tg = lane&3;
    int row_l = lane&7, sub = lane>>3;
    uint32_t aoffP = (uint32_t)(moff + (sub&1)*8 + row_l)*80u;
    uint32_t acolb = (uint32_t)((sub>>1)*16);
    uint32_t boffP = (uint32_t)(noff + (sub>>1)*8 + row_l)*80u;
    uint32_t bcolb = (uint32_t)((sub&1)*16);
    uint32_t As0 = smem_u32(&sm.As[0][0][0]);
    uint32_t Bs0 = smem_u32(&sm.Bs[0][0][0]);

    float acc[8][4] = {};
    {
        uint4 rA[2]; uint4 rB;
        ldA16s(g_zb,row0,0,tid,rA); ldB16(g_wihb,Kn,bcol,G4n,0,tid,rB);
        stAB16(&sm,0,tid,rA,rB);
        __syncthreads();
        const int nchunks = Kn/32;
        for (int kt=0; kt<nchunks; kt++){
            int cur = kt&1;
            bool more = (kt+1 < nchunks);
            if (more){ ldA16s(g_zb,row0,kt+1,tid,rA); ldB16(g_wihb,Kn,bcol,G4n,kt+1,tid,rB); }
            comp16L(As0 + cur*(128*80), Bs0 + cur*(64*80),
                    aoffP, acolb, boffP, bcolb, acc);
            if (more) stAB16(&sm,cur^1,tid,rA,rB);
            __syncthreads();
        }
    }
    #pragma unroll
    for (int nt=0; nt<4; nt++){
        #pragma unroll
        for (int c=0;c<2;c++){
            int col = bcol + noff + nt*8 + tg*2 + c;
            float bias = b_ih[col] + b_hh[col];
            #pragma unroll
            for (int mt=0;mt<2;mt++)
                #pragma unroll
                for (int hf=0; hf<2; hf++){
                    int row = row0 + moff + mt*16 + gr + hf*8;
                    g_xproj[(size_t)row*G4n + col] = acc[mt*4+nt][hf*2+c] + bias;
                }
        }
    }
}

// ================= persistent LSTM (single launch, f32x2 dot) =================
__global__ __launch_bounds__(256) void k_lstm_all(const float* __restrict__ w_hh)
{
    extern __shared__ float sm[];
    float* w_s  = sm;
    float* h_s  = sm + 16*512;
    float* pbuf = h_s + 32*516;
    int tid = threadIdx.x, lane = tid & 31, w = tid >> 5;
    int js = blockIdx.x;

    for (int i = tid; i < 16*128; i += 256){
        int r = i >> 7, q = i & 127;
        int grow = (r>>2)*Hn + js*4 + (r&3);
        *(float4*)&w_s[r*512 + q*4] = *(const float4*)&w_hh[(size_t)grow*Hn + q*4];
    }

    int jh = w >> 2;
    int rq = w & 3;
    const ulonglong2* w0p = (const ulonglong2*)(w_s + (rq*4+0)*512 + jh*256);
    const ulonglong2* w1p = (const ulonglong2*)(w_s + (rq*4+1)*512 + jh*256);
    const ulonglong2* w2p = (const ulonglong2*)(w_s + (rq*4+2)*512 + jh*256);
    const ulonglong2* w3p = (const ulonglong2*)(w_s + (rq*4+3)*512 + jh*256);

    float c_reg = 0.f;
    volatile unsigned* vc = &g_ctr;

    for (int t = 0; t < Tn; t++){
        int par = t & 1;
        if (tid == 0 && t > 0){
            unsigned target = (unsigned)t * 128u;
            while (*vc < target) {}
        }
        __syncthreads();

        for (int i = tid; i < 32*128; i += 256){
            int b = i >> 7, q = i & 127;
            float4 hv = __ldcg((const float4*)&g_hbuf[par][b*512 + q*4]);
            *(float4*)&h_s[b*516 + q*4] = hv;
        }
        __syncthreads();

        {
            const ulonglong2* hbp = (const ulonglong2*)(h_s + lane*516 + jh*256);
            ull a00=0,a01=0, a10=0,a11=0, a20=0,a21=0, a30=0,a31=0;
            #pragma unroll 8
            for (int q = 0; q < 64; q++){
                ulonglong2 hv = hbp[q];
                ulonglong2 w0 = w0p[q]; a00=ffma2(w0.x,hv.x,a00); a01=ffma2(w0.y,hv.y,a01);
                ulonglong2 w1 = w1p[q]; a10=ffma2(w1.x,hv.x,a10); a11=ffma2(w1.y,hv.y,a11);
                ulonglong2 w2 = w2p[q]; a20=ffma2(w2.x,hv.x,a20); a21=ffma2(w2.y,hv.y,a21);
                ulonglong2 w3 = w3p[q]; a30=ffma2(w3.x,hv.x,a30); a31=ffma2(w3.y,hv.y,a31);
            }
            float2 u, v2;
            u=unpk(a00); v2=unpk(a01); pbuf[(jh*16 + rq*4+0)*33 + lane] = u.x+u.y+v2.x+v2.y;
            u=unpk(a10); v2=unpk(a11); pbuf[(jh*16 + rq*4+1)*33 + lane] = u.x+u.y+v2.x+v2.y;
            u=unpk(a20); v2=unpk(a21); pbuf[(jh*16 + rq*4+2)*33 + lane] = u.x+u.y+v2.x+v2.y;
            u=unpk(a30); v2=unpk(a31); pbuf[(jh*16 + rq*4+3)*33 + lane] = u.x+u.y+v2.x+v2.y;
        }
        __syncthreads();

        if (tid < 128){
            int b = tid & 31, jj = tid >> 5;
            int j = js*4 + jj;
            float g4[4];
            #pragma unroll
            for (int gate = 0; gate < 4; gate++){
                int r = gate*4 + jj;
                g4[gate] = pbuf[r*33 + b] + pbuf[(16 + r)*33 + b]
                         + g_xproj[(size_t)(b*Tn + t)*G4n + gate*Hn + j];
            }
            float c = c_reg;
            c = sigmf(g4[1])*c + sigmf(g4[0])*tanhf(g4[2]);
            float hv = sigmf(g4[3])*tanhf(c);
            c_reg = c;
            g_hbuf[par^1][b*512 + j] = hv;
            g_hb[(size_t)(b*Tn + t)*Hn + j] = __float2bfloat16(hv);
        }
        __threadfence();
        __syncthreads();
        if (tid == 0) atomicAdd(&g_ctr, 1u);
    }
}

// ================= k_big: cp.async + ldmatrix triple GEMM, 2 CTAs/SM =================
#define A_BYTES 16384
#define B_BYTES 8192
#define BUFSZ   (A_BYTES + B_BYTES)
#define DYN_BIG (2*BUFSZ)

__device__ __forceinline__ void issue_chunk(uint32_t abase, int buf, int tid,
    const __nv_bfloat16* __restrict__ Ag, const __nv_bfloat16* __restrict__ Bg,
    int lda, int local, int row0, int v0)
{
    uint32_t As = abase + buf*BUFSZ;
    uint32_t Bs = As + A_BYTES;
    #pragma unroll
    for (int i=0;i<4;i++){
        int idx = tid + i*256; int r = idx>>3, u = idx&7;
        cp16(As + SWZ128(r*128 + u*16), Ag + (size_t)(row0+r)*lda + local*64 + u*8);
    }
    #pragma unroll
    for (int i=0;i<2;i++){
        int idx = tid + i*256; int r = idx>>3, u = idx&7;
        int v = v0 + r; if (v >= Vn) v = Vn-1;   // clamp; epilogue discards
        cp16(Bs + SWZ128(r*128 + u*16), Bg + (size_t)v*lda + local*64 + u*8);
    }
    CP_COMMIT();
}

// ldmatrix compute for swizzled 128B rows, K=64 chunk.
// Swizzle identity: SWZ128(row*128 + cb) = row*128 + (cb ^ f), f = (row&7)*16,
// valid because cb < 128 occupies only bits 4-6 (no carries).
__device__ __forceinline__ void comp64L(uint32_t As_b, uint32_t Bs_b,
    uint32_t aoff, uint32_t acolb, uint32_t boff, uint32_t bcolb, uint32_t f,
    float (&acc)[8][4])
{
    #pragma unroll
    for (int kk=0; kk<4; kk++){
        uint32_t af0[4], af1[4], b0[4], b1[4];
        uint32_t ac = ((uint32_t)(kk*32) + acolb) ^ f;
        uint32_t bc = ((uint32_t)(kk*32) + bcolb) ^ f;
        ldsm4(af0, As_b + aoff + ac);
        ldsm4(af1, As_b + aoff + 2048u + ac);
        ldsm4(b0,  Bs_b + boff + bc);
        ldsm4(b1,  Bs_b + boff + 2048u + bc);
        mma16(acc[0], af0, b0);
        mma16(acc[1], af0, b0+2);
        mma16(acc[2], af0, b1);
        mma16(acc[3], af0, b1+2);
        mma16(acc[4], af1, b0);
        mma16(acc[5], af1, b0+2);
        mma16(acc[6], af1, b1);
        mma16(acc[7], af1, b1+2);
    }
}

__device__ __forceinline__ void chunk_src(int c, const __nv_bfloat16*& A,
                                          const __nv_bfloat16*& B, int& ld, int& loc)
{
    if (c < 8)      { A=g_hb;  B=g_wpb; ld=Hn;   loc=c;    }
    else if (c < 16){ A=g_ZZb; B=g_W2b; ld=TWOK; loc=c-8;  }
    else            { A=g_zb;  B=g_wgb; ld=Kn;   loc=c-16; }
}

__global__ __launch_bounds__(256,2) void k_big(
    const float* __restrict__ b_prior, const float* __restrict__ b_gen,
    const int* __restrict__ x)
{
    extern __shared__ __align__(128) char dynb[];
    __shared__ float sh_sum[128][3];
    __shared__ float sh_shift[128];
    __shared__ int   sh_xv[128];

    int vt = blockIdx.x, rt = blockIdx.y;
    int row0 = rt*128, v0 = vt*64;
    int tid = threadIdx.x;
    uint32_t abase = smem_u32(dynb);

    if (tid < 128){
        sh_shift[tid] = g_cst[0] - 0.5f*g_sumz2[row0+tid];
        sh_xv[tid]    = x[row0+tid];
        sh_sum[tid][0]=0.f; sh_sum[tid][1]=0.f; sh_sum[tid][2]=0.f;
    }

    int lane = tid&31, wid = tid>>5;
    int moff = (wid>>1)*32, noff = (wid&1)*32;
    int row_l = lane&7, sub = lane>>3;
    uint32_t f     = (uint32_t)(row_l*16);
    uint32_t aoff  = (uint32_t)(moff + (sub&1)*8 + row_l)*128u;
    uint32_t acolb = (uint32_t)((sub>>1)*16);
    uint32_t boff  = (uint32_t)(noff + (sub>>1)*8 + row_l)*128u;
    uint32_t bcolb = (uint32_t)((sub&1)*16);

    float accA[8][4] = {};      // phase P, then reused for phase G
    float accB[8][4] = {};      // phase M
    float rs1[4] = {}, rs2[4] = {}, rs3[4] = {};

    {
        const __nv_bfloat16 *Ag, *Bg; int lda, loc;
        chunk_src(0, Ag, Bg, lda, loc);
        issue_chunk(abase, 0, tid, Ag, Bg, lda, loc, row0, v0);
    }

    // phases P (0..7) and M (8..15)
    #pragma unroll 1
    for (int c = 0; c < 16; c++){
        cp_wait<0>();
        __syncthreads();
        {
            const __nv_bfloat16 *Ag, *Bg; int lda, loc;
            chunk_src(c+1, Ag, Bg, lda, loc);
            issue_chunk(abase, (c+1)&1, tid, Ag, Bg, lda, loc, row0, v0);
        }
        uint32_t As_b = abase + (c&1)*BUFSZ;
        uint32_t Bs_b = As_b + A_BYTES;
        if (c < 8) comp64L(As_b, Bs_b, aoff, acolb, boff, bcolb, f, accA);
        else       comp64L(As_b, Bs_b, aoff, acolb, boff, bcolb, f, accB);
    }

    // epilogue PM: exp(s1), exp(s2) — frees accA for phase G
    #pragma unroll
    for (int nt=0; nt<4; nt++){
        #pragma unroll
        for (int cc=0;cc<2;cc++){
            int n = noff + nt*8 + (lane&3)*2 + cc;
            int v = v0 + n;
            bool ok = v < Vn;
            int vc = ok ? v : (Vn-1);
            float bp = __ldg(&b_prior[vc]);
            float cv = g_cst[vc];
            #pragma unroll
            for (int mt=0;mt<2;mt++){
                #pragma unroll
                for (int hf=0; hf<2; hf++){
                    int rloc = moff + mt*16 + (lane>>2) + hf*8;
                    int ai = hf*2 + cc;
                    float s1 = accA[mt*4+nt][ai] + bp;
                    float s2 = s1 + cv + accB[mt*4+nt][ai] - sh_shift[rloc];
                    if (ok){
                        rs1[mt*2+hf] += __expf(s1);
                        rs2[mt*2+hf] += __expf(s2);
                    }
                }
            }
        }
    }
    #pragma unroll
    for (int i=0;i<8;i++)
        #pragma unroll
        for (int j=0;j<4;j++) accA[i][j] = 0.f;

    // phase G (16..19); chunk 16 already in flight
    #pragma unroll 1
    for (int c = 16; c < 20; c++){
        cp_wait<0>();
        __syncthreads();
        if (c+1 < 20){
            const __nv_bfloat16 *Ag, *Bg; int lda, loc;
            chunk_src(c+1, Ag, Bg, lda, loc);
            issue_chunk(abase, (c+1)&1, tid, Ag, Bg, lda, loc, row0, v0);
        }
        uint32_t As_b = abase + (c&1)*BUFSZ;
        uint32_t Bs_b = As_b + A_BYTES;
        comp64L(As_b, Bs_b, aoff, acolb, boff, bcolb, f, accA);
    }

    // epilogue G: exp(s3) + target logit
    #pragma unroll
    for (int nt=0; nt<4; nt++){
        #pragma unroll
        for (int cc=0;cc<2;cc++){
            int n = noff + nt*8 + (lane&3)*2 + cc;
            int v = v0 + n;
            bool ok = v < Vn;
            int vc = ok ? v : (Vn-1);
            float bg = __ldg(&b_gen[vc]);
            #pragma unroll
            for (int mt=0;mt<2;mt++){
                #pragma unroll
                for (int hf=0; hf<2; hf++){
                    int rloc = moff + mt*16 + (lane>>2) + hf*8;
                    int ai = hf*2 + cc;
                    float s3 = accA[mt*4+nt][ai] + bg;
                    if (ok){
                        rs3[mt*2+hf] += __expf(s3);
                        if (v == sh_xv[rloc]) g_tgt[row0 + rloc] = s3;
                    }
                }
            }
        }
    }

    // reduce across the 4 k-threads sharing each row
    #pragma unroll
    for (int lr=0; lr<4; lr++){
        float v0s = rs1[lr], v1s = rs2[lr], v2s = rs3[lr];
        v0s += __shfl_xor_sync(0xffffffffu, v0s, 1);
        v0s += __shfl_xor_sync(0xffffffffu, v0s, 2);
        v1s += __shfl_xor_sync(0xffffffffu, v1s, 1);
        v1s += __shfl_xor_sync(0xffffffffu, v1s, 2);
        v2s += __shfl_xor_sync(0xffffffffu, v2s, 1);
        v2s += __shfl_xor_sync(0xffffffffu, v2s, 2);
        if ((lane&3)==0){
            int mt = lr>>1, hf = lr&1;
            int rloc = moff + mt*16 + (lane>>2) + hf*8;
            atomicAdd(&sh_sum[rloc][0], v0s);
            atomicAdd(&sh_sum[rloc][1], v1s);
            atomicAdd(&sh_sum[rloc][2], v2s);
        }
    }
    __syncthreads();
    if (tid < 128){
        g_part[(0*NVT + vt)*BT + row0 + tid] = sh_sum[tid][0];
        g_part[(1*NVT + vt)*BT + row0 + tid] = sh_sum[tid][1];
        g_part[(2*NVT + vt)*BT + row0 + tid] = sh_sum[tid][2];
    }
}

// ---------------- per-row LSE finish ----------------
__global__ void k_lse(const int* __restrict__ x_sl)
{
    int row = blockIdx.x*256 + threadIdx.x;
    if (row >= BT) return;
    float S1=0.f, S2=0.f, S3=0.f;
    for (int vt = 0; vt < NVT; vt++){
        S1 += g_part[(0*NVT+vt)*BT + row];
        S2 += g_part[(1*NVT+vt)*BT + row];
        S3 += g_part[(2*NVT+vt)*BT + row];
    }
    int b = row / Tn, t = row % Tn;
    float shift = g_cst[0] - 0.5f*g_sumz2[row];
    float lse_p = logf(S1);
    float lse_m = shift + logf(S2);
    float lse_g = logf(S3);
    float mask = (t < x_sl[b]) ? 1.f : 0.f;
    g_contrib[row] = mask * (g_tgt[row] - lse_g - g_qzlp[row] + (lse_m - lse_p));
}

// ---------------- final scalar ----------------
__global__ void k_final(const int* __restrict__ x_sl, float* __restrict__ out)
{
    __shared__ float red[256];
    int tid = threadIdx.x;
    float s = 0.f;
    for (int i = tid; i < BT; i += 256) s += g_contrib[i];
    red[tid] = s; __syncthreads();
    for (int st = 128; st > 0; st >>= 1){
        if (tid < st) red[tid] += red[tid+st];
        __syncthreads();
    }
    if (tid == 0){
        int tot = 0;
        for (int b = 0; b < Bn; b++) tot += x_sl[b];
        out[0] = -red[0] / (float)tot;
    }
}

// ---------------- launch ----------------
extern "C" void kernel_launch(void* const* d_in, const int* in_sizes, int n_in,
                              void* d_out, int out_size)
{
    const int*   x       = (const int*)  d_in[0];
    const int*   x_sl    = (const int*)  d_in[1];
    const float* eps     = (const float*)d_in[2];
    const float* emb     = (const float*)d_in[3];
    const float* w_ih    = (const float*)d_in[4];
    const float* w_hh    = (const float*)d_in[5];
    const float* b_ih    = (const float*)d_in[6];
    const float* b_hh    = (const float*)d_in[7];
    const float* w_prior = (const float*)d_in[8];
    const float* b_prior = (const float*)d_in[9];
    const float* w_gen   = (const float*)d_in[10];
    const float* b_gen   = (const float*)d_in[11];
    float* out = (float*)d_out;

    int smem_lstm = (16*512 + 32*516 + 2*16*33)*(int)sizeof(float); // ~103 KB
    cudaFuncSetAttribute(k_lstm_all, cudaFuncAttributeMaxDynamicSharedMemorySize, smem_lstm);
    cudaFuncSetAttribute(k_big,      cudaFuncAttributeMaxDynamicSharedMemorySize, DYN_BIG);

    k_prep<<<Vn, 256>>>(x, x_sl, eps, emb, w_ih, w_prior, w_gen);  // 1
    k_xproj16<<<dim3(G4n/64, BT/128), 256>>>(b_ih, b_hh);          // 2
    k_lstm_all<<<128, 256, smem_lstm>>>(w_hh);                     // 3
    k_big<<<dim3(NVT, BT/128), 256, DYN_BIG>>>(b_prior, b_gen, x); // 4  <- ncu target
    k_lse<<<BT/256, 256>>>(x_sl);                                  // 5
    k_final<<<1, 256>>>(x_sl, out);                                // 6
}

// round 13
// speedup vs baseline: 10.4052x; 1.0900x over previous
#include <cuda_runtime.h>
#include <cuda_bf16.h>
#include <cstdint>

#define Bn 32
#define Tn 128
#define Kn 256
#define Hn 512
#define Vn 10000
#define BT (Bn*Tn)
#define G4n (4*Hn)
#define TWOK (2*Kn)
#define NVT 157              // ceil(Vn/64)

#define HALF_LOG_2PI 0.918938533204672741780329736406f

typedef unsigned long long ull;

// ---------------- static scratch ----------------
__device__ __align__(16) __nv_bfloat16 g_zb[BT*Kn];      // 2 MB
__device__ __align__(16) __nv_bfloat16 g_ZZb[BT*TWOK];   // 4 MB [z | z^2]
__device__ __align__(16) __nv_bfloat16 g_hb[BT*Hn];      // 4 MB
__device__ __align__(16) __nv_bfloat16 g_W2b[Vn*TWOK];   // 10 MB
__device__ __align__(16) __nv_bfloat16 g_wpb[Vn*Hn];     // 10 MB
__device__ __align__(16) __nv_bfloat16 g_wgb[Vn*Kn];     // 5 MB
__device__ __align__(16) __nv_bfloat16 g_wihb[G4n*Kn];   // 1 MB
__device__ __align__(16) float g_xproj[BT*G4n];          // 32 MB, layout [(js*128+t)*32+b][16r]
__device__ float g_cst[Vn];
__device__ float g_qzlp[BT];
__device__ float g_sumz2[BT];
__device__ float g_tgt[BT];
__device__ float g_part[3*NVT*BT];
__device__ float g_contrib[BT];
__device__ __align__(16) float g_hbuf[2][Bn*Hn];
__device__ unsigned g_ctr;

__device__ __forceinline__ float softplus_b(float x){
    return (x > 20.f) ? x : log2f(1.f + exp2f(x));
}
__device__ __forceinline__ float sigmf(float x){ return 1.f/(1.f+expf(-x)); }

__device__ __forceinline__ ull ffma2(ull a, ull b, ull c){
    ull d;
    asm("fma.rn.f32x2 %0, %1, %2, %3;" : "=l"(d) : "l"(a), "l"(b), "l"(c));
    return d;
}
__device__ __forceinline__ float2 unpk(ull v){
    float lo, hi;
    asm("mov.b64 {%0, %1}, %2;" : "=f"(lo), "=f"(hi) : "l"(v));
    return make_float2(lo, hi);
}

// ---------------- cp.async / ldmatrix helpers ----------------
__device__ __forceinline__ uint32_t smem_u32(const void* p){
    uint32_t a;
    asm("{ .reg .u64 t; cvta.to.shared.u64 t, %1; cvt.u32.u64 %0, t; }" : "=r"(a) : "l"(p));
    return a;
}
__device__ __forceinline__ void cp16(uint32_t dst, const void* src){
    asm volatile("cp.async.cg.shared.global [%0], [%1], 16;" :: "r"(dst), "l"(src) : "memory");
}
#define CP_COMMIT() asm volatile("cp.async.commit_group;" ::: "memory")
template<int N> __device__ __forceinline__ void cp_wait(){
    asm volatile("cp.async.wait_group %0;" :: "n"(N) : "memory");
}
#define SWZ128(o) ((o) ^ (((o) >> 3) & 0x70))

__device__ __forceinline__ void ldsm4(uint32_t* r, uint32_t addr){
    asm volatile("ldmatrix.sync.aligned.m8n8.x4.shared.b16 {%0,%1,%2,%3}, [%4];"
        : "=r"(r[0]),"=r"(r[1]),"=r"(r[2]),"=r"(r[3]) : "r"(addr));
}

// ================= prep z: z, z^2, q_z_lp, sum z^2, hbuf/ctr init =================
__global__ void k_prep_z(const int* __restrict__ x, const int* __restrict__ x_sl,
                         const float* __restrict__ eps, const float* __restrict__ emb)
{
    int row = blockIdx.x;
    int k   = threadIdx.x;
    int lin = row*256 + k;
    if (lin < Bn*Hn) g_hbuf[0][lin] = 0.f;
    if (lin == 0) g_ctr = 0u;
    int b = row / Tn, t = row % Tn;
    int xv = x[row];
    float mask = (t < x_sl[b]) ? 1.f : 0.f;
    float mu = emb[xv*TWOK + k];
    float sq = softplus_b(emb[xv*TWOK + Kn + k]);
    float e  = eps[row*Kn + k];
    float zv = (mu + sq*e) * mask;
    g_zb[row*Kn + k]         = __float2bfloat16(zv);
    g_ZZb[row*TWOK + k]      = __float2bfloat16(zv);
    g_ZZb[row*TWOK + Kn + k] = __float2bfloat16(zv*zv);
    float q = -HALF_LOG_2PI - logf(sq) - 0.5f*e*e;
    __shared__ float r1[256], r2[256];
    r1[k] = q; r2[k] = zv*zv;
    __syncthreads();
    for (int s = 128; s > 0; s >>= 1){
        if (k < s){ r1[k] += r1[k+s]; r2[k] += r2[k+s]; }
        __syncthreads();
    }
    if (k == 0){ g_qzlp[row] = r1[0]; g_sumz2[row] = r2[0]; }
}

// ================= prep v: W2b, wpb, wgb, wihb converts + cst =================
__global__ void k_prep_v(const float* __restrict__ emb, const float* __restrict__ w_ih,
                         const float* __restrict__ w_prior, const float* __restrict__ w_gen)
{
    int v = blockIdx.x;
    int k = threadIdx.x;
    __shared__ float red[256];
    float mu = emb[v*TWOK + k];
    float sp = softplus_b(emb[v*TWOK + Kn + k]);
    float inv2 = 0.5f/(sp*sp);
    g_W2b[v*TWOK + k]      = __float2bfloat16(2.f*inv2*mu);
    g_W2b[v*TWOK + Kn + k] = __float2bfloat16(-inv2);
    g_wpb[v*Hn + k]       = __float2bfloat16(w_prior[(size_t)v*Hn + k]);
    g_wpb[v*Hn + 256 + k] = __float2bfloat16(w_prior[(size_t)v*Hn + 256 + k]);
    g_wgb[v*Kn + k]       = __float2bfloat16(w_gen[(size_t)v*Kn + k]);
    {
        int idx = v*256 + k;
        if (idx < G4n*Kn) g_wihb[idx] = __float2bfloat16(w_ih[idx]);
    }
    float c = -HALF_LOG_2PI - logf(sp) - mu*mu*inv2;
    red[k] = c;
    __syncthreads();
    for (int s = 128; s > 0; s >>= 1){
        if (k < s) red[k] += red[k+s];
        __syncthreads();
    }
    if (k == 0) g_cst[v] = red[0];
}

// ================= legacy bf16 mma (m16n8k16) =================
__device__ __forceinline__ void mma16(float* d, const uint32_t* a, const uint32_t* b){
    asm volatile("mma.sync.aligned.m16n8k16.row.col.f32.bf16.bf16.f32 "
        "{%0,%1,%2,%3}, {%4,%5,%6,%7}, {%8,%9}, {%0,%1,%2,%3};"
        : "+f"(d[0]),"+f"(d[1]),"+f"(d[2]),"+f"(d[3])
        : "r"(a[0]),"r"(a[1]),"r"(a[2]),"r"(a[3]), "r"(b[0]),"r"(b[1]));
}

// ---------------- x_proj GEMM (ldmatrix + padded smem, K=32 chunks) ----------------
struct __align__(16) SmemTC {
    __nv_bfloat16 As[2][128][40];
    __nv_bfloat16 Bs[2][64][40];
};
__device__ __forceinline__ void ldA16s(const __nv_bfloat16* __restrict__ zb,
                                       int row0, int kt, int tid, uint4 (&rA)[2]){
    #pragma unroll
    for (int i=0;i<2;i++){
        int idx = tid + i*256;
        int row = idx>>2, q = idx&3;
        int grow = row0 + row;
        rA[i] = make_uint4(0u,0u,0u,0u);
        if ((grow & (Tn-1)) != 0)
            rA[i] = *(const uint4*)(zb + (size_t)(grow-1)*Kn + kt*32 + q*8);
    }
}
__device__ __forceinline__ void ldB16(const __nv_bfloat16* __restrict__ Bg, int ldb,
                                      int v0, int nmax, int kt, int tid, uint4& rB){
    int row = tid>>2, q = tid&3;
    int v = v0 + row; if (v >= nmax) v = nmax-1;
    rB = *(const uint4*)(Bg + (size_t)v*ldb + kt*32 + q*8);
}
__device__ __forceinline__ void stAB16(SmemTC* sm, int buf, int tid,
                                       const uint4 (&rA)[2], const uint4& rB){
    #pragma unroll
    for (int i=0;i<2;i++){
        int idx = tid + i*256; int row = idx>>2, q = idx&3;
        *(uint4*)&sm->As[buf][row][q*8] = rA[i];
    }
    { int row = tid>>2, q = tid&3;
      *(uint4*)&sm->Bs[buf][row][q*8] = rB; }
}
__device__ __forceinline__ void comp16L(uint32_t As_b, uint32_t Bs_b,
    uint32_t aoffP, uint32_t acolb, uint32_t boffP, uint32_t bcolb,
    float (&acc)[8][4])
{
    #pragma unroll
    for (int kk=0; kk<2; kk++){
        uint32_t af0[4], af1[4], b0[4], b1[4];
        uint32_t ac = kk*32 + acolb;
        uint32_t bc = kk*32 + bcolb;
        ldsm4(af0, As_b + aoffP + ac);
        ldsm4(af1, As_b + aoffP + 16*80 + ac);
        ldsm4(b0,  Bs_b + boffP + bc);
        ldsm4(b1,  Bs_b + boffP + 16*80 + bc);
        mma16(acc[0], af0, b0);
        mma16(acc[1], af0, b0+2);
        mma16(acc[2], af0, b1);
        mma16(acc[3], af0, b1+2);
        mma16(acc[4], af1, b0);
        mma16(acc[5], af1, b0+2);
        mma16(acc[6], af1, b1);
        mme_dummy:;
        mma16(acc[7], af1, b1+2);
    }
}

__global__ __launch_bounds__(256) void k_xproj16(const float* __restrict__ b_ih,
                                                 const float* __restrict__ b_hh)
{
    __shared__ SmemTC sm;
    int bcol = blockIdx.x * 64;
    int row0 = blockIdx.y * 128;
    int tid = threadIdx.x;
    int lane = tid&31, wid = tid>>5;
    int moff = (wid>>1)*32, noff = (wid&1)*32;
    int gr = lane>>2, tg = lane&3;
    int row_l = lane&7, sub = lane>>3;
    uint32_t aoffP = (uint32_t)(moff + (sub&1)*8 + row_l)*80u;
    uint32_t acolb = (uint32_t)((sub>>1)*16);
    uint32_t boffP = (uint32_t)(noff + (sub>>1)*8 + row_l)*80u;
    uint32_t bcolb = (uint32_t)((sub&1)*16);
    uint32_t As0 = smem_u32(&sm.As[0][0][0]);
    uint32_t Bs0 = smem_u32(&sm.Bs[0][0][0]);

    float acc[8][4] = {};
    {
        uint4 rA[2]; uint4 rB;
        ldA16s(g_zb,row0,0,tid,rA); ldB16(g_wihb,Kn,bcol,G4n,0,tid,rB);
        stAB16(&sm,0,tid,rA,rB);
        __syncthreads();
        const int nchunks = Kn/32;
        for (int kt=0; kt<nchunks; kt++){
            int cur = kt&1;
            bool more = (kt+1 < nchunks);
            if (more){ ldA16s(g_zb,row0,kt+1,tid,rA); ldB16(g_wihb,Kn,bcol,G4n,kt+1,tid,rB); }
            comp16L(As0 + cur*(128*80), Bs0 + cur*(64*80),
                    aoffP, acolb, boffP, bcolb, acc);
            if (more) stAB16(&sm,cur^1,tid,rA,rB);
            __syncthreads();
        }
    }
    // epilogue: store in LSTM-friendly layout [(js*128+t)*32+b][16r]
    #pragma unroll
    for (int nt=0; nt<4; nt++){
        #pragma unroll
        for (int c=0;c<2;c++){
            int col = bcol + noff + nt*8 + tg*2 + c;   // gate-col 0..2047
            float bias = b_ih[col] + b_hh[col];
            int gate = col >> 9;
            int jc   = col & 511;
            int js   = jc >> 2, jj = jc & 3;
            int r    = gate*4 + jj;
            #pragma unroll
            for (int mt=0;mt<2;mt++)
                #pragma unroll
                for (int hf=0; hf<2; hf++){
                    int row = row0 + moff + mt*16 + gr + hf*8;  // b*Tn + t
                    int b = row >> 7, tt = row & 127;
                    size_t addr = ((size_t)(js*Tn + tt)*32 + b)*16 + r;
                    g_xproj[addr] = acc[mt*4+nt][hf*2+c] + bias;
                }
        }
    }
}

// ================= persistent LSTM v2: 16x h-reuse + xproj prefetch =================
// CTA js: 16 gate-rows (4 gates x 4 j), all 32 batches. Warp w = K-eighth,
// owns ALL 16 rows (16 packed-f32x2 accumulators). pbuf[16][8][33].
#define LSTM_WS   (16*512)
#define LSTM_HS   (32*516)
#define LSTM_PB   (16*8*33)
#define LSTM_XP   (2*512)
#define LSTM_SMEM ((LSTM_WS + LSTM_HS + LSTM_PB + LSTM_XP)*(int)sizeof(float))

__global__ __launch_bounds__(256) void k_lstm_all(const float* __restrict__ w_hh)
{
    extern __shared__ float sm[];
    float* w_s  = sm;                       // [16][512]
    float* h_s  = sm + LSTM_WS;             // [32][516]
    float* pbuf = h_s + LSTM_HS;            // [16][8][33]
    float* xp_s = pbuf + LSTM_PB;           // [2][512]
    int tid = threadIdx.x, lane = tid & 31, w = tid >> 5;
    int js = blockIdx.x;

    // cache w_hh slice (once): local row r -> global row (r>>2)*Hn + js*4 + (r&3)
    for (int i = tid; i < 16*128; i += 256){
        int r = i >> 7, q = i & 127;
        int grow = (r>>2)*Hn + js*4 + (r&3);
        *(float4*)&w_s[r*512 + q*4] = *(const float4*)&w_hh[(size_t)grow*Hn + q*4];
    }

    uint32_t xp_base = smem_u32(xp_s);
    // prefetch xproj for t=0 into buf 0
    if (tid < 128)
        cp16(xp_base + tid*16, g_xproj + (size_t)(js*Tn + 0)*512 + tid*4);
    CP_COMMIT();

    int kq = w;                              // K-eighth
    const float* wbase = w_s + kq*64;
    float c_reg = 0.f;                       // thread (b=tid&31, jj=tid>>5), tid<128
    volatile unsigned* vc = &g_ctr;

    for (int t = 0; t < Tn; t++){
        int par = t & 1;
        if (tid == 0 && t > 0){
            unsigned target = (unsigned)t * 128u;
            while (*vc < target) {}
        }
        __syncthreads();

        // stage h(t-1)
        for (int i = tid; i < 32*128; i += 256){
            int b = i >> 7, q = i & 127;
            float4 hv = __ldcg((const float4*)&g_hbuf[par][b*512 + q*4]);
            *(float4*)&h_s[b*516 + q*4] = hv;
        }
        // prefetch xproj for t+1
        if (t+1 < Tn && tid < 128)
            cp16(xp_base + ((t+1)&1)*2048 + tid*16,
                 g_xproj + (size_t)(js*Tn + (t+1))*512 + tid*4);
        CP_COMMIT();
        __syncthreads();

        // dot: warp kq covers K [kq*64, kq*64+64), all 16 rows
        {
            const ulonglong2* hb = (const ulonglong2*)(h_s + lane*516 + kq*64);
            ull acc[16];
            #pragma unroll
            for (int r=0;r<16;r++) acc[r] = 0ull;
            #pragma unroll
            for (int q = 0; q < 16; q++){
                ulonglong2 hv = hb[q];
                #pragma unroll
                for (int r = 0; r < 16; r++){
                    ulonglong2 wv = *(const ulonglong2*)(wbase + r*512 + q*4);
                    acc[r] = ffma2(wv.x, hv.x, acc[r]);
                    acc[r] = ffma2(wv.y, hv.y, acc[r]);
                }
            }
            #pragma unroll
            for (int r = 0; r < 16; r++){
                float2 u = unpk(acc[r]);
                pbuf[(r*8 + kq)*33 + lane] = u.x + u.y;
            }
        }
        cp_wait<1>();        // xp(t) resident (newest group = t+1 may stay in flight)
        __syncthreads();

        // activation
        if (tid < 128){
            int b = tid & 31, jj = tid >> 5;
            int j = js*4 + jj;
            const float* xp = xp_s + (t&1)*512 + b*16;
            float g4[4];
            #pragma unroll
            for (int gate = 0; gate < 4; gate++){
                int r = gate*4 + jj;
                float s = xp[r];
                #pragma unroll
                for (int e = 0; e < 8; e++) s += pbuf[(r*8 + e)*33 + b];
                g4[gate] = s;
            }
            float c = c_reg;
            c = sigmf(g4[1])*c + sigmf(g4[0])*tanhf(g4[2]);
            float hv = sigmf(g4[3])*tanhf(c);
            c_reg = c;
            g_hbuf[par^1][b*512 + j] = hv;
            g_hb[(size_t)(b*Tn + t)*Hn + j] = __float2bfloat16(hv);
        }
        __threadfence();
        __syncthreads();
        if (tid == 0) atomicAdd(&g_ctr, 1u);
    }
}

// ================= k_big: cp.async + ldmatrix triple GEMM, 2 CTAs/SM =================
#define A_BYTES 16384
#define B_BYTES 8192
#define BUFSZ   (A_BYTES + B_BYTES)
#define DYN_BIG (2*BUFSZ)

__device__ __forceinline__ void issue_chunk(uint32_t abase, int buf, int tid,
    const __nv_bfloat16* __restrict__ Ag, const __nv_bfloat16* __restrict__ Bg,
    int lda, int local, int row0, int v0)
{
    uint32_t As = abase + buf*BUFSZ;
    uint32_t Bs = As + A_BYTES;
    #pragma unroll
    for (int i=0;i<4;i++){
        int idx = tid + i*256; int r = idx>>3, u = idx&7;
        cp16(As + SWZ128(r*128 + u*16), Ag + (size_t)(row0+r)*lda + local*64 + u*8);
    }
    #pragma unroll
    for (int i=0;i<2;i++){
        int idx = tid + i*256; int r = idx>>3, u = idx&7;
        int v = v0 + r; if (v >= Vn) v = Vn-1;   // clamp; epilogue discards
        cp16(Bs + SWZ128(r*128 + u*16), Bg + (size_t)v*lda + local*64 + u*8);
    }
    CP_COMMIT();
}

__device__ __forceinline__ void comp64L(uint32_t As_b, uint32_t Bs_b,
    uint32_t aoff, uint32_t acolb, uint32_t boff, uint32_t bcolb, uint32_t f,
    float (&acc)[8][4])
{
    #pragma unroll
    for (int kk=0; kk<4; kk++){
        uint32_t af0[4], af1[4], b0[4], b1[4];
        uint32_t ac = ((uint32_t)(kk*32) + acolb) ^ f;
        uint32_t bc = ((uint32_t)(kk*32) + bcolb) ^ f;
        ldsm4(af0, As_b + aoff + ac);
        ldsm4(af1, As_b + aoff + 2048u + ac);
        ldsm4(b0,  Bs_b + boff + bc);
        ldsm4(b1,  Bs_b + boff + 2048u + bc);
        mma16(acc[0], af0, b0);
        mma16(acc[1], af0, b0+2);
        mma16(acc[2], af0, b1);
        mma16(acc[3], af0, b1+2);
        mma16(acc[4], af1, b0);
        mma16(acc[5], af1, b0+2);
        mma16(acc[6], af1, b1);
        mma16(acc[7], af1, b1+2);
    }
}

__device__ __forceinline__ void chunk_src(int c, const __nv_bfloat16*& A,
                                          const __nv_bfloat16*& B, int& ld, int& loc)
{
    if (c < 8)      { A=g_hb;  B=g_wpb; ld=Hn;   loc=c;    }
    else if (c < 16){ A=g_ZZb; B=g_W2b; ld=TWOK; loc=c-8;  }
    else            { A=g_zb;  B=g_wgb; ld=Kn;   loc=c-16; }
}

__global__ __launch_bounds__(256,2) void k_big(
    const float* __restrict__ b_prior, const float* __restrict__ b_gen,
    const int* __restrict__ x)
{
    extern __shared__ __align__(128) char dynb[];
    __shared__ float sh_sum[128][3];
    __shared__ float sh_shift[128];
    __shared__ int   sh_xv[128];

    int vt = blockIdx.x, rt = blockIdx.y;
    int row0 = rt*128, v0 = vt*64;
    int tid = threadIdx.x;
    uint32_t abase = smem_u32(dynb);

    if (tid < 128){
        sh_shift[tid] = g_cst[0] - 0.5f*g_sumz2[row0+tid];
        sh_xv[tid]    = x[row0+tid];
        sh_sum[tid][0]=0.f; sh_sum[tid][1]=0.f; sh_sum[tid][2]=0.f;
    }

    int lane = tid&31, wid = tid>>5;
    int moff = (wid>>1)*32, noff = (wid&1)*32;
    int row_l = lane&7, sub = lane>>3;
    uint32_t f     = (uint32_t)(row_l*16);
    uint32_t aoff  = (uint32_t)(moff + (sub&1)*8 + row_l)*128u;
    uint32_t acolb = (uint32_t)((sub>>1)*16);
    uint32_t boff  = (uint32_t)(noff + (sub>>1)*8 + row_l)*128u;
    uint32_t bcolb = (uint32_t)((sub&1)*16);

    float accA[8][4] = {};      // phase P, then reused for phase G
    float accB[8][4] = {};      // phase M
    float rs1[4] = {}, rs2[4] = {}, rs3[4] = {};

    {
        const __nv_bfloat16 *Ag, *Bg; int lda, loc;
        chunk_src(0, Ag, Bg, lda, loc);
        issue_chunk(abase, 0, tid, Ag, Bg, lda, loc, row0, v0);
    }

    #pragma unroll 1
    for (int c = 0; c < 16; c++){
        cp_wait<0>();
        __syncthreads();
        {
            const __nv_bfloat16 *Ag, *Bg; int lda, loc;
            chunk_src(c+1, Ag, Bg, lda, loc);
            issue_chunk(abase, (c+1)&1, tid, Ag, Bg, lda, loc, row0, v0);
        }
        uint32_t As_b = abase + (c&1)*BUFSZ;
        uint32_t Bs_b = As_b + A_BYTES;
        if (c < 8) comp64L(As_b, Bs_b, aoff, acolb, boff, bcolb, f, accA);
        else       comp64L(As_b, Bs_b, aoff, acolb, boff, bcolb, f, accB);
    }

    // epilogue PM: exp(s1), exp(s2) — frees accA for phase G
    #pragma unroll
    for (int nt=0; nt<4; nt++){
        #pragma unroll
        for (int cc=0;cc<2;cc++){
            int n = noff + nt*8 + (lane&3)*2 + cc;
            int v = v0 + n;
            bool ok = v < Vn;
            int vc = ok ? v : (Vn-1);
            float bp = __ldg(&b_prior[vc]);
            float cv = g_cst[vc];
            #pragma unroll
            for (int mt=0;mt<2;mt++){
                #pragma unroll
                for (int hf=0; hf<2; hf++){
                    int rloc = moff + mt*16 + (lane>>2) + hf*8;
                    int ai = hf*2 + cc;
                    float s1 = accA[mt*4+nt][ai] + bp;
                    float s2 = s1 + cv + accB[mt*4+nt][ai] - sh_shift[rloc];
                    if (ok){
                        rs1[mt*2+hf] += __expf(s1);
                        rs2[mt*2+hf] += __expf(s2);
                    }
                }
            }
        }
    }
    #pragma unroll
    for (int i=0;i<8;i++)
        #pragma unroll
        for (int j=0;j<4;j++) accA[i][j] = 0.f;

    // phase G (16..19)
    #pragma unroll 1
    for (int c = 16; c < 20; c++){
        cp_wait<0>();
        __syncthreads();
        if (c+1 < 20){
            const __nv_bfloat16 *Ag, *Bg; int lda, loc;
            chunk_src(c+1, Ag, Bg, lda, loc);
            issue_chunk(abase, (c+1)&1, tid, Ag, Bg, lda, loc, row0, v0);
        }
        uint32_t As_b = abase + (c&1)*BUFSZ;
        uint32_t Bs_b = As_b + A_BYTES;
        comp64L(As_b, Bs_b, aoff, acolb, boff, bcolb, f, accA);
    }

    // epilogue G
    #pragma unroll
    for (int nt=0; nt<4; nt++){
        #pragma unroll
        for (int cc=0;cc<2;cc++){
            int n = noff + nt*8 + (lane&3)*2 + cc;
            int v = v0 + n;
            bool ok = v < Vn;
            int vc = ok ? v : (Vn-1);
            float bg = __ldg(&b_gen[vc]);
            #pragma unroll
            for (int mt=0;mt<2;mt++){
                #pragma unroll
                for (int hf=0; hf<2; hf++){
                    int rloc = moff + mt*16 + (lane>>2) + hf*8;
                    int ai = hf*2 + cc;
                    float s3 = accA[mt*4+nt][ai] + bg;
                    if (ok){
                        rs3[mt*2+hf] += __expf(s3);
                        if (v == sh_xv[rloc]) g_tgt[row0 + rloc] = s3;
                    }
                }
            }
        }
    }

    #pragma unroll
    for (int lr=0; lr<4; lr++){
        float v0s = rs1[lr], v1s = rs2[lr], v2s = rs3[lr];
        v0s += __shfl_xor_sync(0xffffffffu, v0s, 1);
        v0s += __shfl_xor_sync(0xffffffffu, v0s, 2);
        v1s += __shfl_xor_sync(0xffffffffu, v1s, 1);
        v1s += __shfl_xor_sync(0xffffffffu, v1s, 2);
        v2s += __shfl_xor_sync(0xffffffffu, v2s, 1);
        v2s += __shfl_xor_sync(0xffffffffu, v2s, 2);
        if ((lane&3)==0){
            int mt = lr>>1, hf = lr&1;
            int rloc = moff + mt*16 + (lane>>2) + hf*8;
            atomicAdd(&sh_sum[rloc][0], v0s);
            atomicAdd(&sh_sum[rloc][1], v1s);
            atomicAdd(&sh_sum[rloc][2], v2s);
        }
    }
    __syncthreads();
    if (tid < 128){
        g_part[(0*NVT + vt)*BT + row0 + tid] = sh_sum[tid][0];
        g_part[(1*NVT + vt)*BT + row0 + tid] = sh_sum[tid][1];
        g_part[(2*NVT + vt)*BT + row0 + tid] = sh_sum[tid][2];
    }
}

// ---------------- per-row LSE finish ----------------
__global__ void k_lse(const int* __restrict__ x_sl)
{
    int row = blockIdx.x*256 + threadIdx.x;
    if (row >= BT) return;
    float S1=0.f, S2=0.f, S3=0.f;
    for (int vt = 0; vt < NVT; vt++){
        S1 += g_part[(0*NVT+vt)*BT + row];
        S2 += g_part[(1*NVT+vt)*BT + row];
        S3 += g_part[(2*NVT+vt)*BT + row];
    }
    int b = row / Tn, t = row % Tn;
    float shift = g_cst[0] - 0.5f*g_sumz2[row];
    float lse_p = logf(S1);
    float lse_m = shift + logf(S2);
    float lse_g = logf(S3);
    float mask = (t < x_sl[b]) ? 1.f : 0.f;
    g_contrib[row] = mask * (g_tgt[row] - lse_g - g_qzlp[row] + (lse_m - lse_p));
}

// ---------------- final scalar ----------------
__global__ void k_final(const int* __restrict__ x_sl, float* __restrict__ out)
{
    __shared__ float red[256];
    int tid = threadIdx.x;
    float s = 0.f;
    for (int i = tid; i < BT; i += 256) s += g_contrib[i];
    red[tid] = s; __syncthreads();
    for (int st = 128; st > 0; st >>= 1){
        if (tid < st) red[tid] += red[tid+st];
        __syncthreads();
    }
    if (tid == 0){
        int tot = 0;
        for (int b = 0; b < Bn; b++) tot += x_sl[b];
        out[0] = -red[0] / (float)tot;
    }
}

// ---------------- launch ----------------
extern "C" void kernel_launch(void* const* d_in, const int* in_sizes, int n_in,
                              void* d_out, int out_size)
{
    const int*   x       = (const int*)  d_in[0];
    const int*   x_sl    = (const int*)  d_in[1];
    const float* eps     = (const float*)d_in[2];
    const float* emb     = (const float*)d_in[3];
    const float* w_ih    = (const float*)d_in[4];
    const float* w_hh    = (const float*)d_in[5];
    const float* b_ih    = (const float*)d_in[6];
    const float* b_hh    = (const float*)d_in[7];
    const float* w_prior = (const float*)d_in[8];
    const float* b_prior = (const float*)d_in[9];
    const float* w_gen   = (const float*)d_in[10];
    const float* b_gen   = (const float*)d_in[11];
    float* out = (float*)d_out;

    cudaFuncSetAttribute(k_lstm_all, cudaFuncAttributeMaxDynamicSharedMemorySize, LSTM_SMEM);
    cudaFuncSetAttribute(k_big,      cudaFuncAttributeMaxDynamicSharedMemorySize, DYN_BIG);

    k_prep_z<<<BT, 256>>>(x, x_sl, eps, emb);                      // 1
    k_prep_v<<<Vn, 256>>>(emb, w_ih, w_prior, w_gen);              // 2
    k_xproj16<<<dim3(G4n/64, BT/128), 256>>>(b_ih, b_hh);          // 3
    k_lstm_all<<<128, 256, LSTM_SMEM>>>(w_hh);                     // 4  <- ncu target
    k_big<<<dim3(NVT, BT/128), 256, DYN_BIG>>>(b_prior, b_gen, x); // 5
    k_lse<<<BT/256, 256>>>(x_sl);                                  // 6
    k_final<<<1, 256>>>(x_sl, out);                                // 7
}

// round 14
// speedup vs baseline: 11.1036x; 1.0671x over previous
#include <cuda_runtime.h>
#include <cuda_bf16.h>
#include <cstdint>

#define Bn 32
#define Tn 128
#define Kn 256
#define Hn 512
#define Vn 10000
#define BT (Bn*Tn)
#define G4n (4*Hn)
#define TWOK (2*Kn)
#define NVT 157              // ceil(Vn/64)

#define HALF_LOG_2PI 0.918938533204672741780329736406f

typedef unsigned long long ull;

// ---------------- static scratch ----------------
__device__ __align__(16) __nv_bfloat16 g_zb[BT*Kn];      // 2 MB
__device__ __align__(16) __nv_bfloat16 g_ZZb[BT*TWOK];   // 4 MB [z | z^2]
__device__ __align__(16) __nv_bfloat16 g_hb[BT*Hn];      // 4 MB
__device__ __align__(16) __nv_bfloat16 g_W2b[Vn*TWOK];   // 10 MB
__device__ __align__(16) __nv_bfloat16 g_wpb[Vn*Hn];     // 10 MB
__device__ __align__(16) __nv_bfloat16 g_wgb[Vn*Kn];     // 5 MB
__device__ __align__(16) __nv_bfloat16 g_wihb[G4n*Kn];   // 1 MB
__device__ __align__(16) float g_xproj[BT*G4n];          // 32 MB, layout [(js*128+t)*32+b][16r]
__device__ float g_cst[Vn];
__device__ float g_qzlp[BT];
__device__ float g_sumz2[BT];
__device__ float g_tgt[BT];
__device__ float g_part[3*NVT*BT];
__device__ float g_contrib[BT];
__device__ __align__(16) float g_hbuf[2][Hn*Bn];         // TRANSPOSED: [j][b]
__device__ unsigned g_ctr;

__device__ __forceinline__ float softplus_b(float x){
    return (x > 20.f) ? x : log2f(1.f + exp2f(x));
}
__device__ __forceinline__ float sigmf(float x){ return 1.f/(1.f+expf(-x)); }

__device__ __forceinline__ ull ffma2(ull a, ull b, ull c){
    ull d;
    asm("fma.rn.f32x2 %0, %1, %2, %3;" : "=l"(d) : "l"(a), "l"(b), "l"(c));
    return d;
}
__device__ __forceinline__ float2 unpk(ull v){
    float lo, hi;
    asm("mov.b64 {%0, %1}, %2;" : "=f"(lo), "=f"(hi) : "l"(v));
    return make_float2(lo, hi);
}
__device__ __forceinline__ ull pk2(float lo, float hi){
    ull v;
    asm("mov.b64 %0, {%1, %2};" : "=l"(v) : "f"(lo), "f"(hi));
    return v;
}

// ---------------- cp.async / ldmatrix helpers ----------------
__device__ __forceinline__ uint32_t smem_u32(const void* p){
    uint32_t a;
    asm("{ .reg .u64 t; cvta.to.shared.u64 t, %1; cvt.u32.u64 %0, t; }" : "=r"(a) : "l"(p));
    return a;
}
__device__ __forceinline__ void cp16(uint32_t dst, const void* src){
    asm volatile("cp.async.cg.shared.global [%0], [%1], 16;" :: "r"(dst), "l"(src) : "memory");
}
#define CP_COMMIT() asm volatile("cp.async.commit_group;" ::: "memory")
template<int N> __device__ __forceinline__ void cp_wait(){
    asm volatile("cp.async.wait_group %0;" :: "n"(N) : "memory");
}
#define SWZ128(o) ((o) ^ (((o) >> 3) & 0x70))

__device__ __forceinline__ void ldsm4(uint32_t* r, uint32_t addr){
    asm volatile("ldmatrix.sync.aligned.m8n8.x4.shared.b16 {%0,%1,%2,%3}, [%4];"
        : "=r"(r[0]),"=r"(r[1]),"=r"(r[2]),"=r"(r[3]) : "r"(addr));
}

// ================= prep z =================
__global__ void k_prep_z(const int* __restrict__ x, const int* __restrict__ x_sl,
                         const float* __restrict__ eps, const float* __restrict__ emb)
{
    int row = blockIdx.x;
    int k   = threadIdx.x;
    int lin = row*256 + k;
    if (lin < Hn*Bn) g_hbuf[0][lin] = 0.f;
    if (lin == 0) g_ctr = 0u;
    int b = row / Tn, t = row % Tn;
    int xv = x[row];
    float mask = (t < x_sl[b]) ? 1.f : 0.f;
    float mu = emb[xv*TWOK + k];
    float sq = softplus_b(emb[xv*TWOK + Kn + k]);
    float e  = eps[row*Kn + k];
    float zv = (mu + sq*e) * mask;
    g_zb[row*Kn + k]         = __float2bfloat16(zv);
    g_ZZb[row*TWOK + k]      = __float2bfloat16(zv);
    g_ZZb[row*TWOK + Kn + k] = __float2bfloat16(zv*zv);
    float q = -HALF_LOG_2PI - logf(sq) - 0.5f*e*e;
    __shared__ float r1[256], r2[256];
    r1[k] = q; r2[k] = zv*zv;
    __syncthreads();
    for (int s = 128; s > 0; s >>= 1){
        if (k < s){ r1[k] += r1[k+s]; r2[k] += r2[k+s]; }
        __syncthreads();
    }
    if (k == 0){ g_qzlp[row] = r1[0]; g_sumz2[row] = r2[0]; }
}

// ================= prep v =================
__global__ void k_prep_v(const float* __restrict__ emb, const float* __restrict__ w_ih,
                         const float* __restrict__ w_prior, const float* __restrict__ w_gen)
{
    int v = blockIdx.x;
    int k = threadIdx.x;
    __shared__ float red[256];
    float mu = emb[v*TWOK + k];
    float sp = softplus_b(emb[v*TWOK + Kn + k]);
    float inv2 = 0.5f/(sp*sp);
    g_W2b[v*TWOK + k]      = __float2bfloat16(2.f*inv2*mu);
    g_W2b[v*TWOK + Kn + k] = __float2bfloat16(-inv2);
    g_wpb[v*Hn + k]       = __float2bfloat16(w_prior[(size_t)v*Hn + k]);
    g_wpb[v*Hn + 256 + k] = __float2bfloat16(w_prior[(size_t)v*Hn + 256 + k]);
    g_wgb[v*Kn + k]       = __float2bfloat16(w_gen[(size_t)v*Kn + k]);
    {
        int idx = v*256 + k;
        if (idx < G4n*Kn) g_wihb[idx] = __float2bfloat16(w_ih[idx]);
    }
    float c = -HALF_LOG_2PI - logf(sp) - mu*mu*inv2;
    red[k] = c;
    __syncthreads();
    for (int s = 128; s > 0; s >>= 1){
        if (k < s) red[k] += red[k+s];
        __syncthreads();
    }
    if (k == 0) g_cst[v] = red[0];
}

// ================= legacy bf16 mma (m16n8k16) =================
__device__ __forceinline__ void mma16(float* d, const uint32_t* a, const uint32_t* b){
    asm volatile("mma.sync.aligned.m16n8k16.row.col.f32.bf16.bf16.f32 "
        "{%0,%1,%2,%3}, {%4,%5,%6,%7}, {%8,%9}, {%0,%1,%2,%3};"
        : "+f"(d[0]),"+f"(d[1]),"+f"(d[2]),"+f"(d[3])
        : "r"(a[0]),"r"(a[1]),"r"(a[2]),"r"(a[3]), "r"(b[0]),"r"(b[1]));
}

// ---------------- x_proj GEMM ----------------
struct __align__(16) SmemTC {
    __nv_bfloat16 As[2][128][40];
    __nv_bfloat16 Bs[2][64][40];
};
__device__ __forceinline__ void ldA16s(const __nv_bfloat16* __restrict__ zb,
                                       int row0, int kt, int tid, uint4 (&rA)[2]){
    #pragma unroll
    for (int i=0;i<2;i++){
        int idx = tid + i*256;
        int row = idx>>2, q = idx&3;
        int grow = row0 + row;
        rA[i] = make_uint4(0u,0u,0u,0u);
        if ((grow & (Tn-1)) != 0)
            rA[i] = *(const uint4*)(zb + (size_t)(grow-1)*Kn + kt*32 + q*8);
    }
}
__device__ __forceinline__ void ldB16(const __nv_bfloat16* __restrict__ Bg, int ldb,
                                      int v0, int nmax, int kt, int tid, uint4& rB){
    int row = tid>>2, q = tid&3;
    int v = v0 + row; if (v >= nmax) v = nmax-1;
    rB = *(const uint4*)(Bg + (size_t)v*ldb + kt*32 + q*8);
}
__device__ __forceinline__ void stAB16(SmemTC* sm, int buf, int tid,
                                       const uint4 (&rA)[2], const uint4& rB){
    #pragma unroll
    for (int i=0;i<2;i++){
        int idx = tid + i*256; int row = idx>>2, q = idx&3;
        *(uint4*)&sm->As[buf][row][q*8] = rA[i];
    }
    { int row = tid>>2, q = tid&3;
      *(uint4*)&sm->Bs[buf][row][q*8] = rB; }
}
__device__ __forceinline__ void comp16L(uint32_t As_b, uint32_t Bs_b,
    uint32_t aoffP, uint32_t acolb, uint32_t boffP, uint32_t bcolb,
    float (&acc)[8][4])
{
    #pragma unroll
    for (int kk=0; kk<2; kk++){
        uint32_t af0[4], af1[4], b0[4], b1[4];
        uint32_t ac = kk*32 + acolb;
        uint32_t bc = kk*32 + bcolb;
        ldsm4(af0, As_b + aoffP + ac);
        ldsm4(af1, As_b + aoffP + 16*80 + ac);
        ldsm4(b0,  Bs_b + boffP + bc);
        ldsm4(b1,  Bs_b + boffP + 16*80 + bc);
        mma16(acc[0], af0, b0);
        mma16(acc[1], af0, b0+2);
        mma16(acc[2], af0, b1);
        mma16(acc[3], af0, b1+2);
        mma16(acc[4], af1, b0);
        mma16(acc[5], af1, b0+2);
        mma16(acc[6], af1, b1);
        mma16(acc[7], af1, b1+2);
    }
}

__global__ __launch_bounds__(256) void k_xproj16(const float* __restrict__ b_ih,
                                                 const float* __restrict__ b_hh)
{
    __shared__ SmemTC sm;
    int bcol = blockIdx.x * 64;
    int row0 = blockIdx.y * 128;
    int tid = threadIdx.x;
    int lane = tid&31, wid = tid>>5;
    int moff = (wid>>1)*32, noff = (wid&1)*32;
    int gr = lane>>2, tg = lane&3;
    int row_l = lane&7, sub = lane>>3;
    uint32_t aoffP = (uint32_t)(moff + (sub&1)*8 + row_l)*80u;
    uint32_t acolb = (uint32_t)((sub>>1)*16);
    uint32_t boffP = (uint32_t)(noff + (sub>>1)*8 + row_l)*80u;
    uint32_t bcolb = (uint32_t)((sub&1)*16);
    uint32_t As0 = smem_u32(&sm.As[0][0][0]);
    uint32_t Bs0 = smem_u32(&sm.Bs[0][0][0]);

    float acc[8][4] = {};
    {
        uint4 rA[2]; uint4 rB;
        ldA16s(g_zb,row0,0,tid,rA); ldB16(g_wihb,Kn,bcol,G4n,0,tid,rB);
        stAB16(&sm,0,tid,rA,rB);
        __syncthreads();
        const int nchunks = Kn/32;
        for (int kt=0; kt<nchunks; kt++){
            int cur = kt&1;
            bool more = (kt+1 < nchunks);
            if (more){ ldA16s(g_zb,row0,kt+1,tid,rA); ldB16(g_wihb,Kn,bcol,G4n,kt+1,tid,rB); }
            comp16L(As0 + cur*(128*80), Bs0 + cur*(64*80),
                    aoffP, acolb, boffP, bcolb, acc);
            if (more) stAB16(&sm,cur^1,tid,rA,rB);
            __syncthreads();
        }
    }
    // epilogue: store in LSTM-friendly layout [(js*128+t)*32+b][16r]
    #pragma unroll
    for (int nt=0; nt<4; nt++){
        #pragma unroll
        for (int c=0;c<2;c++){
            int col = bcol + noff + nt*8 + tg*2 + c;
            float bias = b_ih[col] + b_hh[col];
            int gate = col >> 9;
            int jc   = col & 511;
            int js   = jc >> 2, jj = jc & 3;
            int r    = gate*4 + jj;
            #pragma unroll
            for (int mt=0;mt<2;mt++)
                #pragma unroll
                for (int hf=0; hf<2; hf++){
                    int row = row0 + moff + mt*16 + gr + hf*8;
                    int b = row >> 7, tt = row & 127;
                    size_t addr = ((size_t)(js*Tn + tt)*32 + b)*16 + r;
                    g_xproj[addr] = acc[mt*4+nt][hf*2+c] + bias;
                }
        }
    }
}

// ================= persistent LSTM v3: transposed h + 512 threads =================
// CTA js: 16 gate-rows (4 gates x 4 j) for all 32 batches. 16 warps, warp = K-32.
// h exchanged via g_hbuf[par][j][b] (transposed) -> coalesced LDG, no smem staging.
#define LSTM_WS   (16*512)
#define LSTM_PB   (16*16*33)
#define LSTM_XP   (2*512)
#define LSTM_SMEM ((LSTM_WS + LSTM_PB + LSTM_XP)*(int)sizeof(float))

__global__ __launch_bounds__(512) void k_lstm_all(const float* __restrict__ w_hh)
{
    extern __shared__ float sm[];
    float* w_s  = sm;                       // [16 rows][512 k]
    float* pbuf = sm + LSTM_WS;             // [16 rows][16 kq][33]
    float* xp_s = pbuf + LSTM_PB;           // [2][512]
    int tid = threadIdx.x, lane = tid & 31, w = tid >> 5;
    int js = blockIdx.x;

    // cache w_hh slice: local row r -> global row (r>>2)*Hn + js*4 + (r&3)
    for (int i = tid; i < 16*128; i += 512){
        int r = i >> 7, q = i & 127;
        int grow = (r>>2)*Hn + js*4 + (r&3);
        *(float4*)&w_s[r*512 + q*4] = *(const float4*)&w_hh[(size_t)grow*Hn + q*4];
    }

    uint32_t xp_base = smem_u32(xp_s);
    if (tid < 128)
        cp16(xp_base + tid*16, g_xproj + (size_t)(js*Tn + 0)*512 + tid*4);
    CP_COMMIT();

    int kq = w;                              // K-32nd: k in [kq*32, kq*32+32)
    const float* wbase = w_s + kq*32;
    float c_reg = 0.f;                       // thread (b=tid&31, jj=tid>>5), tid<128
    volatile unsigned* vc = &g_ctr;

    for (int t = 0; t < Tn; t++){
        int par = t & 1;
        if (tid == 0 && t > 0){
            unsigned target = (unsigned)t * 128u;
            while (*vc < target) {}
        }
        // prefetch xproj for t+1
        if (t+1 < Tn && tid < 128)
            cp16(xp_base + ((t+1)&1)*2048 + tid*16,
                 g_xproj + (size_t)(js*Tn + (t+1))*512 + tid*4);
        CP_COMMIT();
        __syncthreads();    // release barrier observation to all warps

        // dot: warp kq covers 32 k, all 16 rows. h loads: per-k 128B coalesced LDG (L2).
        {
            const float* hg = &g_hbuf[par][0] + (size_t)kq*32*32 + lane;
            ull acc[16];
            #pragma unroll
            for (int r=0;r<16;r++) acc[r] = 0ull;
            #pragma unroll
            for (int q = 0; q < 8; q++){     // 4 k per iter
                float h0 = __ldcg(hg + (q*4+0)*32);
                float h1 = __ldcg(hg + (q*4+1)*32);
                float h2 = __ldcg(hg + (q*4+2)*32);
                float h3 = __ldcg(hg + (q*4+3)*32);
                ull hv01 = pk2(h0, h1);
                ull hv23 = pk2(h2, h3);
                #pragma unroll
                for (int r = 0; r < 16; r++){
                    ulonglong2 wv = *(const ulonglong2*)(wbase + r*512 + q*4);
                    acc[r] = ffma2(wv.x, hv01, acc[r]);
                    acc[r] = ffma2(wv.y, hv23, acc[r]);
                }
            }
            #pragma unroll
            for (int r = 0; r < 16; r++){
                float2 u = unpk(acc[r]);
                pbuf[(r*16 + kq)*33 + lane] = u.x + u.y;
            }
        }
        cp_wait<1>();        // xp(t) resident
        __syncthreads();

        // activation (tid < 128)
        if (tid < 128){
            int b = tid & 31, jj = tid >> 5;
            int j = js*4 + jj;
            const float* xp = xp_s + (t&1)*512 + b*16;
            float g4[4];
            #pragma unroll
            for (int gate = 0; gate < 4; gate++){
                int r = gate*4 + jj;
                float s = xp[r];
                #pragma unroll
                for (int e = 0; e < 16; e++) s += pbuf[(r*16 + e)*33 + b];
                g4[gate] = s;
            }
            float c = c_reg;
            c = sigmf(g4[1])*c + sigmf(g4[0])*tanhf(g4[2]);
            float hv = sigmf(g4[3])*tanhf(c);
            c_reg = c;
            g_hbuf[par^1][j*32 + b] = hv;                        // transposed
            g_hb[(size_t)(b*Tn + t)*Hn + j] = __float2bfloat16(hv);
        }
        __threadfence();
        __syncthreads();
        if (tid == 0) atomicAdd(&g_ctr, 1u);
    }
}

// ================= k_big: cp.async + ldmatrix triple GEMM, 2 CTAs/SM =================
#define A_BYTES 16384
#define B_BYTES 8192
#define BUFSZ   (A_BYTES + B_BYTES)
#define DYN_BIG (2*BUFSZ)

__device__ __forceinline__ void issue_chunk(uint32_t abase, int buf, int tid,
    const __nv_bfloat16* __restrict__ Ag, const __nv_bfloat16* __restrict__ Bg,
    int lda, int local, int row0, int v0)
{
    uint32_t As = abase + buf*BUFSZ;
    uint32_t Bs = As + A_BYTES;
    #pragma unroll
    for (int i=0;i<4;i++){
        int idx = tid + i*256; int r = idx>>3, u = idx&7;
        cp16(As + SWZ128(r*128 + u*16), Ag + (size_t)(row0+r)*lda + local*64 + u*8);
    }
    #pragma unroll
    for (int i=0;i<2;i++){
        int idx = tid + i*256; int r = idx>>3, u = idx&7;
        int v = v0 + r; if (v >= Vn) v = Vn-1;
        cp16(Bs + SWZ128(r*128 + u*16), Bg + (size_t)v*lda + local*64 + u*8);
    }
    CP_COMMIT();
}

__device__ __forceinline__ void comp64L(uint32_t As_b, uint32_t Bs_b,
    uint32_t aoff, uint32_t acolb, uint32_t boff, uint32_t bcolb, uint32_t f,
    float (&acc)[8][4])
{
    #pragma unroll
    for (int kk=0; kk<4; kk++){
        uint32_t af0[4], af1[4], b0[4], b1[4];
        uint32_t ac = ((uint32_t)(kk*32) + acolb) ^ f;
        uint32_t bc = ((uint32_t)(kk*32) + bcolb) ^ f;
        ldsm4(af0, As_b + aoff + ac);
        ldsm4(af1, As_b + aoff + 2048u + ac);
        ldsm4(b0,  Bs_b + boff + bc);
        ldsm4(b1,  Bs_b + boff + 2048u + bc);
        mma16(acc[0], af0, b0);
        mma16(acc[1], af0, b0+2);
        mma16(acc[2], af0, b1);
        mma16(acc[3], af0, b1+2);
        mma16(acc[4], af1, b0);
        mma16(acc[5], af1, b0+2);
        mma16(acc[6], af1, b1);
        mma16(acc[7], af1, b1+2);
    }
}

__device__ __forceinline__ void chunk_src(int c, const __nv_bfloat16*& A,
                                          const __nv_bfloat16*& B, int& ld, int& loc)
{
    if (c < 8)      { A=g_hb;  B=g_wpb; ld=Hn;   loc=c;    }
    else if (c < 16){ A=g_ZZb; B=g_W2b; ld=TWOK; loc=c-8;  }
    else            { A=g_zb;  B=g_wgb; ld=Kn;   loc=c-16; }
}

__global__ __launch_bounds__(256,2) void k_big(
    const float* __restrict__ b_prior, const float* __restrict__ b_gen,
    const int* __restrict__ x)
{
    extern __shared__ __align__(128) char dynb[];
    __shared__ float sh_sum[128][3];
    __shared__ float sh_shift[128];
    __shared__ int   sh_xv[128];

    int vt = blockIdx.x, rt = blockIdx.y;
    int row0 = rt*128, v0 = vt*64;
    int tid = threadIdx.x;
    uint32_t abase = smem_u32(dynb);

    if (tid < 128){
        sh_shift[tid] = g_cst[0] - 0.5f*g_sumz2[row0+tid];
        sh_xv[tid]    = x[row0+tid];
        sh_sum[tid][0]=0.f; sh_sum[tid][1]=0.f; sh_sum[tid][2]=0.f;
    }

    int lane = tid&31, wid = tid>>5;
    int moff = (wid>>1)*32, noff = (wid&1)*32;
    int row_l = lane&7, sub = lane>>3;
    uint32_t f     = (uint32_t)(row_l*16);
    uint32_t aoff  = (uint32_t)(moff + (sub&1)*8 + row_l)*128u;
    uint32_t acolb = (uint32_t)((sub>>1)*16);
    uint32_t boff  = (uint32_t)(noff + (sub>>1)*8 + row_l)*128u;
    uint32_t bcolb = (uint32_t)((sub&1)*16);

    float accA[8][4] = {};
    float accB[8][4] = {};
    float rs1[4] = {}, rs2[4] = {}, rs3[4] = {};

    {
        const __nv_bfloat16 *Ag, *Bg; int lda, loc;
        chunk_src(0, Ag, Bg, lda, loc);
        issue_chunk(abase, 0, tid, Ag, Bg, lda, loc, row0, v0);
    }

    #pragma unroll 1
    for (int c = 0; c < 16; c++){
        cp_wait<0>();
        __syncthreads();
        {
            const __nv_bfloat16 *Ag, *Bg; int lda, loc;
            chunk_src(c+1, Ag, Bg, lda, loc);
            issue_chunk(abase, (c+1)&1, tid, Ag, Bg, lda, loc, row0, v0);
        }
        uint32_t As_b = abase + (c&1)*BUFSZ;
        uint32_t Bs_b = As_b + A_BYTES;
        if (c < 8) comp64L(As_b, Bs_b, aoff, acolb, boff, bcolb, f, accA);
        else       comp64L(As_b, Bs_b, aoff, acolb, boff, bcolb, f, accB);
    }

    // epilogue PM
    #pragma unroll
    for (int nt=0; nt<4; nt++){
        #pragma unroll
        for (int cc=0;cc<2;cc++){
            int n = noff + nt*8 + (lane&3)*2 + cc;
            int v = v0 + n;
            bool ok = v < Vn;
            int vc = ok ? v : (Vn-1);
            float bp = __ldg(&b_prior[vc]);
            float cv = g_cst[vc];
            #pragma unroll
            for (int mt=0;mt<2;mt++){
                #pragma unroll
                for (int hf=0; hf<2; hf++){
                    int rloc = moff + mt*16 + (lane>>2) + hf*8;
                    int ai = hf*2 + cc;
                    float s1 = accA[mt*4+nt][ai] + bp;
                    float s2 = s1 + cv + accB[mt*4+nt][ai] - sh_shift[rloc];
                    if (ok){
                        rs1[mt*2+hf] += __expf(s1);
                        rs2[mt*2+hf] += __expf(s2);
                    }
                }
            }
        }
    }
    #pragma unroll
    for (int i=0;i<8;i++)
        #pragma unroll
        for (int j=0;j<4;j++) accA[i][j] = 0.f;

    // phase G
    #pragma unroll 1
    for (int c = 16; c < 20; c++){
        cp_wait<0>();
        __syncthreads();
        if (c+1 < 20){
            const __nv_bfloat16 *Ag, *Bg; int lda, loc;
            chunk_src(c+1, Ag, Bg, lda, loc);
            issue_chunk(abase, (c+1)&1, tid, Ag, Bg, lda, loc, row0, v0);
        }
        uint32_t As_b = abase + (c&1)*BUFSZ;
        uint32_t Bs_b = As_b + A_BYTES;
        comp64L(As_b, Bs_b, aoff, acolb, boff, bcolb, f, accA);
    }

    // epilogue G
    #pragma unroll
    for (int nt=0; nt<4; nt++){
        #pragma unroll
        for (int cc=0;cc<2;cc++){
            int n = noff + nt*8 + (lane&3)*2 + cc;
            int v = v0 + n;
            bool ok = v < Vn;
            int vc = ok ? v : (Vn-1);
            float bg = __ldg(&b_gen[vc]);
            #pragma unroll
            for (int mt=0;mt<2;mt++){
                #pragma unroll
                for (int hf=0; hf<2; hf++){
                    int rloc = moff + mt*16 + (lane>>2) + hf*8;
                    int ai = hf*2 + cc;
                    float s3 = accA[mt*4+nt][ai] + bg;
                    if (ok){
                        rs3[mt*2+hf] += __expf(s3);
                        if (v == sh_xv[rloc]) g_tgt[row0 + rloc] = s3;
                    }
                }
            }
        }
    }

    #pragma unroll
    for (int lr=0; lr<4; lr++){
        float v0s = rs1[lr], v1s = rs2[lr], v2s = rs3[lr];
        v0s += __shfl_xor_sync(0xffffffffu, v0s, 1);
        v0s += __shfl_xor_sync(0xffffffffu, v0s, 2);
        v1s += __shfl_xor_sync(0xffffffffu, v1s, 1);
        v1s += __shfl_xor_sync(0xffffffffu, v1s, 2);
        v2s += __shfl_xor_sync(0xffffffffu, v2s, 1);
        v2s += __shfl_xor_sync(0xffffffffu, v2s, 2);
        if ((lane&3)==0){
            int mt = lr>>1, hf = lr&1;
            int rloc = moff + mt*16 + (lane>>2) + hf*8;
            atomicAdd(&sh_sum[rloc][0], v0s);
            atomicAdd(&sh_sum[rloc][1], v1s);
            atomicAdd(&sh_sum[rloc][2], v2s);
        }
    }
    __syncthreads();
    if (tid < 128){
        g_part[(0*NVT + vt)*BT + row0 + tid] = sh_sum[tid][0];
        g_part[(1*NVT + vt)*BT + row0 + tid] = sh_sum[tid][1];
        g_part[(2*NVT + vt)*BT + row0 + tid] = sh_sum[tid][2];
    }
}

// ---------------- per-row LSE finish ----------------
__global__ void k_lse(const int* __restrict__ x_sl)
{
    int row = blockIdx.x*256 + threadIdx.x;
    if (row >= BT) return;
    float S1=0.f, S2=0.f, S3=0.f;
    for (int vt = 0; vt < NVT; vt++){
        S1 += g_part[(0*NVT+vt)*BT + row];
        S2 += g_part[(1*NVT+vt)*BT + row];
        S3 += g_part[(2*NVT+vt)*BT + row];
    }
    int b = row / Tn, t = row % Tn;
    float shift = g_cst[0] - 0.5f*g_sumz2[row];
    float lse_p = logf(S1);
    float lse_m = shift + logf(S2);
    float lse_g = logf(S3);
    float mask = (t < x_sl[b]) ? 1.f : 0.f;
    g_contrib[row] = mask * (g_tgt[row] - lse_g - g_qzlp[row] + (lse_m - lse_p));
}

// ---------------- final scalar ----------------
__global__ void k_final(const int* __restrict__ x_sl, float* __restrict__ out)
{
    __shared__ float red[256];
    int tid = threadIdx.x;
    float s = 0.f;
    for (int i = tid; i < BT; i += 256) s += g_contrib[i];
    red[tid] = s; __syncthreads();
    for (int st = 128; st > 0; st >>= 1){
        if (tid < st) red[tid] += red[tid+st];
        __syncthreads();
    }
    if (tid == 0){
        int tot = 0;
        for (int b = 0; b < Bn; b++) tot += x_sl[b];
        out[0] = -red[0] / (float)tot;
    }
}

// ---------------- launch ----------------
extern "C" void kernel_launch(void* const* d_in, const int* in_sizes, int n_in,
                              void* d_out, int out_size)
{
    const int*   x       = (const int*)  d_in[0];
    const int*   x_sl    = (const int*)  d_in[1];
    const float* eps     = (const float*)d_in[2];
    const float* emb     = (const float*)d_in[3];
    const float* w_ih    = (const float*)d_in[4];
    const float* w_hh    = (const float*)d_in[5];
    const float* b_ih    = (const float*)d_in[6];
    const float* b_hh    = (const float*)d_in[7];
    const float* w_prior = (const float*)d_in[8];
    const float* b_prior = (const float*)d_in[9];
    const float* w_gen   = (const float*)d_in[10];
    const float* b_gen   = (const float*)d_in[11];
    float* out = (float*)d_out;

    cudaFuncSetAttribute(k_lstm_all, cudaFuncAttributeMaxDynamicSharedMemorySize, LSTM_SMEM);
    cudaFuncSetAttribute(k_big,      cudaFuncAttributeMaxDynamicSharedMemorySize, DYN_BIG);

    k_prep_z<<<BT, 256>>>(x, x_sl, eps, emb);                      // 1
    k_prep_v<<<Vn, 256>>>(emb, w_ih, w_prior, w_gen);              // 2
    k_xproj16<<<dim3(G4n/64, BT/128), 256>>>(b_ih, b_hh);          // 3
    k_lstm_all<<<128, 512, LSTM_SMEM>>>(w_hh);                     // 4  <- ncu target
    k_big<<<dim3(NVT, BT/128), 256, DYN_BIG>>>(b_prior, b_gen, x); // 5
    k_lse<<<BT/256, 256>>>(x_sl);                                  // 6
    k_final<<<1, 256>>>(x_sl, out);                                // 7
}